// round 1
// baseline (speedup 1.0000x reference)
#include <cuda_runtime.h>
#include <math.h>

// Problem constants: B=1, n_seq=S=256, seq_len=L=256, c_m=256, H=8, ch=32, HC=256
#define S_DIM 256
#define L_DIM 256
#define C_DIM 256
#define HC_DIM 256
#define NH 8
#define CH 32
#define NROWS (S_DIM * L_DIM)  // 65536

// Scratch (device globals per allocation rules): 6 x 64MB
__device__ float g_mn[NROWS * C_DIM];
__device__ float g_q[NROWS * HC_DIM];
__device__ float g_k[NROWS * HC_DIM];
__device__ float g_v[NROWS * HC_DIM];
__device__ float g_g[NROWS * HC_DIM];
__device__ float g_att[NROWS * HC_DIM];

// ---------------------------------------------------------------------------
// LayerNorm over last dim (256). One warp per row, 8 floats per lane.
// ---------------------------------------------------------------------------
__global__ __launch_bounds__(256) void ln_kernel(
    const float* __restrict__ m, const float* __restrict__ w,
    const float* __restrict__ b, float* __restrict__ out)
{
    const int warp = threadIdx.x >> 5;
    const int lane = threadIdx.x & 31;
    const int row  = blockIdx.x * 8 + warp;

    const float4* x4 = (const float4*)(m + (size_t)row * C_DIM);
    float4 v0 = x4[lane * 2 + 0];
    float4 v1 = x4[lane * 2 + 1];

    float s1 = (v0.x + v0.y) + (v0.z + v0.w) + (v1.x + v1.y) + (v1.z + v1.w);
    float s2 = v0.x * v0.x + v0.y * v0.y + v0.z * v0.z + v0.w * v0.w
             + v1.x * v1.x + v1.y * v1.y + v1.z * v1.z + v1.w * v1.w;

    #pragma unroll
    for (int o = 16; o > 0; o >>= 1) {
        s1 += __shfl_xor_sync(0xffffffffu, s1, o);
        s2 += __shfl_xor_sync(0xffffffffu, s2, o);
    }
    const float mu  = s1 * (1.0f / 256.0f);
    const float var = s2 * (1.0f / 256.0f) - mu * mu;
    const float rs  = rsqrtf(var + 1e-5f);

    const float4* w4 = (const float4*)w;
    const float4* b4 = (const float4*)b;
    float4 w0 = w4[lane * 2 + 0], w1 = w4[lane * 2 + 1];
    float4 b0 = b4[lane * 2 + 0], b1 = b4[lane * 2 + 1];

    float4 r0, r1;
    r0.x = (v0.x - mu) * rs * w0.x + b0.x;
    r0.y = (v0.y - mu) * rs * w0.y + b0.y;
    r0.z = (v0.z - mu) * rs * w0.z + b0.z;
    r0.w = (v0.w - mu) * rs * w0.w + b0.w;
    r1.x = (v1.x - mu) * rs * w1.x + b1.x;
    r1.y = (v1.y - mu) * rs * w1.y + b1.y;
    r1.z = (v1.z - mu) * rs * w1.z + b1.z;
    r1.w = (v1.w - mu) * rs * w1.w + b1.w;

    float4* o4 = (float4*)(out + (size_t)row * C_DIM);
    o4[lane * 2 + 0] = r0;
    o4[lane * 2 + 1] = r1;
}

// ---------------------------------------------------------------------------
// SGEMM: C[M,N] = A[M,K] @ B[K,N] (+ bias[N]). 128x128x8 tile, 8x8/thread.
// M=65536, N=256, K=256 (all dims divide evenly; no bounds checks).
// ---------------------------------------------------------------------------
#define BM 128
#define BN 128
#define BKT 8

__global__ __launch_bounds__(256) void sgemm_bias(
    const float* __restrict__ A, const float* __restrict__ B,
    float* __restrict__ C, const float* __restrict__ bias,
    int M, int N, int K)
{
    __shared__ float As[BKT][BM];
    __shared__ float Bs[BKT][BN];

    const int tid  = threadIdx.x;
    const int arow = tid >> 1;
    const int acol = (tid & 1) << 2;
    const int brow = tid >> 5;
    const int bcol = (tid & 31) << 2;
    const int tx   = tid & 15;
    const int ty   = tid >> 4;

    const float* Ap = A + (size_t)blockIdx.y * BM * K;
    const float* Bp = B + blockIdx.x * BN;

    float acc[8][8];
    #pragma unroll
    for (int i = 0; i < 8; i++)
        #pragma unroll
        for (int j = 0; j < 8; j++) acc[i][j] = 0.0f;

    for (int k0 = 0; k0 < K; k0 += BKT) {
        float4 av = *(const float4*)(Ap + (size_t)arow * K + k0 + acol);
        As[acol + 0][arow] = av.x;
        As[acol + 1][arow] = av.y;
        As[acol + 2][arow] = av.z;
        As[acol + 3][arow] = av.w;
        *(float4*)(&Bs[brow][bcol]) =
            *(const float4*)(Bp + (size_t)(k0 + brow) * N + bcol);
        __syncthreads();

        #pragma unroll
        for (int k = 0; k < BKT; k++) {
            float a[8], b[8];
            #pragma unroll
            for (int i = 0; i < 8; i++) a[i] = As[k][ty * 8 + i];
            #pragma unroll
            for (int j = 0; j < 8; j++) b[j] = Bs[k][tx * 8 + j];
            #pragma unroll
            for (int i = 0; i < 8; i++)
                #pragma unroll
                for (int j = 0; j < 8; j++)
                    acc[i][j] = fmaf(a[i], b[j], acc[i][j]);
        }
        __syncthreads();
    }

    #pragma unroll
    for (int i = 0; i < 8; i++) {
        const size_t row = (size_t)blockIdx.y * BM + ty * 8 + i;
        #pragma unroll
        for (int j4 = 0; j4 < 2; j4++) {
            const int col = blockIdx.x * BN + tx * 8 + j4 * 4;
            float4 r;
            r.x = acc[i][j4 * 4 + 0];
            r.y = acc[i][j4 * 4 + 1];
            r.z = acc[i][j4 * 4 + 2];
            r.w = acc[i][j4 * 4 + 3];
            if (bias) {
                float4 bb = *(const float4*)(bias + col);
                r.x += bb.x; r.y += bb.y; r.z += bb.z; r.w += bb.w;
            }
            *(float4*)(C + row * N + col) = r;
        }
    }
}

// ---------------------------------------------------------------------------
// Attention per (l, h) tile: softmax(Q K^T / sqrt(32)) V, flash-style online
// softmax with 16-wide logit chunks in registers. Epilogue applies the
// reference's scrambling reshape + sigmoid gate and writes g_att directly:
//   s' = h*32 + l/8 ; l' = (l%8)*32 + s/8 ; c' = (s%8)*32 + c
// Q/K/V layout: buf[(s*256 + l)*256 + h*32 + c]
// ---------------------------------------------------------------------------
__global__ __launch_bounds__(256, 2) void attn_kernel(
    const float* __restrict__ Qg, const float* __restrict__ Kg,
    const float* __restrict__ Vg, const float* __restrict__ Gg,
    float* __restrict__ Og)
{
    extern __shared__ float sh[];
    float* Ks = sh;         // 256*32
    float* Vs = sh + 8192;  // 256*32

    const int l   = blockIdx.x >> 3;
    const int h   = blockIdx.x & 7;
    const int tid = threadIdx.x;

    const size_t base0 = (size_t)l * HC_DIM + h * CH;

    // Cooperative, coalesced K/V tile load (8 threads cover one 128B row).
    #pragma unroll
    for (int i = 0; i < 8; i++) {
        const int idx = i * 256 + tid;
        const int t   = idx >> 3;
        const int cc  = idx & 7;
        const size_t gofs = base0 + (size_t)t * HC_DIM * L_DIM + cc * 4;
        *(float4*)(Ks + t * 32 + cc * 4) = *(const float4*)(Kg + gofs);
        *(float4*)(Vs + t * 32 + cc * 4) = *(const float4*)(Vg + gofs);
    }

    // Per-thread query row s = tid
    float q[32];
    {
        const size_t qofs = base0 + (size_t)tid * HC_DIM * L_DIM;
        #pragma unroll
        for (int cc = 0; cc < 8; cc++) {
            float4 t4 = *(const float4*)(Qg + qofs + cc * 4);
            q[cc * 4 + 0] = t4.x; q[cc * 4 + 1] = t4.y;
            q[cc * 4 + 2] = t4.z; q[cc * 4 + 3] = t4.w;
        }
    }
    __syncthreads();

    float o[32];
    #pragma unroll
    for (int c = 0; c < 32; c++) o[c] = 0.0f;
    float mx = -3.0e38f, sum = 0.0f;
    const float scale = 0.17677669529663689f;  // 1/sqrt(32)

    for (int t0 = 0; t0 < 256; t0 += 16) {
        float x[16];
        #pragma unroll
        for (int tt = 0; tt < 16; tt++) {
            const float4* kr = (const float4*)(Ks + (t0 + tt) * 32);
            float a0 = 0.f, a1 = 0.f, a2 = 0.f, a3 = 0.f;
            #pragma unroll
            for (int cc = 0; cc < 8; cc++) {
                float4 kk = kr[cc];
                a0 = fmaf(q[cc * 4 + 0], kk.x, a0);
                a1 = fmaf(q[cc * 4 + 1], kk.y, a1);
                a2 = fmaf(q[cc * 4 + 2], kk.z, a2);
                a3 = fmaf(q[cc * 4 + 3], kk.w, a3);
            }
            x[tt] = ((a0 + a1) + (a2 + a3)) * scale;
        }
        float cm = mx;
        #pragma unroll
        for (int tt = 0; tt < 16; tt++) cm = fmaxf(cm, x[tt]);
        const float f = __expf(mx - cm);
        mx = cm;
        sum *= f;
        #pragma unroll
        for (int c = 0; c < 32; c++) o[c] *= f;
        #pragma unroll
        for (int tt = 0; tt < 16; tt++) {
            const float p = __expf(x[tt] - mx);
            sum += p;
            const float4* vr = (const float4*)(Vs + (t0 + tt) * 32);
            #pragma unroll
            for (int cc = 0; cc < 8; cc++) {
                float4 vv = vr[cc];
                o[cc * 4 + 0] = fmaf(p, vv.x, o[cc * 4 + 0]);
                o[cc * 4 + 1] = fmaf(p, vv.y, o[cc * 4 + 1]);
                o[cc * 4 + 2] = fmaf(p, vv.z, o[cc * 4 + 2]);
                o[cc * 4 + 3] = fmaf(p, vv.w, o[cc * 4 + 3]);
            }
        }
    }
    const float inv = 1.0f / sum;

    // Scramble + sigmoid gate + store (coalesced: 8 consecutive s share j_o).
    const int i_o = h * 32 + (l >> 3);
    const int j_o = ((l & 7) << 5) + (tid >> 3);
    const int k_o = (tid & 7) << 5;
    const size_t obase = ((size_t)i_o * 256 + j_o) * 256 + k_o;
    #pragma unroll
    for (int cc = 0; cc < 8; cc++) {
        float4 gp = *(const float4*)(Gg + obase + cc * 4);
        float4 r;
        r.x = o[cc * 4 + 0] * inv / (1.0f + __expf(-gp.x));
        r.y = o[cc * 4 + 1] * inv / (1.0f + __expf(-gp.y));
        r.z = o[cc * 4 + 2] * inv / (1.0f + __expf(-gp.z));
        r.w = o[cc * 4 + 3] * inv / (1.0f + __expf(-gp.w));
        *(float4*)(Og + obase + cc * 4) = r;
    }
}

// ---------------------------------------------------------------------------
extern "C" void kernel_launch(void* const* d_in, const int* in_sizes, int n_in,
                              void* d_out, int out_size)
{
    const float* m    = (const float*)d_in[0];
    const float* ln_w = (const float*)d_in[1];
    const float* ln_b = (const float*)d_in[2];
    const float* wq   = (const float*)d_in[3];
    const float* wk   = (const float*)d_in[4];
    const float* wv   = (const float*)d_in[5];
    const float* wg   = (const float*)d_in[6];
    const float* bg   = (const float*)d_in[7];
    const float* wo   = (const float*)d_in[8];
    const float* bo   = (const float*)d_in[9];
    float* out = (float*)d_out;

    float *mn, *q, *k, *v, *g, *att;
    cudaGetSymbolAddress((void**)&mn,  g_mn);
    cudaGetSymbolAddress((void**)&q,   g_q);
    cudaGetSymbolAddress((void**)&k,   g_k);
    cudaGetSymbolAddress((void**)&v,   g_v);
    cudaGetSymbolAddress((void**)&g,   g_g);
    cudaGetSymbolAddress((void**)&att, g_att);

    cudaFuncSetAttribute(attn_kernel,
                         cudaFuncAttributeMaxDynamicSharedMemorySize, 65536);

    // 1. LayerNorm
    ln_kernel<<<NROWS / 8, 256>>>(m, ln_w, ln_b, mn);

    // 2. Q/K/V/Gate projections
    dim3 gg(HC_DIM / BN, NROWS / BM);
    sgemm_bias<<<gg, 256>>>(mn, wq, q,   nullptr, NROWS, HC_DIM, C_DIM);
    sgemm_bias<<<gg, 256>>>(mn, wk, k,   nullptr, NROWS, HC_DIM, C_DIM);
    sgemm_bias<<<gg, 256>>>(mn, wv, v,   nullptr, NROWS, HC_DIM, C_DIM);
    sgemm_bias<<<gg, 256>>>(mn, wg, g,   bg,      NROWS, HC_DIM, C_DIM);

    // 3. Attention + scramble + gate
    attn_kernel<<<L_DIM * NH, 256, 65536>>>(q, k, v, g, att);

    // 4. Output projection
    dim3 go(C_DIM / BN, NROWS / BM);
    sgemm_bias<<<go, 256>>>(att, wo, out, bo, NROWS, C_DIM, C_DIM);
}

// round 3
// speedup vs baseline: 1.7863x; 1.7863x over previous
#include <cuda_runtime.h>
#include <cuda_bf16.h>
#include <cstdint>
#include <math.h>

// Problem constants: B=1, n_seq=S=256, seq_len=L=256, c_m=256, H=8, ch=32, HC=256
#define S_DIM 256
#define L_DIM 256
#define C_DIM 256
#define HC_DIM 256
#define NH 8
#define CH 32
#define NROWS (S_DIM * L_DIM)  // 65536

// ---------------------------------------------------------------------------
// Scratch (device globals per allocation rules)
// ---------------------------------------------------------------------------
// A operands, split layout [row][512]: cols 0-255 = hi, 256-511 = lo (bf16)
__device__ __align__(16) __nv_bfloat16 g_mn_split[NROWS * 512];
__device__ __align__(16) __nv_bfloat16 g_att_split[NROWS * 512];
// f32 intermediates
__device__ __align__(16) float g_q[NROWS * HC_DIM];
__device__ __align__(16) float g_k[NROWS * HC_DIM];
__device__ __align__(16) float g_v[NROWS * HC_DIM];
__device__ __align__(16) float g_g[NROWS * HC_DIM];
// B operands, K-extended to 768: rows [0,256)=hi, [256,512)=hi, [512,768)=lo
__device__ __align__(16) __nv_bfloat16 g_Bqkvg[768 * 1024];  // cols: q|k|v|g
__device__ __align__(16) __nv_bfloat16 g_Bo[768 * 256];

// ---------------------------------------------------------------------------
// Helpers
// ---------------------------------------------------------------------------
__device__ __forceinline__ uint32_t smem_u32(const void* p) {
    uint32_t a;
    asm("{ .reg .u64 t; cvta.to.shared.u64 t, %1; cvt.u32.u64 %0, t; }"
        : "=r"(a) : "l"(p));
    return a;
}

#define SWZ(o) ((o) ^ (((o) >> 3) & 0x70))

__device__ __forceinline__ void cp_async16(uint32_t saddr, const void* gptr) {
    asm volatile("cp.async.cg.shared.global [%0], [%1], 16;"
                 :: "r"(saddr), "l"(__cvta_generic_to_global(gptr)) : "memory");
}
#define CP_COMMIT() asm volatile("cp.async.commit_group;" ::: "memory")
#define CP_WAIT2()  asm volatile("cp.async.wait_group 2;" ::: "memory")

__device__ __forceinline__ void ldsm4(uint32_t* r, uint32_t addr) {
    asm volatile("ldmatrix.sync.aligned.m8n8.x4.shared.b16 {%0,%1,%2,%3}, [%4];"
                 : "=r"(r[0]), "=r"(r[1]), "=r"(r[2]), "=r"(r[3]) : "r"(addr));
}
__device__ __forceinline__ void ldsm4t(uint32_t* r, uint32_t addr) {
    asm volatile("ldmatrix.sync.aligned.m8n8.x4.trans.shared.b16 {%0,%1,%2,%3}, [%4];"
                 : "=r"(r[0]), "=r"(r[1]), "=r"(r[2]), "=r"(r[3]) : "r"(addr));
}
__device__ __forceinline__ void mma_bf16(float* c, const uint32_t* a,
                                         uint32_t b0, uint32_t b1) {
    asm volatile(
        "mma.sync.aligned.m16n8k16.row.col.f32.bf16.bf16.f32 "
        "{%0,%1,%2,%3}, {%4,%5,%6,%7}, {%8,%9}, {%0,%1,%2,%3};"
        : "+f"(c[0]), "+f"(c[1]), "+f"(c[2]), "+f"(c[3])
        : "r"(a[0]), "r"(a[1]), "r"(a[2]), "r"(a[3]), "r"(b0), "r"(b1));
}

// fp32 -> bf16 hi/lo split (packed pairs)
__device__ __forceinline__ void split2(float a, float b, uint32_t& h, uint32_t& l) {
    __nv_bfloat162 hb = __floats2bfloat162_rn(a, b);
    float la = a - __bfloat162float(hb.x);
    float lb = b - __bfloat162float(hb.y);
    __nv_bfloat162 lo = __floats2bfloat162_rn(la, lb);
    h = *reinterpret_cast<uint32_t*>(&hb);
    l = *reinterpret_cast<uint32_t*>(&lo);
}

// ---------------------------------------------------------------------------
// LayerNorm -> split bf16 [row][512]. One warp per row.
// ---------------------------------------------------------------------------
__global__ __launch_bounds__(256) void ln_kernel(
    const float* __restrict__ m, const float* __restrict__ w,
    const float* __restrict__ b, __nv_bfloat16* __restrict__ osplit)
{
    const int warp = threadIdx.x >> 5;
    const int lane = threadIdx.x & 31;
    const int row  = blockIdx.x * 8 + warp;

    const float4* x4 = (const float4*)(m + (size_t)row * C_DIM);
    float4 v0 = x4[lane * 2 + 0];
    float4 v1 = x4[lane * 2 + 1];

    float s1 = (v0.x + v0.y) + (v0.z + v0.w) + (v1.x + v1.y) + (v1.z + v1.w);
    float s2 = v0.x * v0.x + v0.y * v0.y + v0.z * v0.z + v0.w * v0.w
             + v1.x * v1.x + v1.y * v1.y + v1.z * v1.z + v1.w * v1.w;
    #pragma unroll
    for (int o = 16; o > 0; o >>= 1) {
        s1 += __shfl_xor_sync(0xffffffffu, s1, o);
        s2 += __shfl_xor_sync(0xffffffffu, s2, o);
    }
    const float mu  = s1 * (1.0f / 256.0f);
    const float var = s2 * (1.0f / 256.0f) - mu * mu;
    const float rs  = rsqrtf(var + 1e-5f);

    const float4* w4 = (const float4*)w;
    const float4* b4 = (const float4*)b;
    float4 w0 = w4[lane * 2 + 0], w1 = w4[lane * 2 + 1];
    float4 b0 = b4[lane * 2 + 0], b1 = b4[lane * 2 + 1];

    float r[8];
    r[0] = (v0.x - mu) * rs * w0.x + b0.x;
    r[1] = (v0.y - mu) * rs * w0.y + b0.y;
    r[2] = (v0.z - mu) * rs * w0.z + b0.z;
    r[3] = (v0.w - mu) * rs * w0.w + b0.w;
    r[4] = (v1.x - mu) * rs * w1.x + b1.x;
    r[5] = (v1.y - mu) * rs * w1.y + b1.y;
    r[6] = (v1.z - mu) * rs * w1.z + b1.z;
    r[7] = (v1.w - mu) * rs * w1.w + b1.w;

    uint4 H, L;
    split2(r[0], r[1], H.x, L.x);
    split2(r[2], r[3], H.y, L.y);
    split2(r[4], r[5], H.z, L.z);
    split2(r[6], r[7], H.w, L.w);
    const size_t ofs = (size_t)row * 512 + lane * 8;
    *(uint4*)(osplit + ofs)       = H;
    *(uint4*)(osplit + ofs + 256) = L;
}

// ---------------------------------------------------------------------------
// Weight prep: B_ext[k_ext][n] with k_ext rows [hi, hi, lo] from w[k][n].
// grid (768, 5); by 0-3 -> B_qkvg col block, by 4 -> B_o.
// ---------------------------------------------------------------------------
__global__ __launch_bounds__(256) void wconv_kernel(
    const float* __restrict__ w0, const float* __restrict__ w1,
    const float* __restrict__ w2, const float* __restrict__ w3,
    const float* __restrict__ w4,
    __nv_bfloat16* __restrict__ Bqkvg, __nv_bfloat16* __restrict__ Bo)
{
    const float* ws[5] = {w0, w1, w2, w3, w4};
    const int k   = blockIdx.x;        // 0..767
    const int wi  = blockIdx.y;        // 0..4
    const int n   = threadIdx.x;       // 0..255
    const int ks  = k & 255;
    const int seg = k >> 8;            // 0,1 -> hi ; 2 -> lo
    float x = ws[wi][ks * 256 + n];
    __nv_bfloat16 h = __float2bfloat16_rn(x);
    __nv_bfloat16 v = (seg < 2) ? h : __float2bfloat16_rn(x - __bfloat162float(h));
    if (wi < 4) Bqkvg[(size_t)k * 1024 + wi * 256 + n] = v;
    else        Bo[(size_t)k * 256 + n] = v;
}

// ---------------------------------------------------------------------------
// bf16 GEMM via mma.sync: C[M=65536, Nb] = A_ext[M, 768] @ B_ext[768, Nb]
// A physical [row][512] (hi|lo); k-chunk kb in [0,12): A col = (kb<8?kb:kb-8)*64
// Block tile 128x128, 3-stage cp.async pipeline, warp tile 64x32.
// Output column block -> one of 4 f32 buffers (256-wide each) + optional bias.
// ---------------------------------------------------------------------------
#define STAGE_BYTES 32768   // A 16KB + B 16KB
#define NSTAGE 3
#define GEMM_SMEM (NSTAGE * STAGE_BYTES)

__device__ __forceinline__ void ld_chunk(
    uint32_t sbase, const __nv_bfloat16* __restrict__ A,
    const __nv_bfloat16* __restrict__ B, int Nb,
    size_t row0, int n0, int kb, int tid)
{
    const int a_off = (kb < 8 ? kb : kb - 8) * 64;
    #pragma unroll
    for (int t = 0; t < 4; t++) {
        const int i = tid + t * 256;
        const int r = i >> 3, c8 = i & 7;
        cp_async16(sbase + SWZ((uint32_t)(r * 128 + c8 * 16)),
                   A + (row0 + r) * 512 + a_off + c8 * 8);
    }
    const uint32_t bbase = sbase + 16384;
    #pragma unroll
    for (int t = 0; t < 4; t++) {
        const int i = tid + t * 256;
        const int k = i >> 4, u = i & 15;
        const uint32_t sub = (u >= 8) ? 8192u : 0u;
        cp_async16(bbase + sub + SWZ((uint32_t)(k * 128 + (u & 7) * 16)),
                   B + (size_t)(kb * 64 + k) * Nb + n0 + u * 8);
    }
}

__global__ __launch_bounds__(256) void gemm_mma(
    const __nv_bfloat16* __restrict__ A, const __nv_bfloat16* __restrict__ B,
    int Nb,
    float* C0, float* C1, float* C2, float* C3,
    const float* bias0, const float* bias1,
    const float* bias2, const float* bias3)
{
    extern __shared__ char smem[];
    const uint32_t sb = smem_u32(smem);
    const int tid  = threadIdx.x;
    const int warp = tid >> 5, lane = tid & 31;
    const int wm = (warp >> 2) * 64;        // 0 or 64
    const int wn = (warp & 3) * 32;         // 0,32,64,96
    const size_t row0 = (size_t)blockIdx.y * 128;
    const int n0 = blockIdx.x * 128;

    // Prologue: stages 0,1,2 <- chunks 0,1,2
    #pragma unroll
    for (int s = 0; s < 3; s++) {
        ld_chunk(sb + s * STAGE_BYTES, A, B, Nb, row0, n0, s, tid);
        CP_COMMIT();
    }

    float acc[4][4][4];
    #pragma unroll
    for (int i = 0; i < 4; i++)
        #pragma unroll
        for (int j = 0; j < 4; j++)
            #pragma unroll
            for (int x = 0; x < 4; x++) acc[i][j][x] = 0.0f;

    const int lr  = lane & 15;      // row within 16
    const int lh  = lane >> 4;      // 0/1 -> k-half / n-half
    const uint32_t bsub = (wn >= 64) ? 8192u : 0u;
    const int wn2 = wn & 63;

    #pragma unroll 1
    for (int kb = 0; kb < 12; kb++) {
        CP_WAIT2();
        __syncthreads();
        const int stg = kb % 3;
        const uint32_t As = sb + stg * STAGE_BYTES;
        const uint32_t Bs = As + 16384 + bsub;

        #pragma unroll
        for (int kk = 0; kk < 4; kk++) {
            uint32_t a[4][4];
            #pragma unroll
            for (int i = 0; i < 4; i++)
                ldsm4(a[i], As + SWZ((uint32_t)((wm + i * 16 + lr) * 128
                                                + (kk * 16 + lh * 8) * 2)));
            uint32_t bfr[2][4];
            #pragma unroll
            for (int j2 = 0; j2 < 2; j2++)
                ldsm4t(bfr[j2], Bs + SWZ((uint32_t)((kk * 16 + lr) * 128
                                                + (wn2 + j2 * 16 + lh * 8) * 2)));
            #pragma unroll
            for (int i = 0; i < 4; i++)
                #pragma unroll
                for (int j = 0; j < 4; j++)
                    mma_bf16(acc[i][j], a[i],
                             bfr[j >> 1][(j & 1) * 2], bfr[j >> 1][(j & 1) * 2 + 1]);
        }
        __syncthreads();
        if (kb + 3 < 12) ld_chunk(sb + stg * STAGE_BYTES, A, B, Nb, row0, n0, kb + 3, tid);
        CP_COMMIT();
    }

    // Output buffer select: 256-wide buffers; global col = n0 + local
    const int buf = (n0 >> 8) & 3;
    float* C = (buf == 0) ? C0 : (buf == 1) ? C1 : (buf == 2) ? C2 : C3;
    const float* bias = (buf == 0) ? bias0 : (buf == 1) ? bias1
                       : (buf == 2) ? bias2 : bias3;
    const int colbase = (n0 & 255) + wn + (lane & 3) * 2;

    #pragma unroll
    for (int i = 0; i < 4; i++) {
        const size_t r0 = row0 + wm + i * 16 + (lane >> 2);
        #pragma unroll
        for (int j = 0; j < 4; j++) {
            const int col = colbase + j * 8;
            float bx = 0.f, by = 0.f;
            if (bias) { bx = bias[col]; by = bias[col + 1]; }
            float2 v0 = make_float2(acc[i][j][0] + bx, acc[i][j][1] + by);
            float2 v1 = make_float2(acc[i][j][2] + bx, acc[i][j][3] + by);
            *(float2*)(C + r0 * 256 + col)       = v0;
            *(float2*)(C + (r0 + 8) * 256 + col) = v1;
        }
    }
}

// ---------------------------------------------------------------------------
// Attention per (l, h) tile, flash-style online softmax (fp32); epilogue
// applies the reference's scrambling reshape + sigmoid gate and writes
// split bf16 [row][512] for the output projection.
//   s' = h*32 + l/8 ; l' = (l%8)*32 + s/8 ; c' = (s%8)*32 + c
// ---------------------------------------------------------------------------
__global__ __launch_bounds__(256, 2) void attn_kernel(
    const float* __restrict__ Qg, const float* __restrict__ Kg,
    const float* __restrict__ Vg, const float* __restrict__ Gg,
    __nv_bfloat16* __restrict__ Osplit)
{
    extern __shared__ float sh[];
    float* Ks = sh;         // 256*32
    float* Vs = sh + 8192;  // 256*32

    const int l   = blockIdx.x >> 3;
    const int h   = blockIdx.x & 7;
    const int tid = threadIdx.x;

    const size_t base0 = (size_t)l * HC_DIM + h * CH;

    #pragma unroll
    for (int i = 0; i < 8; i++) {
        const int idx = i * 256 + tid;
        const int t   = idx >> 3;
        const int cc  = idx & 7;
        const size_t gofs = base0 + (size_t)t * HC_DIM * L_DIM + cc * 4;
        *(float4*)(Ks + t * 32 + cc * 4) = *(const float4*)(Kg + gofs);
        *(float4*)(Vs + t * 32 + cc * 4) = *(const float4*)(Vg + gofs);
    }

    float q[32];
    {
        const size_t qofs = base0 + (size_t)tid * HC_DIM * L_DIM;
        #pragma unroll
        for (int cc = 0; cc < 8; cc++) {
            float4 t4 = *(const float4*)(Qg + qofs + cc * 4);
            q[cc * 4 + 0] = t4.x; q[cc * 4 + 1] = t4.y;
            q[cc * 4 + 2] = t4.z; q[cc * 4 + 3] = t4.w;
        }
    }
    __syncthreads();

    float o[32];
    #pragma unroll
    for (int c = 0; c < 32; c++) o[c] = 0.0f;
    float mx = -3.0e38f, sum = 0.0f;
    const float scale = 0.17677669529663689f;  // 1/sqrt(32)

    for (int t0 = 0; t0 < 256; t0 += 16) {
        float x[16];
        #pragma unroll
        for (int tt = 0; tt < 16; tt++) {
            const float4* kr = (const float4*)(Ks + (t0 + tt) * 32);
            float a0 = 0.f, a1 = 0.f, a2 = 0.f, a3 = 0.f;
            #pragma unroll
            for (int cc = 0; cc < 8; cc++) {
                float4 kk = kr[cc];
                a0 = fmaf(q[cc * 4 + 0], kk.x, a0);
                a1 = fmaf(q[cc * 4 + 1], kk.y, a1);
                a2 = fmaf(q[cc * 4 + 2], kk.z, a2);
                a3 = fmaf(q[cc * 4 + 3], kk.w, a3);
            }
            x[tt] = ((a0 + a1) + (a2 + a3)) * scale;
        }
        float cm = mx;
        #pragma unroll
        for (int tt = 0; tt < 16; tt++) cm = fmaxf(cm, x[tt]);
        const float f = __expf(mx - cm);
        mx = cm;
        sum *= f;
        #pragma unroll
        for (int c = 0; c < 32; c++) o[c] *= f;
        #pragma unroll
        for (int tt = 0; tt < 16; tt++) {
            const float p = __expf(x[tt] - mx);
            sum += p;
            const float4* vr = (const float4*)(Vs + (t0 + tt) * 32);
            #pragma unroll
            for (int cc = 0; cc < 8; cc++) {
                float4 vv = vr[cc];
                o[cc * 4 + 0] = fmaf(p, vv.x, o[cc * 4 + 0]);
                o[cc * 4 + 1] = fmaf(p, vv.y, o[cc * 4 + 1]);
                o[cc * 4 + 2] = fmaf(p, vv.z, o[cc * 4 + 2]);
                o[cc * 4 + 3] = fmaf(p, vv.w, o[cc * 4 + 3]);
            }
        }
    }
    const float inv = 1.0f / sum;

    const int i_o = h * 32 + (l >> 3);
    const int j_o = ((l & 7) << 5) + (tid >> 3);
    const int k_o = (tid & 7) << 5;
    const size_t obase = ((size_t)i_o * 256 + j_o) * 512 + k_o;
    #pragma unroll
    for (int q8 = 0; q8 < 4; q8++) {
        float4 g0 = *(const float4*)(Gg + ((obase >> 1) * 1 + 0));  // placeholder
        (void)g0;
        // recompute gate base in the 256-wide G layout:
        const size_t gbase = ((size_t)i_o * 256 + j_o) * 256 + k_o;
        float4 ga = *(const float4*)(Gg + gbase + q8 * 8);
        float4 gb = *(const float4*)(Gg + gbase + q8 * 8 + 4);
        float vals[8];
        vals[0] = o[q8 * 8 + 0] * inv / (1.0f + __expf(-ga.x));
        vals[1] = o[q8 * 8 + 1] * inv / (1.0f + __expf(-ga.y));
        vals[2] = o[q8 * 8 + 2] * inv / (1.0f + __expf(-ga.z));
        vals[3] = o[q8 * 8 + 3] * inv / (1.0f + __expf(-ga.w));
        vals[4] = o[q8 * 8 + 4] * inv / (1.0f + __expf(-gb.x));
        vals[5] = o[q8 * 8 + 5] * inv / (1.0f + __expf(-gb.y));
        vals[6] = o[q8 * 8 + 6] * inv / (1.0f + __expf(-gb.z));
        vals[7] = o[q8 * 8 + 7] * inv / (1.0f + __expf(-gb.w));
        uint4 H, L;
        split2(vals[0], vals[1], H.x, L.x);
        split2(vals[2], vals[3], H.y, L.y);
        split2(vals[4], vals[5], H.z, L.z);
        split2(vals[6], vals[7], H.w, L.w);
        *(uint4*)(Osplit + obase + q8 * 8)       = H;
        *(uint4*)(Osplit + obase + q8 * 8 + 256) = L;
    }
}

// ---------------------------------------------------------------------------
extern "C" void kernel_launch(void* const* d_in, const int* in_sizes, int n_in,
                              void* d_out, int out_size)
{
    const float* m    = (const float*)d_in[0];
    const float* ln_w = (const float*)d_in[1];
    const float* ln_b = (const float*)d_in[2];
    const float* wq   = (const float*)d_in[3];
    const float* wk   = (const float*)d_in[4];
    const float* wv   = (const float*)d_in[5];
    const float* wg   = (const float*)d_in[6];
    const float* bg   = (const float*)d_in[7];
    const float* wo   = (const float*)d_in[8];
    const float* bo   = (const float*)d_in[9];
    float* out = (float*)d_out;

    __nv_bfloat16 *mns, *ats, *Bq, *Bo;
    float *q, *k, *v, *g;
    cudaGetSymbolAddress((void**)&mns, g_mn_split);
    cudaGetSymbolAddress((void**)&ats, g_att_split);
    cudaGetSymbolAddress((void**)&q,   g_q);
    cudaGetSymbolAddress((void**)&k,   g_k);
    cudaGetSymbolAddress((void**)&v,   g_v);
    cudaGetSymbolAddress((void**)&g,   g_g);
    cudaGetSymbolAddress((void**)&Bq,  g_Bqkvg);
    cudaGetSymbolAddress((void**)&Bo,  g_Bo);

    cudaFuncSetAttribute(gemm_mma,
                         cudaFuncAttributeMaxDynamicSharedMemorySize, GEMM_SMEM);
    cudaFuncSetAttribute(attn_kernel,
                         cudaFuncAttributeMaxDynamicSharedMemorySize, 65536);

    // 1. LayerNorm -> split bf16
    ln_kernel<<<NROWS / 8, 256>>>(m, ln_w, ln_b, mns);

    // 2. Weight prep (K-extended split bf16)
    wconv_kernel<<<dim3(768, 5), 256>>>(wq, wk, wv, wg, wo, Bq, Bo);

    // 3. Fused Q/K/V/G projection: [65536,768] @ [768,1024]
    gemm_mma<<<dim3(8, NROWS / 128), 256, GEMM_SMEM>>>(
        mns, Bq, 1024, q, k, v, g, nullptr, nullptr, nullptr, bg);

    // 4. Attention + scramble + gate -> split bf16
    attn_kernel<<<L_DIM * NH, 256, 65536>>>(q, k, v, g, ats);

    // 5. Output projection: [65536,768] @ [768,256] -> d_out
    gemm_mma<<<dim3(2, NROWS / 128), 256, GEMM_SMEM>>>(
        ats, Bo, 256, out, nullptr, nullptr, nullptr, bo, nullptr, nullptr, nullptr);
}

// round 5
// speedup vs baseline: 2.5427x; 1.4235x over previous
#include <cuda_runtime.h>
#include <cuda_bf16.h>
#include <cstdint>
#include <math.h>

// Problem constants: B=1, n_seq=S=256, seq_len=L=256, c_m=256, H=8, ch=32, HC=256
#define S_DIM 256
#define L_DIM 256
#define C_DIM 256
#define HC_DIM 256
#define NH 8
#define CH 32
#define NROWS (S_DIM * L_DIM)  // 65536

// ---------------------------------------------------------------------------
// Scratch (device globals per allocation rules)
// ---------------------------------------------------------------------------
// A operands for GEMMs, split layout [row][512]: cols 0-255 hi, 256-511 lo
__device__ __align__(16) __nv_bfloat16 g_mn_split[NROWS * 512];
__device__ __align__(16) __nv_bfloat16 g_att_split[NROWS * 512];
// Q/K/V attention-tile layout: [(l*8+h)][s][64] rows = [hi32|lo32] bf16
// size = 2048 tiles * 256 * 64 = NROWS * 512  (R4 bug: was NROWS*64 -> OOB)
__device__ __align__(16) __nv_bfloat16 g_qs[NROWS * 512];
__device__ __align__(16) __nv_bfloat16 g_ks[NROWS * 512];
__device__ __align__(16) __nv_bfloat16 g_vs[NROWS * 512];
// Gate stays f32 [row][256]
__device__ __align__(16) float g_g[NROWS * HC_DIM];
// B operands, K-extended to 768: rows [0,256)=hi, [256,512)=hi, [512,768)=lo
__device__ __align__(16) __nv_bfloat16 g_Bqkvg[768 * 1024];  // cols: q|k|v|g
__device__ __align__(16) __nv_bfloat16 g_Bo[768 * 256];

// ---------------------------------------------------------------------------
// Helpers
// ---------------------------------------------------------------------------
__device__ __forceinline__ uint32_t smem_u32(const void* p) {
    uint32_t a;
    asm("{ .reg .u64 t; cvta.to.shared.u64 t, %1; cvt.u32.u64 %0, t; }"
        : "=r"(a) : "l"(p));
    return a;
}

#define SWZ(o) ((o) ^ (((o) >> 3) & 0x70))

__device__ __forceinline__ void cp_async16(uint32_t saddr, const void* gptr) {
    asm volatile("cp.async.cg.shared.global [%0], [%1], 16;"
                 :: "r"(saddr), "l"(__cvta_generic_to_global(gptr)) : "memory");
}
#define CP_COMMIT() asm volatile("cp.async.commit_group;" ::: "memory")
#define CP_WAIT2()  asm volatile("cp.async.wait_group 2;" ::: "memory")
#define CP_WAIT0()  asm volatile("cp.async.wait_group 0;" ::: "memory")

__device__ __forceinline__ void ldsm4(uint32_t* r, uint32_t addr) {
    asm volatile("ldmatrix.sync.aligned.m8n8.x4.shared.b16 {%0,%1,%2,%3}, [%4];"
                 : "=r"(r[0]), "=r"(r[1]), "=r"(r[2]), "=r"(r[3]) : "r"(addr));
}
__device__ __forceinline__ void ldsm4t(uint32_t* r, uint32_t addr) {
    asm volatile("ldmatrix.sync.aligned.m8n8.x4.trans.shared.b16 {%0,%1,%2,%3}, [%4];"
                 : "=r"(r[0]), "=r"(r[1]), "=r"(r[2]), "=r"(r[3]) : "r"(addr));
}
__device__ __forceinline__ void mma_bf16(float* c, const uint32_t* a,
                                         uint32_t b0, uint32_t b1) {
    asm volatile(
        "mma.sync.aligned.m16n8k16.row.col.f32.bf16.bf16.f32 "
        "{%0,%1,%2,%3}, {%4,%5,%6,%7}, {%8,%9}, {%0,%1,%2,%3};"
        : "+f"(c[0]), "+f"(c[1]), "+f"(c[2]), "+f"(c[3])
        : "r"(a[0]), "r"(a[1]), "r"(a[2]), "r"(a[3]), "r"(b0), "r"(b1));
}

// fp32 -> bf16 hi/lo split (packed pairs)
__device__ __forceinline__ void split2(float a, float b, uint32_t& h, uint32_t& l) {
    __nv_bfloat162 hb = __floats2bfloat162_rn(a, b);
    float la = a - __bfloat162float(hb.x);
    float lb = b - __bfloat162float(hb.y);
    __nv_bfloat162 lo = __floats2bfloat162_rn(la, lb);
    h = *reinterpret_cast<uint32_t*>(&hb);
    l = *reinterpret_cast<uint32_t*>(&lo);
}

// ---------------------------------------------------------------------------
// LayerNorm -> split bf16 [row][512]. One warp per row.
// ---------------------------------------------------------------------------
__global__ __launch_bounds__(256) void ln_kernel(
    const float* __restrict__ m, const float* __restrict__ w,
    const float* __restrict__ b, __nv_bfloat16* __restrict__ osplit)
{
    const int warp = threadIdx.x >> 5;
    const int lane = threadIdx.x & 31;
    const int row  = blockIdx.x * 8 + warp;

    const float4* x4 = (const float4*)(m + (size_t)row * C_DIM);
    float4 v0 = x4[lane * 2 + 0];
    float4 v1 = x4[lane * 2 + 1];

    float s1 = (v0.x + v0.y) + (v0.z + v0.w) + (v1.x + v1.y) + (v1.z + v1.w);
    float s2 = v0.x * v0.x + v0.y * v0.y + v0.z * v0.z + v0.w * v0.w
             + v1.x * v1.x + v1.y * v1.y + v1.z * v1.z + v1.w * v1.w;
    #pragma unroll
    for (int o = 16; o > 0; o >>= 1) {
        s1 += __shfl_xor_sync(0xffffffffu, s1, o);
        s2 += __shfl_xor_sync(0xffffffffu, s2, o);
    }
    const float mu  = s1 * (1.0f / 256.0f);
    const float var = s2 * (1.0f / 256.0f) - mu * mu;
    const float rs  = rsqrtf(var + 1e-5f);

    const float4* w4 = (const float4*)w;
    const float4* b4 = (const float4*)b;
    float4 w0 = w4[lane * 2 + 0], w1 = w4[lane * 2 + 1];
    float4 b0 = b4[lane * 2 + 0], b1 = b4[lane * 2 + 1];

    float r[8];
    r[0] = (v0.x - mu) * rs * w0.x + b0.x;
    r[1] = (v0.y - mu) * rs * w0.y + b0.y;
    r[2] = (v0.z - mu) * rs * w0.z + b0.z;
    r[3] = (v0.w - mu) * rs * w0.w + b0.w;
    r[4] = (v1.x - mu) * rs * w1.x + b1.x;
    r[5] = (v1.y - mu) * rs * w1.y + b1.y;
    r[6] = (v1.z - mu) * rs * w1.z + b1.z;
    r[7] = (v1.w - mu) * rs * w1.w + b1.w;

    uint4 H, L;
    split2(r[0], r[1], H.x, L.x);
    split2(r[2], r[3], H.y, L.y);
    split2(r[4], r[5], H.z, L.z);
    split2(r[6], r[7], H.w, L.w);
    const size_t ofs = (size_t)row * 512 + lane * 8;
    *(uint4*)(osplit + ofs)       = H;
    *(uint4*)(osplit + ofs + 256) = L;
}

// ---------------------------------------------------------------------------
// Weight prep: B_ext[k_ext][n] with k_ext rows [hi, hi, lo] from w[k][n].
// ---------------------------------------------------------------------------
__global__ __launch_bounds__(256) void wconv_kernel(
    const float* __restrict__ w0, const float* __restrict__ w1,
    const float* __restrict__ w2, const float* __restrict__ w3,
    const float* __restrict__ w4,
    __nv_bfloat16* __restrict__ Bqkvg, __nv_bfloat16* __restrict__ Bo)
{
    const float* ws[5] = {w0, w1, w2, w3, w4};
    const int k   = blockIdx.x;        // 0..767
    const int wi  = blockIdx.y;        // 0..4
    const int n   = threadIdx.x;       // 0..255
    const int ks  = k & 255;
    const int seg = k >> 8;            // 0,1 -> hi ; 2 -> lo
    float x = ws[wi][ks * 256 + n];
    __nv_bfloat16 h = __float2bfloat16_rn(x);
    __nv_bfloat16 v = (seg < 2) ? h : __float2bfloat16_rn(x - __bfloat162float(h));
    if (wi < 4) Bqkvg[(size_t)k * 1024 + wi * 256 + n] = v;
    else        Bo[(size_t)k * 256 + n] = v;
}

// ---------------------------------------------------------------------------
// bf16 GEMM via mma.sync: C[M=65536, Nb] = A_ext[M,768] @ B_ext[768,Nb]
// qkv_mode=1: bufs 0..2 scatter split-bf16 into attention-tile layout,
//             buf 3 writes f32 (+bias). qkv_mode=0: buf 0 f32 (+bias).
// ---------------------------------------------------------------------------
#define STAGE_BYTES 32768
#define NSTAGE 3
#define GEMM_SMEM (NSTAGE * STAGE_BYTES)

__device__ __forceinline__ void ld_chunk(
    uint32_t sbase, const __nv_bfloat16* __restrict__ A,
    const __nv_bfloat16* __restrict__ B, int Nb,
    size_t row0, int n0, int kb, int tid)
{
    const int a_off = (kb < 8 ? kb : kb - 8) * 64;
    #pragma unroll
    for (int t = 0; t < 4; t++) {
        const int i = tid + t * 256;
        const int r = i >> 3, c8 = i & 7;
        cp_async16(sbase + SWZ((uint32_t)(r * 128 + c8 * 16)),
                   A + (row0 + r) * 512 + a_off + c8 * 8);
    }
    const uint32_t bbase = sbase + 16384;
    #pragma unroll
    for (int t = 0; t < 4; t++) {
        const int i = tid + t * 256;
        const int k = i >> 4, u = i & 15;
        const uint32_t sub = (u >= 8) ? 8192u : 0u;
        cp_async16(bbase + sub + SWZ((uint32_t)(k * 128 + (u & 7) * 16)),
                   B + (size_t)(kb * 64 + k) * Nb + n0 + u * 8);
    }
}

__global__ __launch_bounds__(256) void gemm_mma(
    const __nv_bfloat16* __restrict__ A, const __nv_bfloat16* __restrict__ B,
    int Nb, int qkv_mode,
    void* C0, void* C1, void* C2, void* C3,
    const float* bias0, const float* bias3)
{
    extern __shared__ char smem[];
    const uint32_t sb = smem_u32(smem);
    const int tid  = threadIdx.x;
    const int warp = tid >> 5, lane = tid & 31;
    const int wm = (warp >> 2) * 64;
    const int wn = (warp & 3) * 32;
    const size_t row0 = (size_t)blockIdx.y * 128;
    const int n0 = blockIdx.x * 128;

    #pragma unroll
    for (int s = 0; s < 3; s++) {
        ld_chunk(sb + s * STAGE_BYTES, A, B, Nb, row0, n0, s, tid);
        CP_COMMIT();
    }

    float acc[4][4][4];
    #pragma unroll
    for (int i = 0; i < 4; i++)
        #pragma unroll
        for (int j = 0; j < 4; j++)
            #pragma unroll
            for (int x = 0; x < 4; x++) acc[i][j][x] = 0.0f;

    const int lr  = lane & 15;
    const int lh  = lane >> 4;
    const uint32_t bsub = (wn >= 64) ? 8192u : 0u;
    const int wn2 = wn & 63;

    #pragma unroll 1
    for (int kb = 0; kb < 12; kb++) {
        CP_WAIT2();
        __syncthreads();
        const int stg = kb % 3;
        const uint32_t As = sb + stg * STAGE_BYTES;
        const uint32_t Bs = As + 16384 + bsub;

        #pragma unroll
        for (int kk = 0; kk < 4; kk++) {
            uint32_t a[4][4];
            #pragma unroll
            for (int i = 0; i < 4; i++)
                ldsm4(a[i], As + SWZ((uint32_t)((wm + i * 16 + lr) * 128
                                                + (kk * 16 + lh * 8) * 2)));
            uint32_t bfr[2][4];
            #pragma unroll
            for (int j2 = 0; j2 < 2; j2++)
                ldsm4t(bfr[j2], Bs + SWZ((uint32_t)((kk * 16 + lr) * 128
                                                + (wn2 + j2 * 16 + lh * 8) * 2)));
            #pragma unroll
            for (int i = 0; i < 4; i++)
                #pragma unroll
                for (int j = 0; j < 4; j++)
                    mma_bf16(acc[i][j], a[i],
                             bfr[j >> 1][(j & 1) * 2], bfr[j >> 1][(j & 1) * 2 + 1]);
        }
        __syncthreads();
        if (kb + 3 < 12) ld_chunk(sb + stg * STAGE_BYTES, A, B, Nb, row0, n0, kb + 3, tid);
        CP_COMMIT();
    }

    const int buf = (n0 >> 8) & 3;
    const int colbase = (n0 & 255) + wn + (lane & 3) * 2;

    if (qkv_mode && buf < 3) {
        __nv_bfloat16* Cq = (__nv_bfloat16*)((buf == 0) ? C0 : (buf == 1) ? C1 : C2);
        #pragma unroll
        for (int i = 0; i < 4; i++) {
            const int r0 = (int)row0 + wm + i * 16 + (lane >> 2);
            #pragma unroll
            for (int j = 0; j < 4; j++) {
                const int col = colbase + j * 8;
                const int hh = col >> 5, cc = col & 31;
                #pragma unroll
                for (int rr = 0; rr < 2; rr++) {
                    const int r = r0 + rr * 8;
                    const int s = r >> 8, ll = r & 255;
                    const size_t dst = ((size_t)(ll * 8 + hh) * 256 + s) * 64 + cc;
                    uint32_t H, L;
                    split2(acc[i][j][rr * 2], acc[i][j][rr * 2 + 1], H, L);
                    *(uint32_t*)(Cq + dst)      = H;
                    *(uint32_t*)(Cq + dst + 32) = L;
                }
            }
        }
    } else {
        float* C = (float*)((qkv_mode) ? C3 : C0);
        const float* bias = (qkv_mode) ? bias3 : bias0;
        #pragma unroll
        for (int i = 0; i < 4; i++) {
            const size_t r0 = row0 + wm + i * 16 + (lane >> 2);
            #pragma unroll
            for (int j = 0; j < 4; j++) {
                const int col = colbase + j * 8;
                float bx = 0.f, by = 0.f;
                if (bias) { bx = bias[col]; by = bias[col + 1]; }
                float2 v0 = make_float2(acc[i][j][0] + bx, acc[i][j][1] + by);
                float2 v1 = make_float2(acc[i][j][2] + bx, acc[i][j][3] + by);
                *(float2*)(C + r0 * 256 + col)       = v0;
                *(float2*)(C + (r0 + 8) * 256 + col) = v1;
            }
        }
    }
}

// ---------------------------------------------------------------------------
// Tensor-core flash attention per (l,h) tile with split-bf16 compensation.
// Q/K/V tiles: [(l*8+h)][s][64] bf16 rows = [hi32|lo32], 128B, SW128 in smem.
// Epilogue: online-softmax normalize, sigmoid gate, scramble-reshape, write
// split bf16 [row][512] for the output projection.
//   s' = h*32 + l/8 ; l' = (l%8)*32 + s/8 ; c' = (s%8)*32 + c
// ---------------------------------------------------------------------------
#define ATT_SMEM (3 * 32768)

__global__ __launch_bounds__(256) void attn_mma_kernel(
    const __nv_bfloat16* __restrict__ Qg, const __nv_bfloat16* __restrict__ Kg,
    const __nv_bfloat16* __restrict__ Vg, const float* __restrict__ Gg,
    __nv_bfloat16* __restrict__ Osplit)
{
    extern __shared__ char smem[];
    const uint32_t sb = smem_u32(smem);
    const uint32_t QS = sb, KS = sb + 32768, VS = sb + 65536;

    const int tile = blockIdx.x;
    const int l = tile >> 3, h = tile & 7;
    const int tid = threadIdx.x;
    const size_t gbase0 = (size_t)tile * 256 * 64;

    // Load Q, K, V tiles (32KB each) via cp.async
    #pragma unroll
    for (int t = 0; t < 8; t++) {
        const int idx = t * 256 + tid;
        const int r = idx >> 3, j = idx & 7;
        const uint32_t so = SWZ((uint32_t)(r * 128 + j * 16));
        const size_t go = gbase0 + (size_t)r * 64 + j * 8;
        cp_async16(QS + so, Qg + go);
        cp_async16(KS + so, Kg + go);
        cp_async16(VS + so, Vg + go);
    }
    CP_COMMIT();
    CP_WAIT0();
    __syncthreads();

    const int warp = tid >> 5, lane = tid & 31;
    const int s0 = warp * 32;
    const int lr = lane & 15, lh = lane >> 4;

    // Q fragments (kept in regs, reused across all t-chunks)
    uint32_t qh[2][2][4], ql[2][2][4];
    #pragma unroll
    for (int m = 0; m < 2; m++)
        #pragma unroll
        for (int kk = 0; kk < 2; kk++) {
            const uint32_t rowb = (uint32_t)(s0 + m * 16 + lr) * 128;
            ldsm4(qh[m][kk], QS + SWZ(rowb + (kk * 16 + lh * 8) * 2));
            ldsm4(ql[m][kk], QS + SWZ(rowb + (32 + kk * 16 + lh * 8) * 2));
        }

    float o[2][4][4];
    #pragma unroll
    for (int m = 0; m < 2; m++)
        #pragma unroll
        for (int j = 0; j < 4; j++)
            #pragma unroll
            for (int x = 0; x < 4; x++) o[m][j][x] = 0.0f;
    float mx[2][2] = {{-1e30f, -1e30f}, {-1e30f, -1e30f}};
    float sm[2][2] = {{0.f, 0.f}, {0.f, 0.f}};
    const float S2 = 0.17677669529663689f * 1.44269504088896f;  // scale*log2e

    #pragma unroll 1
    for (int chunk = 0; chunk < 4; chunk++) {
        const int t0 = chunk * 64;
        float s_acc[2][8][4];
        #pragma unroll
        for (int m = 0; m < 2; m++)
            #pragma unroll
            for (int j = 0; j < 8; j++)
                #pragma unroll
                for (int x = 0; x < 4; x++) s_acc[m][j][x] = 0.0f;

        // ---- S = Q K^T (3 split terms) ----
        #pragma unroll
        for (int g = 0; g < 4; g++) {
            const uint32_t krow = (uint32_t)(t0 + g * 16 + (lane & 7)
                                             + ((lane >> 4) << 3)) * 128;
            const uint32_t colb = ((uint32_t)((lane >> 3) & 1)) * 16;
            uint32_t kh[2][4], kl[2][4];
            #pragma unroll
            for (int ch = 0; ch < 2; ch++) {
                ldsm4(kh[ch], KS + SWZ(krow + (ch * 32 + colb)));
                ldsm4(kl[ch], KS + SWZ(krow + (64 + ch * 32 + colb)));
            }
            #pragma unroll
            for (int m = 0; m < 2; m++)
                #pragma unroll
                for (int ch = 0; ch < 2; ch++) {
                    mma_bf16(s_acc[m][2 * g],     qh[m][ch], kh[ch][0], kh[ch][1]);
                    mma_bf16(s_acc[m][2 * g + 1], qh[m][ch], kh[ch][2], kh[ch][3]);
                    mma_bf16(s_acc[m][2 * g],     ql[m][ch], kh[ch][0], kh[ch][1]);
                    mma_bf16(s_acc[m][2 * g + 1], ql[m][ch], kh[ch][2], kh[ch][3]);
                    mma_bf16(s_acc[m][2 * g],     qh[m][ch], kl[ch][0], kl[ch][1]);
                    mma_bf16(s_acc[m][2 * g + 1], qh[m][ch], kl[ch][2], kl[ch][3]);
                }
        }

        // ---- online softmax ----
        #pragma unroll
        for (int m = 0; m < 2; m++)
            #pragma unroll
            for (int rr = 0; rr < 2; rr++) {
                float cm = mx[m][rr];
                #pragma unroll
                for (int j = 0; j < 8; j++) {
                    cm = fmaxf(cm, s_acc[m][j][rr * 2]);
                    cm = fmaxf(cm, s_acc[m][j][rr * 2 + 1]);
                }
                cm = fmaxf(cm, __shfl_xor_sync(0xffffffffu, cm, 1));
                cm = fmaxf(cm, __shfl_xor_sync(0xffffffffu, cm, 2));
                const float f = exp2f((mx[m][rr] - cm) * S2);
                mx[m][rr] = cm;
                float psum = 0.f;
                #pragma unroll
                for (int j = 0; j < 8; j++) {
                    float p0 = exp2f((s_acc[m][j][rr * 2]     - cm) * S2);
                    float p1 = exp2f((s_acc[m][j][rr * 2 + 1] - cm) * S2);
                    s_acc[m][j][rr * 2]     = p0;
                    s_acc[m][j][rr * 2 + 1] = p1;
                    psum += p0 + p1;
                }
                sm[m][rr] = sm[m][rr] * f + psum;
                #pragma unroll
                for (int j = 0; j < 4; j++) {
                    o[m][j][rr * 2]     *= f;
                    o[m][j][rr * 2 + 1] *= f;
                }
            }

        // ---- O += P V (3 split terms) ----
        #pragma unroll
        for (int g = 0; g < 4; g++) {
            const uint32_t vrow = (uint32_t)(t0 + g * 16 + lr) * 128;
            uint32_t vh[2][4], vl[2][4];
            #pragma unroll
            for (int j2 = 0; j2 < 2; j2++) {
                ldsm4t(vh[j2], VS + SWZ(vrow + (j2 * 16 + lh * 8) * 2));
                ldsm4t(vl[j2], VS + SWZ(vrow + (32 + j2 * 16 + lh * 8) * 2));
            }
            #pragma unroll
            for (int m = 0; m < 2; m++) {
                uint32_t ah[4], al[4];
                split2(s_acc[m][2 * g][0],     s_acc[m][2 * g][1],     ah[0], al[0]);
                split2(s_acc[m][2 * g][2],     s_acc[m][2 * g][3],     ah[1], al[1]);
                split2(s_acc[m][2 * g + 1][0], s_acc[m][2 * g + 1][1], ah[2], al[2]);
                split2(s_acc[m][2 * g + 1][2], s_acc[m][2 * g + 1][3], ah[3], al[3]);
                #pragma unroll
                for (int j = 0; j < 4; j++) {
                    const int j2 = j >> 1, jj = (j & 1) * 2;
                    mma_bf16(o[m][j], ah, vh[j2][jj], vh[j2][jj + 1]);
                    mma_bf16(o[m][j], al, vh[j2][jj], vh[j2][jj + 1]);
                    mma_bf16(o[m][j], ah, vl[j2][jj], vl[j2][jj + 1]);
                }
            }
        }
    }

    // ---- epilogue: normalize, gate, scramble, store split bf16 ----
    const int i_o = h * 32 + (l >> 3);
    #pragma unroll
    for (int m = 0; m < 2; m++)
        #pragma unroll
        for (int rr = 0; rr < 2; rr++) {
            float v = sm[m][rr];
            v += __shfl_xor_sync(0xffffffffu, v, 1);
            v += __shfl_xor_sync(0xffffffffu, v, 2);
            const float inv = 1.0f / v;
            const int s = s0 + m * 16 + (lane >> 2) + rr * 8;
            const int j_o = ((l & 7) << 5) + (s >> 3);
            const int k_o = (s & 7) << 5;
            const size_t gb = ((size_t)i_o * 256 + j_o) * 256 + k_o;
            const size_t ob = ((size_t)i_o * 256 + j_o) * 512 + k_o;
            #pragma unroll
            for (int j = 0; j < 4; j++) {
                const int c = j * 8 + (lane & 3) * 2;
                const float2 gg = *(const float2*)(Gg + gb + c);
                const float w0 = o[m][j][rr * 2] * inv
                                 / (1.0f + exp2f(-gg.x * 1.44269504088896f));
                const float w1 = o[m][j][rr * 2 + 1] * inv
                                 / (1.0f + exp2f(-gg.y * 1.44269504088896f));
                uint32_t H, L;
                split2(w0, w1, H, L);
                *(uint32_t*)(Osplit + ob + c)       = H;
                *(uint32_t*)(Osplit + ob + 256 + c) = L;
            }
        }
}

// ---------------------------------------------------------------------------
extern "C" void kernel_launch(void* const* d_in, const int* in_sizes, int n_in,
                              void* d_out, int out_size)
{
    const float* m    = (const float*)d_in[0];
    const float* ln_w = (const float*)d_in[1];
    const float* ln_b = (const float*)d_in[2];
    const float* wq   = (const float*)d_in[3];
    const float* wk   = (const float*)d_in[4];
    const float* wv   = (const float*)d_in[5];
    const float* wg   = (const float*)d_in[6];
    const float* bg   = (const float*)d_in[7];
    const float* wo   = (const float*)d_in[8];
    const float* bo   = (const float*)d_in[9];
    float* out = (float*)d_out;

    __nv_bfloat16 *mns, *ats, *Bq, *Bo, *qs, *ks, *vs;
    float *g;
    cudaGetSymbolAddress((void**)&mns, g_mn_split);
    cudaGetSymbolAddress((void**)&ats, g_att_split);
    cudaGetSymbolAddress((void**)&qs,  g_qs);
    cudaGetSymbolAddress((void**)&ks,  g_ks);
    cudaGetSymbolAddress((void**)&vs,  g_vs);
    cudaGetSymbolAddress((void**)&g,   g_g);
    cudaGetSymbolAddress((void**)&Bq,  g_Bqkvg);
    cudaGetSymbolAddress((void**)&Bo,  g_Bo);

    cudaFuncSetAttribute(gemm_mma,
                         cudaFuncAttributeMaxDynamicSharedMemorySize, GEMM_SMEM);
    cudaFuncSetAttribute(attn_mma_kernel,
                         cudaFuncAttributeMaxDynamicSharedMemorySize, ATT_SMEM);

    // 1. LayerNorm -> split bf16
    ln_kernel<<<NROWS / 8, 256>>>(m, ln_w, ln_b, mns);

    // 2. Weight prep
    wconv_kernel<<<dim3(768, 5), 256>>>(wq, wk, wv, wg, wo, Bq, Bo);

    // 3. Fused Q/K/V/G projection: [65536,768] @ [768,1024]
    //    q/k/v scattered to attention-tile split-bf16; g -> f32 (+bg)
    gemm_mma<<<dim3(8, NROWS / 128), 256, GEMM_SMEM>>>(
        mns, Bq, 1024, 1, qs, ks, vs, g, nullptr, bg);

    // 4. Tensor-core flash attention + gate + scramble -> split bf16
    attn_mma_kernel<<<L_DIM * NH, 256, ATT_SMEM>>>(qs, ks, vs, g, ats);

    // 5. Output projection: [65536,768] @ [768,256] -> d_out (+bo)
    gemm_mma<<<dim3(2, NROWS / 128), 256, GEMM_SMEM>>>(
        ats, Bo, 256, 0, out, nullptr, nullptr, nullptr, bo, nullptr);
}

// round 6
// speedup vs baseline: 2.6313x; 1.0348x over previous
#include <cuda_runtime.h>
#include <cuda_bf16.h>
#include <cstdint>
#include <math.h>

// Problem constants: B=1, n_seq=S=256, seq_len=L=256, c_m=256, H=8, ch=32, HC=256
#define S_DIM 256
#define L_DIM 256
#define C_DIM 256
#define HC_DIM 256
#define NH 8
#define CH 32
#define NROWS (S_DIM * L_DIM)  // 65536

// ---------------------------------------------------------------------------
// Scratch (device globals per allocation rules)
// ---------------------------------------------------------------------------
// A operands for GEMMs, split layout [row][512]: cols 0-255 hi, 256-511 lo
__device__ __align__(16) __nv_bfloat16 g_mn_split[NROWS * 512];
__device__ __align__(16) __nv_bfloat16 g_att_split[NROWS * 512];
// Q/K/V attention-tile layout: [(l*8+h)][s][64] rows = [hi32|lo32] bf16
__device__ __align__(16) __nv_bfloat16 g_qs[NROWS * 512];
__device__ __align__(16) __nv_bfloat16 g_ks[NROWS * 512];
__device__ __align__(16) __nv_bfloat16 g_vs[NROWS * 512];
// Gate stays f32 [row][256]
__device__ __align__(16) float g_g[NROWS * HC_DIM];
// B operands, K-extended to 768: rows [0,256)=hi, [256,512)=hi, [512,768)=lo
__device__ __align__(16) __nv_bfloat16 g_Bqkvg[768 * 1024];  // cols: q|k|v|g
__device__ __align__(16) __nv_bfloat16 g_Bo[768 * 256];

// ---------------------------------------------------------------------------
// Helpers
// ---------------------------------------------------------------------------
__device__ __forceinline__ uint32_t smem_u32(const void* p) {
    uint32_t a;
    asm("{ .reg .u64 t; cvta.to.shared.u64 t, %1; cvt.u32.u64 %0, t; }"
        : "=r"(a) : "l"(p));
    return a;
}

#define SWZ(o) ((o) ^ (((o) >> 3) & 0x70))

__device__ __forceinline__ void cp_async16(uint32_t saddr, const void* gptr) {
    asm volatile("cp.async.cg.shared.global [%0], [%1], 16;"
                 :: "r"(saddr), "l"(__cvta_generic_to_global(gptr)) : "memory");
}
#define CP_COMMIT() asm volatile("cp.async.commit_group;" ::: "memory")
#define CP_WAIT2()  asm volatile("cp.async.wait_group 2;" ::: "memory")
#define CP_WAIT0()  asm volatile("cp.async.wait_group 0;" ::: "memory")

__device__ __forceinline__ void ldsm4(uint32_t* r, uint32_t addr) {
    asm volatile("ldmatrix.sync.aligned.m8n8.x4.shared.b16 {%0,%1,%2,%3}, [%4];"
                 : "=r"(r[0]), "=r"(r[1]), "=r"(r[2]), "=r"(r[3]) : "r"(addr));
}
__device__ __forceinline__ void ldsm4t(uint32_t* r, uint32_t addr) {
    asm volatile("ldmatrix.sync.aligned.m8n8.x4.trans.shared.b16 {%0,%1,%2,%3}, [%4];"
                 : "=r"(r[0]), "=r"(r[1]), "=r"(r[2]), "=r"(r[3]) : "r"(addr));
}
__device__ __forceinline__ void mma_bf16(float* c, const uint32_t* a,
                                         uint32_t b0, uint32_t b1) {
    asm volatile(
        "mma.sync.aligned.m16n8k16.row.col.f32.bf16.bf16.f32 "
        "{%0,%1,%2,%3}, {%4,%5,%6,%7}, {%8,%9}, {%0,%1,%2,%3};"
        : "+f"(c[0]), "+f"(c[1]), "+f"(c[2]), "+f"(c[3])
        : "r"(a[0]), "r"(a[1]), "r"(a[2]), "r"(a[3]), "r"(b0), "r"(b1));
}

// fp32 -> bf16 hi/lo split (packed pairs), bit-trick reconstruction:
// bf16 -> f32 is a 16-bit left shift, no CVT needed for the hi readback.
__device__ __forceinline__ void split2(float a, float b, uint32_t& h, uint32_t& l) {
    uint32_t hb;
    asm("cvt.rn.bf16x2.f32 %0, %1, %2;" : "=r"(hb) : "f"(b), "f"(a));
    const float fa = __uint_as_float(hb << 16);
    const float fb = __uint_as_float(hb & 0xffff0000u);
    const float la = a - fa;
    const float lb = b - fb;
    uint32_t lo;
    asm("cvt.rn.bf16x2.f32 %0, %1, %2;" : "=r"(lo) : "f"(lb), "f"(la));
    h = hb;
    l = lo;
}

// ---------------------------------------------------------------------------
// LayerNorm -> split bf16 [row][512]. One warp per row.
// ---------------------------------------------------------------------------
__global__ __launch_bounds__(256) void ln_kernel(
    const float* __restrict__ m, const float* __restrict__ w,
    const float* __restrict__ b, __nv_bfloat16* __restrict__ osplit)
{
    const int warp = threadIdx.x >> 5;
    const int lane = threadIdx.x & 31;
    const int row  = blockIdx.x * 8 + warp;

    const float4* x4 = (const float4*)(m + (size_t)row * C_DIM);
    float4 v0 = x4[lane * 2 + 0];
    float4 v1 = x4[lane * 2 + 1];

    float s1 = (v0.x + v0.y) + (v0.z + v0.w) + (v1.x + v1.y) + (v1.z + v1.w);
    float s2 = v0.x * v0.x + v0.y * v0.y + v0.z * v0.z + v0.w * v0.w
             + v1.x * v1.x + v1.y * v1.y + v1.z * v1.z + v1.w * v1.w;
    #pragma unroll
    for (int o = 16; o > 0; o >>= 1) {
        s1 += __shfl_xor_sync(0xffffffffu, s1, o);
        s2 += __shfl_xor_sync(0xffffffffu, s2, o);
    }
    const float mu  = s1 * (1.0f / 256.0f);
    const float var = s2 * (1.0f / 256.0f) - mu * mu;
    const float rs  = rsqrtf(var + 1e-5f);

    const float4* w4 = (const float4*)w;
    const float4* b4 = (const float4*)b;
    float4 w0 = w4[lane * 2 + 0], w1 = w4[lane * 2 + 1];
    float4 b0 = b4[lane * 2 + 0], b1 = b4[lane * 2 + 1];

    float r[8];
    r[0] = (v0.x - mu) * rs * w0.x + b0.x;
    r[1] = (v0.y - mu) * rs * w0.y + b0.y;
    r[2] = (v0.z - mu) * rs * w0.z + b0.z;
    r[3] = (v0.w - mu) * rs * w0.w + b0.w;
    r[4] = (v1.x - mu) * rs * w1.x + b1.x;
    r[5] = (v1.y - mu) * rs * w1.y + b1.y;
    r[6] = (v1.z - mu) * rs * w1.z + b1.z;
    r[7] = (v1.w - mu) * rs * w1.w + b1.w;

    uint4 H, L;
    split2(r[0], r[1], H.x, L.x);
    split2(r[2], r[3], H.y, L.y);
    split2(r[4], r[5], H.z, L.z);
    split2(r[6], r[7], H.w, L.w);
    const size_t ofs = (size_t)row * 512 + lane * 8;
    *(uint4*)(osplit + ofs)       = H;
    *(uint4*)(osplit + ofs + 256) = L;
}

// ---------------------------------------------------------------------------
// Weight prep: B_ext[k_ext][n] with k_ext rows [hi, hi, lo] from w[k][n].
// ---------------------------------------------------------------------------
__global__ __launch_bounds__(256) void wconv_kernel(
    const float* __restrict__ w0, const float* __restrict__ w1,
    const float* __restrict__ w2, const float* __restrict__ w3,
    const float* __restrict__ w4,
    __nv_bfloat16* __restrict__ Bqkvg, __nv_bfloat16* __restrict__ Bo)
{
    const float* ws[5] = {w0, w1, w2, w3, w4};
    const int k   = blockIdx.x;        // 0..767
    const int wi  = blockIdx.y;        // 0..4
    const int n   = threadIdx.x;       // 0..255
    const int ks  = k & 255;
    const int seg = k >> 8;            // 0,1 -> hi ; 2 -> lo
    float x = ws[wi][ks * 256 + n];
    __nv_bfloat16 h = __float2bfloat16_rn(x);
    __nv_bfloat16 v = (seg < 2) ? h : __float2bfloat16_rn(x - __bfloat162float(h));
    if (wi < 4) Bqkvg[(size_t)k * 1024 + wi * 256 + n] = v;
    else        Bo[(size_t)k * 256 + n] = v;
}

// ---------------------------------------------------------------------------
// bf16 GEMM via mma.sync: C[M=65536, Nb] = A_ext[M,768] @ B_ext[768,Nb]
// qkv_mode=1: bufs 0..2 scatter split-bf16 into attention-tile layout,
//             buf 3 writes f32 (+bias). qkv_mode=0: buf 0 f32 (+bias).
// ---------------------------------------------------------------------------
#define STAGE_BYTES 32768
#define NSTAGE 3
#define GEMM_SMEM (NSTAGE * STAGE_BYTES)

__device__ __forceinline__ void ld_chunk(
    uint32_t sbase, const __nv_bfloat16* __restrict__ A,
    const __nv_bfloat16* __restrict__ B, int Nb,
    size_t row0, int n0, int kb, int tid)
{
    const int a_off = (kb < 8 ? kb : kb - 8) * 64;
    #pragma unroll
    for (int t = 0; t < 4; t++) {
        const int i = tid + t * 256;
        const int r = i >> 3, c8 = i & 7;
        cp_async16(sbase + SWZ((uint32_t)(r * 128 + c8 * 16)),
                   A + (row0 + r) * 512 + a_off + c8 * 8);
    }
    const uint32_t bbase = sbase + 16384;
    #pragma unroll
    for (int t = 0; t < 4; t++) {
        const int i = tid + t * 256;
        const int k = i >> 4, u = i & 15;
        const uint32_t sub = (u >= 8) ? 8192u : 0u;
        cp_async16(bbase + sub + SWZ((uint32_t)(k * 128 + (u & 7) * 16)),
                   B + (size_t)(kb * 64 + k) * Nb + n0 + u * 8);
    }
}

__global__ __launch_bounds__(256) void gemm_mma(
    const __nv_bfloat16* __restrict__ A, const __nv_bfloat16* __restrict__ B,
    int Nb, int qkv_mode,
    void* C0, void* C1, void* C2, void* C3,
    const float* bias0, const float* bias3)
{
    extern __shared__ char smem[];
    const uint32_t sb = smem_u32(smem);
    const int tid  = threadIdx.x;
    const int warp = tid >> 5, lane = tid & 31;
    const int wm = (warp >> 2) * 64;
    const int wn = (warp & 3) * 32;
    const size_t row0 = (size_t)blockIdx.y * 128;
    const int n0 = blockIdx.x * 128;

    #pragma unroll
    for (int s = 0; s < 3; s++) {
        ld_chunk(sb + s * STAGE_BYTES, A, B, Nb, row0, n0, s, tid);
        CP_COMMIT();
    }

    float acc[4][4][4];
    #pragma unroll
    for (int i = 0; i < 4; i++)
        #pragma unroll
        for (int j = 0; j < 4; j++)
            #pragma unroll
            for (int x = 0; x < 4; x++) acc[i][j][x] = 0.0f;

    const int lr  = lane & 15;
    const int lh  = lane >> 4;
    const uint32_t bsub = (wn >= 64) ? 8192u : 0u;
    const int wn2 = wn & 63;

    #pragma unroll 1
    for (int kb = 0; kb < 12; kb++) {
        CP_WAIT2();
        __syncthreads();
        const int stg = kb % 3;
        const uint32_t As = sb + stg * STAGE_BYTES;
        const uint32_t Bs = As + 16384 + bsub;

        #pragma unroll
        for (int kk = 0; kk < 4; kk++) {
            uint32_t a[4][4];
            #pragma unroll
            for (int i = 0; i < 4; i++)
                ldsm4(a[i], As + SWZ((uint32_t)((wm + i * 16 + lr) * 128
                                                + (kk * 16 + lh * 8) * 2)));
            uint32_t bfr[2][4];
            #pragma unroll
            for (int j2 = 0; j2 < 2; j2++)
                ldsm4t(bfr[j2], Bs + SWZ((uint32_t)((kk * 16 + lr) * 128
                                                + (wn2 + j2 * 16 + lh * 8) * 2)));
            #pragma unroll
            for (int i = 0; i < 4; i++)
                #pragma unroll
                for (int j = 0; j < 4; j++)
                    mma_bf16(acc[i][j], a[i],
                             bfr[j >> 1][(j & 1) * 2], bfr[j >> 1][(j & 1) * 2 + 1]);
        }
        __syncthreads();
        if (kb + 3 < 12) ld_chunk(sb + stg * STAGE_BYTES, A, B, Nb, row0, n0, kb + 3, tid);
        CP_COMMIT();
    }

    const int buf = (n0 >> 8) & 3;
    const int colbase = (n0 & 255) + wn + (lane & 3) * 2;

    if (qkv_mode && buf < 3) {
        __nv_bfloat16* Cq = (__nv_bfloat16*)((buf == 0) ? C0 : (buf == 1) ? C1 : C2);
        #pragma unroll
        for (int i = 0; i < 4; i++) {
            const int r0 = (int)row0 + wm + i * 16 + (lane >> 2);
            #pragma unroll
            for (int j = 0; j < 4; j++) {
                const int col = colbase + j * 8;
                const int hh = col >> 5, cc = col & 31;
                #pragma unroll
                for (int rr = 0; rr < 2; rr++) {
                    const int r = r0 + rr * 8;
                    const int s = r >> 8, ll = r & 255;
                    const size_t dst = ((size_t)(ll * 8 + hh) * 256 + s) * 64 + cc;
                    uint32_t H, L;
                    split2(acc[i][j][rr * 2], acc[i][j][rr * 2 + 1], H, L);
                    *(uint32_t*)(Cq + dst)      = H;
                    *(uint32_t*)(Cq + dst + 32) = L;
                }
            }
        }
    } else {
        float* C = (float*)((qkv_mode) ? C3 : C0);
        const float* bias = (qkv_mode) ? bias3 : bias0;
        #pragma unroll
        for (int i = 0; i < 4; i++) {
            const size_t r0 = row0 + wm + i * 16 + (lane >> 2);
            #pragma unroll
            for (int j = 0; j < 4; j++) {
                const int col = colbase + j * 8;
                float bx = 0.f, by = 0.f;
                if (bias) { bx = bias[col]; by = bias[col + 1]; }
                float2 v0 = make_float2(acc[i][j][0] + bx, acc[i][j][1] + by);
                float2 v1 = make_float2(acc[i][j][2] + bx, acc[i][j][3] + by);
                *(float2*)(C + r0 * 256 + col)       = v0;
                *(float2*)(C + (r0 + 8) * 256 + col) = v1;
            }
        }
    }
}

// ---------------------------------------------------------------------------
// Tensor-core flash attention per (l,h) tile with split-bf16 compensation.
// No online max: logits are O(+-8) here, raw exp2 is safe in fp32, which
// removes the per-chunk max/rescale serialization entirely.
// Epilogue: normalize, sigmoid gate, scramble-reshape, write split bf16.
//   s' = h*32 + l/8 ; l' = (l%8)*32 + s/8 ; c' = (s%8)*32 + c
// ---------------------------------------------------------------------------
#define ATT_SMEM (3 * 32768)

__global__ __launch_bounds__(256) void attn_mma_kernel(
    const __nv_bfloat16* __restrict__ Qg, const __nv_bfloat16* __restrict__ Kg,
    const __nv_bfloat16* __restrict__ Vg, const float* __restrict__ Gg,
    __nv_bfloat16* __restrict__ Osplit)
{
    extern __shared__ char smem[];
    const uint32_t sb = smem_u32(smem);
    const uint32_t QS = sb, KS = sb + 32768, VS = sb + 65536;

    const int tile = blockIdx.x;
    const int l = tile >> 3, h = tile & 7;
    const int tid = threadIdx.x;
    const size_t gbase0 = (size_t)tile * 256 * 64;

    // Load Q, K, V tiles (32KB each) via cp.async
    #pragma unroll
    for (int t = 0; t < 8; t++) {
        const int idx = t * 256 + tid;
        const int r = idx >> 3, j = idx & 7;
        const uint32_t so = SWZ((uint32_t)(r * 128 + j * 16));
        const size_t go = gbase0 + (size_t)r * 64 + j * 8;
        cp_async16(QS + so, Qg + go);
        cp_async16(KS + so, Kg + go);
        cp_async16(VS + so, Vg + go);
    }
    CP_COMMIT();
    CP_WAIT0();
    __syncthreads();

    const int warp = tid >> 5, lane = tid & 31;
    const int s0 = warp * 32;
    const int lr = lane & 15, lh = lane >> 4;

    // Q fragments (kept in regs, reused across all t-chunks)
    uint32_t qh[2][2][4], ql[2][2][4];
    #pragma unroll
    for (int m = 0; m < 2; m++)
        #pragma unroll
        for (int kk = 0; kk < 2; kk++) {
            const uint32_t rowb = (uint32_t)(s0 + m * 16 + lr) * 128;
            ldsm4(qh[m][kk], QS + SWZ(rowb + (kk * 16 + lh * 8) * 2));
            ldsm4(ql[m][kk], QS + SWZ(rowb + (32 + kk * 16 + lh * 8) * 2));
        }

    float o[2][4][4];
    #pragma unroll
    for (int m = 0; m < 2; m++)
        #pragma unroll
        for (int j = 0; j < 4; j++)
            #pragma unroll
            for (int x = 0; x < 4; x++) o[m][j][x] = 0.0f;
    float sm[2][2] = {{0.f, 0.f}, {0.f, 0.f}};
    const float S2 = 0.17677669529663689f * 1.44269504088896f;  // scale*log2e

    #pragma unroll 1
    for (int chunk = 0; chunk < 4; chunk++) {
        const int t0 = chunk * 64;
        float s_acc[2][8][4];
        #pragma unroll
        for (int m = 0; m < 2; m++)
            #pragma unroll
            for (int j = 0; j < 8; j++)
                #pragma unroll
                for (int x = 0; x < 4; x++) s_acc[m][j][x] = 0.0f;

        // ---- S = Q K^T (3 split terms) ----
        #pragma unroll
        for (int g = 0; g < 4; g++) {
            const uint32_t krow = (uint32_t)(t0 + g * 16 + (lane & 7)
                                             + ((lane >> 4) << 3)) * 128;
            const uint32_t colb = ((uint32_t)((lane >> 3) & 1)) * 16;
            uint32_t kh[2][4], kl[2][4];
            #pragma unroll
            for (int ch = 0; ch < 2; ch++) {
                ldsm4(kh[ch], KS + SWZ(krow + (ch * 32 + colb)));
                ldsm4(kl[ch], KS + SWZ(krow + (64 + ch * 32 + colb)));
            }
            #pragma unroll
            for (int m = 0; m < 2; m++)
                #pragma unroll
                for (int ch = 0; ch < 2; ch++) {
                    mma_bf16(s_acc[m][2 * g],     qh[m][ch], kh[ch][0], kh[ch][1]);
                    mma_bf16(s_acc[m][2 * g + 1], qh[m][ch], kh[ch][2], kh[ch][3]);
                    mma_bf16(s_acc[m][2 * g],     ql[m][ch], kh[ch][0], kh[ch][1]);
                    mma_bf16(s_acc[m][2 * g + 1], ql[m][ch], kh[ch][2], kh[ch][3]);
                    mma_bf16(s_acc[m][2 * g],     qh[m][ch], kl[ch][0], kl[ch][1]);
                    mma_bf16(s_acc[m][2 * g + 1], qh[m][ch], kl[ch][2], kl[ch][3]);
                }
        }

        // ---- exp (no max subtraction) + sum accumulation ----
        #pragma unroll
        for (int m = 0; m < 2; m++) {
            float ps0 = 0.f, ps1 = 0.f;
            #pragma unroll
            for (int j = 0; j < 8; j++) {
                const float p0 = exp2f(s_acc[m][j][0] * S2);
                const float p1 = exp2f(s_acc[m][j][1] * S2);
                const float p2 = exp2f(s_acc[m][j][2] * S2);
                const float p3 = exp2f(s_acc[m][j][3] * S2);
                s_acc[m][j][0] = p0; s_acc[m][j][1] = p1;
                s_acc[m][j][2] = p2; s_acc[m][j][3] = p3;
                ps0 += p0 + p1;
                ps1 += p2 + p3;
            }
            sm[m][0] += ps0;
            sm[m][1] += ps1;
        }

        // ---- O += P V (3 split terms) ----
        #pragma unroll
        for (int g = 0; g < 4; g++) {
            const uint32_t vrow = (uint32_t)(t0 + g * 16 + lr) * 128;
            uint32_t vh[2][4], vl[2][4];
            #pragma unroll
            for (int j2 = 0; j2 < 2; j2++) {
                ldsm4t(vh[j2], VS + SWZ(vrow + (j2 * 16 + lh * 8) * 2));
                ldsm4t(vl[j2], VS + SWZ(vrow + (32 + j2 * 16 + lh * 8) * 2));
            }
            #pragma unroll
            for (int m = 0; m < 2; m++) {
                uint32_t ah[4], al[4];
                split2(s_acc[m][2 * g][0],     s_acc[m][2 * g][1],     ah[0], al[0]);
                split2(s_acc[m][2 * g][2],     s_acc[m][2 * g][3],     ah[1], al[1]);
                split2(s_acc[m][2 * g + 1][0], s_acc[m][2 * g + 1][1], ah[2], al[2]);
                split2(s_acc[m][2 * g + 1][2], s_acc[m][2 * g + 1][3], ah[3], al[3]);
                #pragma unroll
                for (int j = 0; j < 4; j++) {
                    const int j2 = j >> 1, jj = (j & 1) * 2;
                    mma_bf16(o[m][j], ah, vh[j2][jj], vh[j2][jj + 1]);
                    mma_bf16(o[m][j], al, vh[j2][jj], vh[j2][jj + 1]);
                    mma_bf16(o[m][j], ah, vl[j2][jj], vl[j2][jj + 1]);
                }
            }
        }
    }

    // ---- epilogue: normalize, gate, scramble, store split bf16 ----
    const int i_o = h * 32 + (l >> 3);
    #pragma unroll
    for (int m = 0; m < 2; m++)
        #pragma unroll
        for (int rr = 0; rr < 2; rr++) {
            float v = sm[m][rr];
            v += __shfl_xor_sync(0xffffffffu, v, 1);
            v += __shfl_xor_sync(0xffffffffu, v, 2);
            const float inv = 1.0f / v;
            const int s = s0 + m * 16 + (lane >> 2) + rr * 8;
            const int j_o = ((l & 7) << 5) + (s >> 3);
            const int k_o = (s & 7) << 5;
            const size_t gb = ((size_t)i_o * 256 + j_o) * 256 + k_o;
            const size_t ob = ((size_t)i_o * 256 + j_o) * 512 + k_o;
            #pragma unroll
            for (int j = 0; j < 4; j++) {
                const int c = j * 8 + (lane & 3) * 2;
                const float2 gg = *(const float2*)(Gg + gb + c);
                const float w0 = o[m][j][rr * 2] * inv
                                 / (1.0f + exp2f(-gg.x * 1.44269504088896f));
                const float w1 = o[m][j][rr * 2 + 1] * inv
                                 / (1.0f + exp2f(-gg.y * 1.44269504088896f));
                uint32_t H, L;
                split2(w0, w1, H, L);
                *(uint32_t*)(Osplit + ob + c)       = H;
                *(uint32_t*)(Osplit + ob + 256 + c) = L;
            }
        }
}

// ---------------------------------------------------------------------------
extern "C" void kernel_launch(void* const* d_in, const int* in_sizes, int n_in,
                              void* d_out, int out_size)
{
    const float* m    = (const float*)d_in[0];
    const float* ln_w = (const float*)d_in[1];
    const float* ln_b = (const float*)d_in[2];
    const float* wq   = (const float*)d_in[3];
    const float* wk   = (const float*)d_in[4];
    const float* wv   = (const float*)d_in[5];
    const float* wg   = (const float*)d_in[6];
    const float* bg   = (const float*)d_in[7];
    const float* wo   = (const float*)d_in[8];
    const float* bo   = (const float*)d_in[9];
    float* out = (float*)d_out;

    __nv_bfloat16 *mns, *ats, *Bq, *Bo, *qs, *ks, *vs;
    float *g;
    cudaGetSymbolAddress((void**)&mns, g_mn_split);
    cudaGetSymbolAddress((void**)&ats, g_att_split);
    cudaGetSymbolAddress((void**)&qs,  g_qs);
    cudaGetSymbolAddress((void**)&ks,  g_ks);
    cudaGetSymbolAddress((void**)&vs,  g_vs);
    cudaGetSymbolAddress((void**)&g,   g_g);
    cudaGetSymbolAddress((void**)&Bq,  g_Bqkvg);
    cudaGetSymbolAddress((void**)&Bo,  g_Bo);

    cudaFuncSetAttribute(gemm_mma,
                         cudaFuncAttributeMaxDynamicSharedMemorySize, GEMM_SMEM);
    cudaFuncSetAttribute(attn_mma_kernel,
                         cudaFuncAttributeMaxDynamicSharedMemorySize, ATT_SMEM);

    // 1. LayerNorm -> split bf16
    ln_kernel<<<NROWS / 8, 256>>>(m, ln_w, ln_b, mns);

    // 2. Weight prep
    wconv_kernel<<<dim3(768, 5), 256>>>(wq, wk, wv, wg, wo, Bq, Bo);

    // 3. Fused Q/K/V/G projection: [65536,768] @ [768,1024]
    gemm_mma<<<dim3(8, NROWS / 128), 256, GEMM_SMEM>>>(
        mns, Bq, 1024, 1, qs, ks, vs, g, nullptr, bg);

    // 4. Tensor-core flash attention + gate + scramble -> split bf16
    attn_mma_kernel<<<L_DIM * NH, 256, ATT_SMEM>>>(qs, ks, vs, g, ats);

    // 5. Output projection: [65536,768] @ [768,256] -> d_out (+bo)
    gemm_mma<<<dim3(2, NROWS / 128), 256, GEMM_SMEM>>>(
        ats, Bo, 256, 0, out, nullptr, nullptr, nullptr, bo, nullptr);
}

// round 7
// speedup vs baseline: 2.7601x; 1.0490x over previous
#include <cuda_runtime.h>
#include <cuda_bf16.h>
#include <cstdint>
#include <math.h>

// Problem constants: B=1, n_seq=S=256, seq_len=L=256, c_m=256, H=8, ch=32, HC=256
#define S_DIM 256
#define L_DIM 256
#define C_DIM 256
#define HC_DIM 256
#define NH 8
#define CH 32
#define NROWS (S_DIM * L_DIM)  // 65536

// ---------------------------------------------------------------------------
// Scratch (device globals per allocation rules)
// ---------------------------------------------------------------------------
__device__ __align__(16) __nv_bfloat16 g_mn_split[NROWS * 512];
__device__ __align__(16) __nv_bfloat16 g_att_split[NROWS * 512];
// Q/K/V attention-tile layout: [(l*8+h)][s][64] rows = [hi32|lo32] bf16
__device__ __align__(16) __nv_bfloat16 g_qs[NROWS * 512];
__device__ __align__(16) __nv_bfloat16 g_ks[NROWS * 512];
__device__ __align__(16) __nv_bfloat16 g_vs[NROWS * 512];
__device__ __align__(16) float g_g[NROWS * HC_DIM];
__device__ __align__(16) __nv_bfloat16 g_Bqkvg[768 * 1024];  // cols: q|k|v|g
__device__ __align__(16) __nv_bfloat16 g_Bo[768 * 256];

// ---------------------------------------------------------------------------
// Helpers
// ---------------------------------------------------------------------------
__device__ __forceinline__ uint32_t smem_u32(const void* p) {
    uint32_t a;
    asm("{ .reg .u64 t; cvta.to.shared.u64 t, %1; cvt.u32.u64 %0, t; }"
        : "=r"(a) : "l"(p));
    return a;
}

#define SWZ(o) ((o) ^ (((o) >> 3) & 0x70))

__device__ __forceinline__ void cp_async16(uint32_t saddr, const void* gptr) {
    asm volatile("cp.async.cg.shared.global [%0], [%1], 16;"
                 :: "r"(saddr), "l"(__cvta_generic_to_global(gptr)) : "memory");
}
#define CP_COMMIT() asm volatile("cp.async.commit_group;" ::: "memory")
#define CP_WAIT2()  asm volatile("cp.async.wait_group 2;" ::: "memory")
#define CP_WAIT0()  asm volatile("cp.async.wait_group 0;" ::: "memory")

__device__ __forceinline__ void ldsm4(uint32_t* r, uint32_t addr) {
    asm volatile("ldmatrix.sync.aligned.m8n8.x4.shared.b16 {%0,%1,%2,%3}, [%4];"
                 : "=r"(r[0]), "=r"(r[1]), "=r"(r[2]), "=r"(r[3]) : "r"(addr));
}
__device__ __forceinline__ void ldsm4t(uint32_t* r, uint32_t addr) {
    asm volatile("ldmatrix.sync.aligned.m8n8.x4.trans.shared.b16 {%0,%1,%2,%3}, [%4];"
                 : "=r"(r[0]), "=r"(r[1]), "=r"(r[2]), "=r"(r[3]) : "r"(addr));
}
__device__ __forceinline__ void mma_bf16(float* c, const uint32_t* a,
                                         uint32_t b0, uint32_t b1) {
    asm volatile(
        "mma.sync.aligned.m16n8k16.row.col.f32.bf16.bf16.f32 "
        "{%0,%1,%2,%3}, {%4,%5,%6,%7}, {%8,%9}, {%0,%1,%2,%3};"
        : "+f"(c[0]), "+f"(c[1]), "+f"(c[2]), "+f"(c[3])
        : "r"(a[0]), "r"(a[1]), "r"(a[2]), "r"(a[3]), "r"(b0), "r"(b1));
}

// fp32 -> bf16 hi/lo split (packed pairs), bit-trick hi reconstruction.
__device__ __forceinline__ void split2(float a, float b, uint32_t& h, uint32_t& l) {
    uint32_t hb;
    asm("cvt.rn.bf16x2.f32 %0, %1, %2;" : "=r"(hb) : "f"(b), "f"(a));
    const float fa = __uint_as_float(hb << 16);
    const float fb = __uint_as_float(hb & 0xffff0000u);
    const float la = a - fa;
    const float lb = b - fb;
    uint32_t lo;
    asm("cvt.rn.bf16x2.f32 %0, %1, %2;" : "=r"(lo) : "f"(lb), "f"(la));
    h = hb;
    l = lo;
}

// ---------------------------------------------------------------------------
// LayerNorm -> split bf16 [row][512]. One warp per row.
// ---------------------------------------------------------------------------
__global__ __launch_bounds__(256) void ln_kernel(
    const float* __restrict__ m, const float* __restrict__ w,
    const float* __restrict__ b, __nv_bfloat16* __restrict__ osplit)
{
    const int warp = threadIdx.x >> 5;
    const int lane = threadIdx.x & 31;
    const int row  = blockIdx.x * 8 + warp;

    const float4* x4 = (const float4*)(m + (size_t)row * C_DIM);
    float4 v0 = x4[lane * 2 + 0];
    float4 v1 = x4[lane * 2 + 1];

    float s1 = (v0.x + v0.y) + (v0.z + v0.w) + (v1.x + v1.y) + (v1.z + v1.w);
    float s2 = v0.x * v0.x + v0.y * v0.y + v0.z * v0.z + v0.w * v0.w
             + v1.x * v1.x + v1.y * v1.y + v1.z * v1.z + v1.w * v1.w;
    #pragma unroll
    for (int o = 16; o > 0; o >>= 1) {
        s1 += __shfl_xor_sync(0xffffffffu, s1, o);
        s2 += __shfl_xor_sync(0xffffffffu, s2, o);
    }
    const float mu  = s1 * (1.0f / 256.0f);
    const float var = s2 * (1.0f / 256.0f) - mu * mu;
    const float rs  = rsqrtf(var + 1e-5f);

    const float4* w4 = (const float4*)w;
    const float4* b4 = (const float4*)b;
    float4 w0 = w4[lane * 2 + 0], w1 = w4[lane * 2 + 1];
    float4 b0 = b4[lane * 2 + 0], b1 = b4[lane * 2 + 1];

    float r[8];
    r[0] = (v0.x - mu) * rs * w0.x + b0.x;
    r[1] = (v0.y - mu) * rs * w0.y + b0.y;
    r[2] = (v0.z - mu) * rs * w0.z + b0.z;
    r[3] = (v0.w - mu) * rs * w0.w + b0.w;
    r[4] = (v1.x - mu) * rs * w1.x + b1.x;
    r[5] = (v1.y - mu) * rs * w1.y + b1.y;
    r[6] = (v1.z - mu) * rs * w1.z + b1.z;
    r[7] = (v1.w - mu) * rs * w1.w + b1.w;

    uint4 H, L;
    split2(r[0], r[1], H.x, L.x);
    split2(r[2], r[3], H.y, L.y);
    split2(r[4], r[5], H.z, L.z);
    split2(r[6], r[7], H.w, L.w);
    const size_t ofs = (size_t)row * 512 + lane * 8;
    *(uint4*)(osplit + ofs)       = H;
    *(uint4*)(osplit + ofs + 256) = L;
}

// ---------------------------------------------------------------------------
// Weight prep: B_ext[k_ext][n] with k_ext rows [hi, hi, lo] from w[k][n].
// ---------------------------------------------------------------------------
__global__ __launch_bounds__(256) void wconv_kernel(
    const float* __restrict__ w0, const float* __restrict__ w1,
    const float* __restrict__ w2, const float* __restrict__ w3,
    const float* __restrict__ w4,
    __nv_bfloat16* __restrict__ Bqkvg, __nv_bfloat16* __restrict__ Bo)
{
    const float* ws[5] = {w0, w1, w2, w3, w4};
    const int k   = blockIdx.x;        // 0..767
    const int wi  = blockIdx.y;        // 0..4
    const int n   = threadIdx.x;       // 0..255
    const int ks  = k & 255;
    const int seg = k >> 8;            // 0,1 -> hi ; 2 -> lo
    float x = ws[wi][ks * 256 + n];
    __nv_bfloat16 h = __float2bfloat16_rn(x);
    __nv_bfloat16 v = (seg < 2) ? h : __float2bfloat16_rn(x - __bfloat162float(h));
    if (wi < 4) Bqkvg[(size_t)k * 1024 + wi * 256 + n] = v;
    else        Bo[(size_t)k * 256 + n] = v;
}

// ---------------------------------------------------------------------------
// bf16 GEMM via mma.sync: C[M=65536, Nb] = A_ext[M,768] @ B_ext[768,Nb]
// qkv_mode=1: bufs 0..2 scatter split-bf16 into attention-tile layout
//             (buf 0 = Q gets pre-scaled by scale*log2e), buf 3 f32 (+bias).
// qkv_mode=0: buf 0 f32 (+bias).
// ---------------------------------------------------------------------------
#define STAGE_BYTES 32768
#define NSTAGE 3
#define GEMM_SMEM (NSTAGE * STAGE_BYTES)

__device__ __forceinline__ void ld_chunk(
    uint32_t sbase, const __nv_bfloat16* __restrict__ A,
    const __nv_bfloat16* __restrict__ B, int Nb,
    size_t row0, int n0, int kb, int tid)
{
    const int a_off = (kb < 8 ? kb : kb - 8) * 64;
    #pragma unroll
    for (int t = 0; t < 4; t++) {
        const int i = tid + t * 256;
        const int r = i >> 3, c8 = i & 7;
        cp_async16(sbase + SWZ((uint32_t)(r * 128 + c8 * 16)),
                   A + (row0 + r) * 512 + a_off + c8 * 8);
    }
    const uint32_t bbase = sbase + 16384;
    #pragma unroll
    for (int t = 0; t < 4; t++) {
        const int i = tid + t * 256;
        const int k = i >> 4, u = i & 15;
        const uint32_t sub = (u >= 8) ? 8192u : 0u;
        cp_async16(bbase + sub + SWZ((uint32_t)(k * 128 + (u & 7) * 16)),
                   B + (size_t)(kb * 64 + k) * Nb + n0 + u * 8);
    }
}

__global__ __launch_bounds__(256) void gemm_mma(
    const __nv_bfloat16* __restrict__ A, const __nv_bfloat16* __restrict__ B,
    int Nb, int qkv_mode,
    void* C0, void* C1, void* C2, void* C3,
    const float* bias0, const float* bias3)
{
    extern __shared__ char smem[];
    const uint32_t sb = smem_u32(smem);
    const int tid  = threadIdx.x;
    const int warp = tid >> 5, lane = tid & 31;
    const int wm = (warp >> 2) * 64;
    const int wn = (warp & 3) * 32;
    const size_t row0 = (size_t)blockIdx.y * 128;
    const int n0 = blockIdx.x * 128;

    #pragma unroll
    for (int s = 0; s < 3; s++) {
        ld_chunk(sb + s * STAGE_BYTES, A, B, Nb, row0, n0, s, tid);
        CP_COMMIT();
    }

    float acc[4][4][4];
    #pragma unroll
    for (int i = 0; i < 4; i++)
        #pragma unroll
        for (int j = 0; j < 4; j++)
            #pragma unroll
            for (int x = 0; x < 4; x++) acc[i][j][x] = 0.0f;

    const int lr  = lane & 15;
    const int lh  = lane >> 4;
    const uint32_t bsub = (wn >= 64) ? 8192u : 0u;
    const int wn2 = wn & 63;

    #pragma unroll 1
    for (int kb = 0; kb < 12; kb++) {
        CP_WAIT2();
        __syncthreads();
        const int stg = kb % 3;
        const uint32_t As = sb + stg * STAGE_BYTES;
        const uint32_t Bs = As + 16384 + bsub;

        #pragma unroll
        for (int kk = 0; kk < 4; kk++) {
            uint32_t a[4][4];
            #pragma unroll
            for (int i = 0; i < 4; i++)
                ldsm4(a[i], As + SWZ((uint32_t)((wm + i * 16 + lr) * 128
                                                + (kk * 16 + lh * 8) * 2)));
            uint32_t bfr[2][4];
            #pragma unroll
            for (int j2 = 0; j2 < 2; j2++)
                ldsm4t(bfr[j2], Bs + SWZ((uint32_t)((kk * 16 + lr) * 128
                                                + (wn2 + j2 * 16 + lh * 8) * 2)));
            #pragma unroll
            for (int i = 0; i < 4; i++)
                #pragma unroll
                for (int j = 0; j < 4; j++)
                    mma_bf16(acc[i][j], a[i],
                             bfr[j >> 1][(j & 1) * 2], bfr[j >> 1][(j & 1) * 2 + 1]);
        }
        __syncthreads();
        if (kb + 3 < 12) ld_chunk(sb + stg * STAGE_BYTES, A, B, Nb, row0, n0, kb + 3, tid);
        CP_COMMIT();
    }

    const int buf = (n0 >> 8) & 3;
    const int colbase = (n0 & 255) + wn + (lane & 3) * 2;

    if (qkv_mode && buf < 3) {
        __nv_bfloat16* Cq = (__nv_bfloat16*)((buf == 0) ? C0 : (buf == 1) ? C1 : C2);
        // Pre-fold softmax scale (and log2e) into Q
        const float qsc = (buf == 0) ? 0.17677669529663689f * 1.44269504088896f
                                     : 1.0f;
        #pragma unroll
        for (int i = 0; i < 4; i++) {
            const int r0 = (int)row0 + wm + i * 16 + (lane >> 2);
            #pragma unroll
            for (int j = 0; j < 4; j++) {
                const int col = colbase + j * 8;
                const int hh = col >> 5, cc = col & 31;
                #pragma unroll
                for (int rr = 0; rr < 2; rr++) {
                    const int r = r0 + rr * 8;
                    const int s = r >> 8, ll = r & 255;
                    const size_t dst = ((size_t)(ll * 8 + hh) * 256 + s) * 64 + cc;
                    uint32_t H, L;
                    split2(acc[i][j][rr * 2] * qsc, acc[i][j][rr * 2 + 1] * qsc,
                           H, L);
                    *(uint32_t*)(Cq + dst)      = H;
                    *(uint32_t*)(Cq + dst + 32) = L;
                }
            }
        }
    } else {
        float* C = (float*)((qkv_mode) ? C3 : C0);
        const float* bias = (qkv_mode) ? bias3 : bias0;
        #pragma unroll
        for (int i = 0; i < 4; i++) {
            const size_t r0 = row0 + wm + i * 16 + (lane >> 2);
            #pragma unroll
            for (int j = 0; j < 4; j++) {
                const int col = colbase + j * 8;
                float bx = 0.f, by = 0.f;
                if (bias) { bx = bias[col]; by = bias[col + 1]; }
                float2 v0 = make_float2(acc[i][j][0] + bx, acc[i][j][1] + by);
                float2 v1 = make_float2(acc[i][j][2] + bx, acc[i][j][3] + by);
                *(float2*)(C + r0 * 256 + col)       = v0;
                *(float2*)(C + (r0 + 8) * 256 + col) = v1;
            }
        }
    }
}

// ---------------------------------------------------------------------------
// Tensor-core flash attention per (l,h) tile, 512 threads / 16 warps
// (16 q-rows per warp) for 4 warps/SMSP latency hiding. Split-bf16
// compensation; no online max (logits bounded, Q pre-scaled by scale*log2e).
// Epilogue: normalize, sigmoid gate, scramble-reshape, write split bf16.
//   s' = h*32 + l/8 ; l' = (l%8)*32 + s/8 ; c' = (s%8)*32 + c
// ---------------------------------------------------------------------------
#define ATT_SMEM (3 * 32768)

__global__ __launch_bounds__(512) void attn_mma_kernel(
    const __nv_bfloat16* __restrict__ Qg, const __nv_bfloat16* __restrict__ Kg,
    const __nv_bfloat16* __restrict__ Vg, const float* __restrict__ Gg,
    __nv_bfloat16* __restrict__ Osplit)
{
    extern __shared__ char smem[];
    const uint32_t sb = smem_u32(smem);
    const uint32_t QS = sb, KS = sb + 32768, VS = sb + 65536;

    const int tile = blockIdx.x;
    const int l = tile >> 3, h = tile & 7;
    const int tid = threadIdx.x;
    const size_t gbase0 = (size_t)tile * 256 * 64;

    // Load Q, K, V tiles (32KB each) via cp.async
    #pragma unroll
    for (int t = 0; t < 4; t++) {
        const int idx = t * 512 + tid;
        const int r = idx >> 3, j = idx & 7;
        const uint32_t so = SWZ((uint32_t)(r * 128 + j * 16));
        const size_t go = gbase0 + (size_t)r * 64 + j * 8;
        cp_async16(QS + so, Qg + go);
        cp_async16(KS + so, Kg + go);
        cp_async16(VS + so, Vg + go);
    }
    CP_COMMIT();
    CP_WAIT0();
    __syncthreads();

    const int warp = tid >> 5, lane = tid & 31;
    const int s0 = warp * 16;
    const int lr = lane & 15, lh = lane >> 4;

    // Q fragments (16 rows per warp, hi+lo)
    uint32_t qh[2][4], ql[2][4];
    #pragma unroll
    for (int kk = 0; kk < 2; kk++) {
        const uint32_t rowb = (uint32_t)(s0 + lr) * 128;
        ldsm4(qh[kk], QS + SWZ(rowb + (kk * 16 + lh * 8) * 2));
        ldsm4(ql[kk], QS + SWZ(rowb + (32 + kk * 16 + lh * 8) * 2));
    }

    float o[4][4];
    #pragma unroll
    for (int j = 0; j < 4; j++)
        #pragma unroll
        for (int x = 0; x < 4; x++) o[j][x] = 0.0f;
    float sm[2] = {0.f, 0.f};

    #pragma unroll 1
    for (int chunk = 0; chunk < 4; chunk++) {
        const int t0 = chunk * 64;
        float s_acc[8][4];
        #pragma unroll
        for (int j = 0; j < 8; j++)
            #pragma unroll
            for (int x = 0; x < 4; x++) s_acc[j][x] = 0.0f;

        // ---- S = Q K^T (3 split terms; Q pre-scaled) ----
        #pragma unroll
        for (int g = 0; g < 4; g++) {
            const uint32_t krow = (uint32_t)(t0 + g * 16 + (lane & 7)
                                             + ((lane >> 4) << 3)) * 128;
            const uint32_t colb = ((uint32_t)((lane >> 3) & 1)) * 16;
            uint32_t kh[2][4], kl[2][4];
            #pragma unroll
            for (int ch = 0; ch < 2; ch++) {
                ldsm4(kh[ch], KS + SWZ(krow + (ch * 32 + colb)));
                ldsm4(kl[ch], KS + SWZ(krow + (64 + ch * 32 + colb)));
            }
            #pragma unroll
            for (int ch = 0; ch < 2; ch++) {
                mma_bf16(s_acc[2 * g],     qh[ch], kh[ch][0], kh[ch][1]);
                mma_bf16(s_acc[2 * g + 1], qh[ch], kh[ch][2], kh[ch][3]);
                mma_bf16(s_acc[2 * g],     ql[ch], kh[ch][0], kh[ch][1]);
                mma_bf16(s_acc[2 * g + 1], ql[ch], kh[ch][2], kh[ch][3]);
                mma_bf16(s_acc[2 * g],     qh[ch], kl[ch][0], kl[ch][1]);
                mma_bf16(s_acc[2 * g + 1], qh[ch], kl[ch][2], kl[ch][3]);
            }
        }

        // ---- exp2 (logits already in log2 units) + sum ----
        {
            float ps0 = 0.f, ps1 = 0.f;
            #pragma unroll
            for (int j = 0; j < 8; j++) {
                const float p0 = exp2f(s_acc[j][0]);
                const float p1 = exp2f(s_acc[j][1]);
                const float p2 = exp2f(s_acc[j][2]);
                const float p3 = exp2f(s_acc[j][3]);
                s_acc[j][0] = p0; s_acc[j][1] = p1;
                s_acc[j][2] = p2; s_acc[j][3] = p3;
                ps0 += p0 + p1;
                ps1 += p2 + p3;
            }
            sm[0] += ps0;
            sm[1] += ps1;
        }

        // ---- O += P V (3 split terms) ----
        #pragma unroll
        for (int g = 0; g < 4; g++) {
            const uint32_t vrow = (uint32_t)(t0 + g * 16 + lr) * 128;
            uint32_t vh[2][4], vl[2][4];
            #pragma unroll
            for (int j2 = 0; j2 < 2; j2++) {
                ldsm4t(vh[j2], VS + SWZ(vrow + (j2 * 16 + lh * 8) * 2));
                ldsm4t(vl[j2], VS + SWZ(vrow + (32 + j2 * 16 + lh * 8) * 2));
            }
            uint32_t ah[4], al[4];
            split2(s_acc[2 * g][0],     s_acc[2 * g][1],     ah[0], al[0]);
            split2(s_acc[2 * g][2],     s_acc[2 * g][3],     ah[1], al[1]);
            split2(s_acc[2 * g + 1][0], s_acc[2 * g + 1][1], ah[2], al[2]);
            split2(s_acc[2 * g + 1][2], s_acc[2 * g + 1][3], ah[3], al[3]);
            #pragma unroll
            for (int j = 0; j < 4; j++) {
                const int j2 = j >> 1, jj = (j & 1) * 2;
                mma_bf16(o[j], ah, vh[j2][jj], vh[j2][jj + 1]);
                mma_bf16(o[j], al, vh[j2][jj], vh[j2][jj + 1]);
                mma_bf16(o[j], ah, vl[j2][jj], vl[j2][jj + 1]);
            }
        }
    }

    // ---- epilogue: normalize, gate, scramble, store split bf16 ----
    const int i_o = h * 32 + (l >> 3);
    #pragma unroll
    for (int rr = 0; rr < 2; rr++) {
        float v = sm[rr];
        v += __shfl_xor_sync(0xffffffffu, v, 1);
        v += __shfl_xor_sync(0xffffffffu, v, 2);
        const float inv = 1.0f / v;
        const int s = s0 + (lane >> 2) + rr * 8;
        const int j_o = ((l & 7) << 5) + (s >> 3);
        const int k_o = (s & 7) << 5;
        const size_t gb = ((size_t)i_o * 256 + j_o) * 256 + k_o;
        const size_t ob = ((size_t)i_o * 256 + j_o) * 512 + k_o;
        #pragma unroll
        for (int j = 0; j < 4; j++) {
            const int c = j * 8 + (lane & 3) * 2;
            const float2 gg = *(const float2*)(Gg + gb + c);
            const float w0 = o[j][rr * 2] * inv
                             / (1.0f + exp2f(-gg.x * 1.44269504088896f));
            const float w1 = o[j][rr * 2 + 1] * inv
                             / (1.0f + exp2f(-gg.y * 1.44269504088896f));
            uint32_t H, L;
            split2(w0, w1, H, L);
            *(uint32_t*)(Osplit + ob + c)       = H;
            *(uint32_t*)(Osplit + ob + 256 + c) = L;
        }
    }
}

// ---------------------------------------------------------------------------
extern "C" void kernel_launch(void* const* d_in, const int* in_sizes, int n_in,
                              void* d_out, int out_size)
{
    const float* m    = (const float*)d_in[0];
    const float* ln_w = (const float*)d_in[1];
    const float* ln_b = (const float*)d_in[2];
    const float* wq   = (const float*)d_in[3];
    const float* wk   = (const float*)d_in[4];
    const float* wv   = (const float*)d_in[5];
    const float* wg   = (const float*)d_in[6];
    const float* bg   = (const float*)d_in[7];
    const float* wo   = (const float*)d_in[8];
    const float* bo   = (const float*)d_in[9];
    float* out = (float*)d_out;

    __nv_bfloat16 *mns, *ats, *Bq, *Bo, *qs, *ks, *vs;
    float *g;
    cudaGetSymbolAddress((void**)&mns, g_mn_split);
    cudaGetSymbolAddress((void**)&ats, g_att_split);
    cudaGetSymbolAddress((void**)&qs,  g_qs);
    cudaGetSymbolAddress((void**)&ks,  g_ks);
    cudaGetSymbolAddress((void**)&vs,  g_vs);
    cudaGetSymbolAddress((void**)&g,   g_g);
    cudaGetSymbolAddress((void**)&Bq,  g_Bqkvg);
    cudaGetSymbolAddress((void**)&Bo,  g_Bo);

    cudaFuncSetAttribute(gemm_mma,
                         cudaFuncAttributeMaxDynamicSharedMemorySize, GEMM_SMEM);
    cudaFuncSetAttribute(attn_mma_kernel,
                         cudaFuncAttributeMaxDynamicSharedMemorySize, ATT_SMEM);

    // 1. LayerNorm -> split bf16
    ln_kernel<<<NROWS / 8, 256>>>(m, ln_w, ln_b, mns);

    // 2. Weight prep
    wconv_kernel<<<dim3(768, 5), 256>>>(wq, wk, wv, wg, wo, Bq, Bo);

    // 3. Fused Q/K/V/G projection: [65536,768] @ [768,1024]
    gemm_mma<<<dim3(8, NROWS / 128), 256, GEMM_SMEM>>>(
        mns, Bq, 1024, 1, qs, ks, vs, g, nullptr, bg);

    // 4. Tensor-core flash attention (512 thr) + gate + scramble
    attn_mma_kernel<<<L_DIM * NH, 512, ATT_SMEM>>>(qs, ks, vs, g, ats);

    // 5. Output projection: [65536,768] @ [768,256] -> d_out (+bo)
    gemm_mma<<<dim3(2, NROWS / 128), 256, GEMM_SMEM>>>(
        ats, Bo, 256, 0, out, nullptr, nullptr, nullptr, bo, nullptr);
}

// round 8
// speedup vs baseline: 2.8784x; 1.0429x over previous
#include <cuda_runtime.h>
#include <cuda_bf16.h>
#include <cstdint>
#include <math.h>

// Problem constants: B=1, n_seq=S=256, seq_len=L=256, c_m=256, H=8, ch=32, HC=256
#define S_DIM 256
#define L_DIM 256
#define C_DIM 256
#define HC_DIM 256
#define NH 8
#define CH 32
#define NROWS (S_DIM * L_DIM)  // 65536

// ---------------------------------------------------------------------------
// Scratch (device globals per allocation rules)
// ---------------------------------------------------------------------------
__device__ __align__(16) __nv_bfloat16 g_mn_split[NROWS * 512];
__device__ __align__(16) __nv_bfloat16 g_att_split[NROWS * 512];
// Q/K/V attention-tile layout: [(l*8+h)][s][64] rows = [hi32|lo32] bf16
__device__ __align__(16) __nv_bfloat16 g_qs[NROWS * 512];
__device__ __align__(16) __nv_bfloat16 g_ks[NROWS * 512];
__device__ __align__(16) __nv_bfloat16 g_vs[NROWS * 512];
__device__ __align__(16) float g_g[NROWS * HC_DIM];
__device__ __align__(16) __nv_bfloat16 g_Bqkvg[768 * 1024];  // cols: q|k|v|g
__device__ __align__(16) __nv_bfloat16 g_Bo[768 * 256];

// ---------------------------------------------------------------------------
// Helpers
// ---------------------------------------------------------------------------
__device__ __forceinline__ uint32_t smem_u32(const void* p) {
    uint32_t a;
    asm("{ .reg .u64 t; cvta.to.shared.u64 t, %1; cvt.u32.u64 %0, t; }"
        : "=r"(a) : "l"(p));
    return a;
}

#define SWZ(o) ((o) ^ (((o) >> 3) & 0x70))

__device__ __forceinline__ void cp_async16(uint32_t saddr, const void* gptr) {
    asm volatile("cp.async.cg.shared.global [%0], [%1], 16;"
                 :: "r"(saddr), "l"(__cvta_generic_to_global(gptr)) : "memory");
}
#define CP_COMMIT() asm volatile("cp.async.commit_group;" ::: "memory")
#define CP_WAIT2()  asm volatile("cp.async.wait_group 2;" ::: "memory")
#define CP_WAIT0()  asm volatile("cp.async.wait_group 0;" ::: "memory")

__device__ __forceinline__ void ldsm4(uint32_t* r, uint32_t addr) {
    asm volatile("ldmatrix.sync.aligned.m8n8.x4.shared.b16 {%0,%1,%2,%3}, [%4];"
                 : "=r"(r[0]), "=r"(r[1]), "=r"(r[2]), "=r"(r[3]) : "r"(addr));
}
__device__ __forceinline__ void ldsm4t(uint32_t* r, uint32_t addr) {
    asm volatile("ldmatrix.sync.aligned.m8n8.x4.trans.shared.b16 {%0,%1,%2,%3}, [%4];"
                 : "=r"(r[0]), "=r"(r[1]), "=r"(r[2]), "=r"(r[3]) : "r"(addr));
}
__device__ __forceinline__ void mma_bf16(float* c, const uint32_t* a,
                                         uint32_t b0, uint32_t b1) {
    asm volatile(
        "mma.sync.aligned.m16n8k16.row.col.f32.bf16.bf16.f32 "
        "{%0,%1,%2,%3}, {%4,%5,%6,%7}, {%8,%9}, {%0,%1,%2,%3};"
        : "+f"(c[0]), "+f"(c[1]), "+f"(c[2]), "+f"(c[3])
        : "r"(a[0]), "r"(a[1]), "r"(a[2]), "r"(a[3]), "r"(b0), "r"(b1));
}

// fp32 -> bf16 hi/lo split (packed pairs), bit-trick hi reconstruction.
__device__ __forceinline__ void split2(float a, float b, uint32_t& h, uint32_t& l) {
    uint32_t hb;
    asm("cvt.rn.bf16x2.f32 %0, %1, %2;" : "=r"(hb) : "f"(b), "f"(a));
    const float fa = __uint_as_float(hb << 16);
    const float fb = __uint_as_float(hb & 0xffff0000u);
    const float la = a - fa;
    const float lb = b - fb;
    uint32_t lo;
    asm("cvt.rn.bf16x2.f32 %0, %1, %2;" : "=r"(lo) : "f"(lb), "f"(la));
    h = hb;
    l = lo;
}

// ---------------------------------------------------------------------------
// LayerNorm -> split bf16 [row][512]. One warp per row.
// ---------------------------------------------------------------------------
__global__ __launch_bounds__(256) void ln_kernel(
    const float* __restrict__ m, const float* __restrict__ w,
    const float* __restrict__ b, __nv_bfloat16* __restrict__ osplit)
{
    const int warp = threadIdx.x >> 5;
    const int lane = threadIdx.x & 31;
    const int row  = blockIdx.x * 8 + warp;

    const float4* x4 = (const float4*)(m + (size_t)row * C_DIM);
    float4 v0 = x4[lane * 2 + 0];
    float4 v1 = x4[lane * 2 + 1];

    float s1 = (v0.x + v0.y) + (v0.z + v0.w) + (v1.x + v1.y) + (v1.z + v1.w);
    float s2 = v0.x * v0.x + v0.y * v0.y + v0.z * v0.z + v0.w * v0.w
             + v1.x * v1.x + v1.y * v1.y + v1.z * v1.z + v1.w * v1.w;
    #pragma unroll
    for (int o = 16; o > 0; o >>= 1) {
        s1 += __shfl_xor_sync(0xffffffffu, s1, o);
        s2 += __shfl_xor_sync(0xffffffffu, s2, o);
    }
    const float mu  = s1 * (1.0f / 256.0f);
    const float var = s2 * (1.0f / 256.0f) - mu * mu;
    const float rs  = rsqrtf(var + 1e-5f);

    const float4* w4 = (const float4*)w;
    const float4* b4 = (const float4*)b;
    float4 w0 = w4[lane * 2 + 0], w1 = w4[lane * 2 + 1];
    float4 b0 = b4[lane * 2 + 0], b1 = b4[lane * 2 + 1];

    float r[8];
    r[0] = (v0.x - mu) * rs * w0.x + b0.x;
    r[1] = (v0.y - mu) * rs * w0.y + b0.y;
    r[2] = (v0.z - mu) * rs * w0.z + b0.z;
    r[3] = (v0.w - mu) * rs * w0.w + b0.w;
    r[4] = (v1.x - mu) * rs * w1.x + b1.x;
    r[5] = (v1.y - mu) * rs * w1.y + b1.y;
    r[6] = (v1.z - mu) * rs * w1.z + b1.z;
    r[7] = (v1.w - mu) * rs * w1.w + b1.w;

    uint4 H, L;
    split2(r[0], r[1], H.x, L.x);
    split2(r[2], r[3], H.y, L.y);
    split2(r[4], r[5], H.z, L.z);
    split2(r[6], r[7], H.w, L.w);
    const size_t ofs = (size_t)row * 512 + lane * 8;
    *(uint4*)(osplit + ofs)       = H;
    *(uint4*)(osplit + ofs + 256) = L;
}

// ---------------------------------------------------------------------------
// Weight prep: B_ext[k_ext][n] with k_ext rows [hi, hi, lo] from w[k][n].
// ---------------------------------------------------------------------------
__global__ __launch_bounds__(256) void wconv_kernel(
    const float* __restrict__ w0, const float* __restrict__ w1,
    const float* __restrict__ w2, const float* __restrict__ w3,
    const float* __restrict__ w4,
    __nv_bfloat16* __restrict__ Bqkvg, __nv_bfloat16* __restrict__ Bo)
{
    const float* ws[5] = {w0, w1, w2, w3, w4};
    const int k   = blockIdx.x;        // 0..767
    const int wi  = blockIdx.y;        // 0..4
    const int n   = threadIdx.x;       // 0..255
    const int ks  = k & 255;
    const int seg = k >> 8;            // 0,1 -> hi ; 2 -> lo
    float x = ws[wi][ks * 256 + n];
    __nv_bfloat16 h = __float2bfloat16_rn(x);
    __nv_bfloat16 v = (seg < 2) ? h : __float2bfloat16_rn(x - __bfloat162float(h));
    if (wi < 4) Bqkvg[(size_t)k * 1024 + wi * 256 + n] = v;
    else        Bo[(size_t)k * 256 + n] = v;
}

// ---------------------------------------------------------------------------
// bf16 GEMM via mma.sync: C[M=65536, Nb] = A_ext[M,768] @ B_ext[768,Nb]
// Hoisted swizzle addressing: SWZ(row*128+col) = row*128 + (col ^ ((row&7)<<4));
// all K/stage strides are above the swizzle bits, so bases are thread-constant.
// ---------------------------------------------------------------------------
#define STAGE_BYTES 32768
#define NSTAGE 3
#define GEMM_SMEM (NSTAGE * STAGE_BYTES)

__device__ __forceinline__ void ld_chunk(
    uint32_t sbase, const __nv_bfloat16* __restrict__ A,
    const __nv_bfloat16* __restrict__ B, int Nb,
    size_t row0, int n0, int kb, int tid)
{
    const int a_off = (kb < 8 ? kb : kb - 8) * 64;
    #pragma unroll
    for (int t = 0; t < 4; t++) {
        const int i = tid + t * 256;
        const int r = i >> 3, c8 = i & 7;
        cp_async16(sbase + SWZ((uint32_t)(r * 128 + c8 * 16)),
                   A + (row0 + r) * 512 + a_off + c8 * 8);
    }
    const uint32_t bbase = sbase + 16384;
    #pragma unroll
    for (int t = 0; t < 4; t++) {
        const int i = tid + t * 256;
        const int k = i >> 4, u = i & 15;
        const uint32_t sub = (u >= 8) ? 8192u : 0u;
        cp_async16(bbase + sub + SWZ((uint32_t)(k * 128 + (u & 7) * 16)),
                   B + (size_t)(kb * 64 + k) * Nb + n0 + u * 8);
    }
}

__global__ __launch_bounds__(256) void gemm_mma(
    const __nv_bfloat16* __restrict__ A, const __nv_bfloat16* __restrict__ B,
    int Nb, int qkv_mode,
    void* C0, void* C1, void* C2, void* C3,
    const float* bias0, const float* bias3)
{
    extern __shared__ char smem[];
    const uint32_t sb = smem_u32(smem);
    const int tid  = threadIdx.x;
    const int warp = tid >> 5, lane = tid & 31;
    const int wm = (warp >> 2) * 64;
    const int wn = (warp & 3) * 32;
    const size_t row0 = (size_t)blockIdx.y * 128;
    const int n0 = blockIdx.x * 128;

    #pragma unroll
    for (int s = 0; s < 3; s++) {
        ld_chunk(sb + s * STAGE_BYTES, A, B, Nb, row0, n0, s, tid);
        CP_COMMIT();
    }

    float acc[4][4][4];
    #pragma unroll
    for (int i = 0; i < 4; i++)
        #pragma unroll
        for (int j = 0; j < 4; j++)
            #pragma unroll
            for (int x = 0; x < 4; x++) acc[i][j][x] = 0.0f;

    const int lr  = lane & 15;
    const int lh  = lane >> 4;
    const uint32_t bsub = (wn >= 64) ? 8192u : 0u;
    const int wn2 = wn & 63;

    // Hoisted swizzled base addresses (relative to stage base)
    const uint32_t mix = (uint32_t)((lr & 7) << 4);
    uint32_t abase[4];
    #pragma unroll
    for (int i = 0; i < 4; i++)
        abase[i] = (uint32_t)((wm + i * 16 + lr) * 128)
                   + ((uint32_t)(lh * 16) ^ mix);
    uint32_t bbase[2];
    #pragma unroll
    for (int j2 = 0; j2 < 2; j2++)
        bbase[j2] = 16384u + bsub + (uint32_t)(lr * 128)
                    + ((uint32_t)(wn2 * 2 + j2 * 32 + lh * 16) ^ mix);

    #pragma unroll 1
    for (int kb = 0; kb < 12; kb++) {
        CP_WAIT2();
        __syncthreads();
        const int stg = kb % 3;
        const uint32_t sgb = sb + stg * STAGE_BYTES;

        #pragma unroll
        for (int kk = 0; kk < 4; kk++) {
            uint32_t a[4][4];
            #pragma unroll
            for (int i = 0; i < 4; i++)
                ldsm4(a[i], sgb + (abase[i] ^ (uint32_t)(kk * 32)));
            uint32_t bfr[2][4];
            #pragma unroll
            for (int j2 = 0; j2 < 2; j2++)
                ldsm4t(bfr[j2], sgb + bbase[j2] + (uint32_t)(kk * 2048));
            #pragma unroll
            for (int i = 0; i < 4; i++)
                #pragma unroll
                for (int j = 0; j < 4; j++)
                    mma_bf16(acc[i][j], a[i],
                             bfr[j >> 1][(j & 1) * 2], bfr[j >> 1][(j & 1) * 2 + 1]);
        }
        __syncthreads();
        if (kb + 3 < 12) ld_chunk(sb + stg * STAGE_BYTES, A, B, Nb, row0, n0, kb + 3, tid);
        CP_COMMIT();
    }

    const int buf = (n0 >> 8) & 3;
    const int colbase = (n0 & 255) + wn + (lane & 3) * 2;

    if (qkv_mode && buf < 3) {
        __nv_bfloat16* Cq = (__nv_bfloat16*)((buf == 0) ? C0 : (buf == 1) ? C1 : C2);
        // Pre-fold softmax scale (and log2e) into Q
        const float qsc = (buf == 0) ? 0.17677669529663689f * 1.44269504088896f
                                     : 1.0f;
        #pragma unroll
        for (int i = 0; i < 4; i++) {
            const int r0 = (int)row0 + wm + i * 16 + (lane >> 2);
            #pragma unroll
            for (int j = 0; j < 4; j++) {
                const int col = colbase + j * 8;
                const int hh = col >> 5, cc = col & 31;
                #pragma unroll
                for (int rr = 0; rr < 2; rr++) {
                    const int r = r0 + rr * 8;
                    const int s = r >> 8, ll = r & 255;
                    const size_t dst = ((size_t)(ll * 8 + hh) * 256 + s) * 64 + cc;
                    uint32_t H, L;
                    split2(acc[i][j][rr * 2] * qsc, acc[i][j][rr * 2 + 1] * qsc,
                           H, L);
                    *(uint32_t*)(Cq + dst)      = H;
                    *(uint32_t*)(Cq + dst + 32) = L;
                }
            }
        }
    } else {
        float* C = (float*)((qkv_mode) ? C3 : C0);
        const float* bias = (qkv_mode) ? bias3 : bias0;
        #pragma unroll
        for (int i = 0; i < 4; i++) {
            const size_t r0 = row0 + wm + i * 16 + (lane >> 2);
            #pragma unroll
            for (int j = 0; j < 4; j++) {
                const int col = colbase + j * 8;
                float bx = 0.f, by = 0.f;
                if (bias) { bx = bias[col]; by = bias[col + 1]; }
                float2 v0 = make_float2(acc[i][j][0] + bx, acc[i][j][1] + by);
                float2 v1 = make_float2(acc[i][j][2] + bx, acc[i][j][3] + by);
                *(float2*)(C + r0 * 256 + col)       = v0;
                *(float2*)(C + (r0 + 8) * 256 + col) = v1;
            }
        }
    }
}

// ---------------------------------------------------------------------------
// Tensor-core flash attention per (l,h) tile, 512 threads / 16 warps.
// Hoisted swizzle addressing (t/chunk strides are above swizzle bits).
// Split-bf16 compensation; no online max (Q pre-scaled by scale*log2e).
//   s' = h*32 + l/8 ; l' = (l%8)*32 + s/8 ; c' = (s%8)*32 + c
// ---------------------------------------------------------------------------
#define ATT_SMEM (3 * 32768)

__global__ __launch_bounds__(512) void attn_mma_kernel(
    const __nv_bfloat16* __restrict__ Qg, const __nv_bfloat16* __restrict__ Kg,
    const __nv_bfloat16* __restrict__ Vg, const float* __restrict__ Gg,
    __nv_bfloat16* __restrict__ Osplit)
{
    extern __shared__ char smem[];
    const uint32_t sb = smem_u32(smem);
    const uint32_t QS = sb, KS = sb + 32768, VS = sb + 65536;

    const int tile = blockIdx.x;
    const int l = tile >> 3, h = tile & 7;
    const int tid = threadIdx.x;
    const size_t gbase0 = (size_t)tile * 256 * 64;

    // Load Q, K, V tiles (32KB each) via cp.async
    #pragma unroll
    for (int t = 0; t < 4; t++) {
        const int idx = t * 512 + tid;
        const int r = idx >> 3, j = idx & 7;
        const uint32_t so = SWZ((uint32_t)(r * 128 + j * 16));
        const size_t go = gbase0 + (size_t)r * 64 + j * 8;
        cp_async16(QS + so, Qg + go);
        cp_async16(KS + so, Kg + go);
        cp_async16(VS + so, Vg + go);
    }
    CP_COMMIT();
    CP_WAIT0();
    __syncthreads();

    const int warp = tid >> 5, lane = tid & 31;
    const int s0 = warp * 16;
    const int lr = lane & 15, lh = lane >> 4;

    // Q fragments (16 rows per warp, hi+lo)
    uint32_t qh[2][4], ql[2][4];
    #pragma unroll
    for (int kk = 0; kk < 2; kk++) {
        const uint32_t rowb = (uint32_t)(s0 + lr) * 128;
        ldsm4(qh[kk], QS + SWZ(rowb + (kk * 16 + lh * 8) * 2));
        ldsm4(ql[kk], QS + SWZ(rowb + (32 + kk * 16 + lh * 8) * 2));
    }

    // Hoisted swizzled K/V base addresses.
    // K rows use klr = (lane&7) + ((lane>>4)<<3); V rows use lr. Both have
    // row&7 = lane&7 -> mix = (lane&7)<<4. Fragment order c: hi0,hi1,lo0,lo1.
    const int klr = (lane & 7) + ((lane >> 4) << 3);
    const uint32_t mix = (uint32_t)((lane & 7) << 4);
    const uint32_t kcolb = (uint32_t)(((lane >> 3) & 1) * 16);
    uint32_t kaddr[4], vaddr[4];
    #pragma unroll
    for (int c = 0; c < 4; c++) {
        kaddr[c] = KS + (uint32_t)(klr * 128) + ((kcolb + c * 32) ^ mix);
        vaddr[c] = VS + (uint32_t)(lr * 128)
                   + (((uint32_t)(lh * 16) + c * 32) ^ mix);
    }

    float o[4][4];
    #pragma unroll
    for (int j = 0; j < 4; j++)
        #pragma unroll
        for (int x = 0; x < 4; x++) o[j][x] = 0.0f;
    float sm[2] = {0.f, 0.f};

    #pragma unroll 1
    for (int chunk = 0; chunk < 4; chunk++) {
        const uint32_t coff = (uint32_t)(chunk * 8192);
        float s_acc[8][4];
        #pragma unroll
        for (int j = 0; j < 8; j++)
            #pragma unroll
            for (int x = 0; x < 4; x++) s_acc[j][x] = 0.0f;

        // ---- S = Q K^T (3 split terms; Q pre-scaled) ----
        #pragma unroll
        for (int g = 0; g < 4; g++) {
            const uint32_t gg = coff + (uint32_t)(g * 2048);
            uint32_t kh[2][4], kl[2][4];
            ldsm4(kh[0], kaddr[0] + gg);
            ldsm4(kh[1], kaddr[1] + gg);
            ldsm4(kl[0], kaddr[2] + gg);
            ldsm4(kl[1], kaddr[3] + gg);
            #pragma unroll
            for (int ch = 0; ch < 2; ch++) {
                mma_bf16(s_acc[2 * g],     qh[ch], kh[ch][0], kh[ch][1]);
                mma_bf16(s_acc[2 * g + 1], qh[ch], kh[ch][2], kh[ch][3]);
                mma_bf16(s_acc[2 * g],     ql[ch], kh[ch][0], kh[ch][1]);
                mma_bf16(s_acc[2 * g + 1], ql[ch], kh[ch][2], kh[ch][3]);
                mma_bf16(s_acc[2 * g],     qh[ch], kl[ch][0], kl[ch][1]);
                mma_bf16(s_acc[2 * g + 1], qh[ch], kl[ch][2], kl[ch][3]);
            }
        }

        // ---- exp2 (logits already in log2 units) + sum ----
        {
            float ps0 = 0.f, ps1 = 0.f;
            #pragma unroll
            for (int j = 0; j < 8; j++) {
                const float p0 = exp2f(s_acc[j][0]);
                const float p1 = exp2f(s_acc[j][1]);
                const float p2 = exp2f(s_acc[j][2]);
                const float p3 = exp2f(s_acc[j][3]);
                s_acc[j][0] = p0; s_acc[j][1] = p1;
                s_acc[j][2] = p2; s_acc[j][3] = p3;
                ps0 += p0 + p1;
                ps1 += p2 + p3;
            }
            sm[0] += ps0;
            sm[1] += ps1;
        }

        // ---- O += P V (3 split terms) ----
        #pragma unroll
        for (int g = 0; g < 4; g++) {
            const uint32_t gg = coff + (uint32_t)(g * 2048);
            uint32_t vh[2][4], vl[2][4];
            ldsm4t(vh[0], vaddr[0] + gg);
            ldsm4t(vh[1], vaddr[1] + gg);
            ldsm4t(vl[0], vaddr[2] + gg);
            ldsm4t(vl[1], vaddr[3] + gg);
            uint32_t ah[4], al[4];
            split2(s_acc[2 * g][0],     s_acc[2 * g][1],     ah[0], al[0]);
            split2(s_acc[2 * g][2],     s_acc[2 * g][3],     ah[1], al[1]);
            split2(s_acc[2 * g + 1][0], s_acc[2 * g + 1][1], ah[2], al[2]);
            split2(s_acc[2 * g + 1][2], s_acc[2 * g + 1][3], ah[3], al[3]);
            #pragma unroll
            for (int j = 0; j < 4; j++) {
                const int j2 = j >> 1, jj = (j & 1) * 2;
                mma_bf16(o[j], ah, vh[j2][jj], vh[j2][jj + 1]);
                mma_bf16(o[j], al, vh[j2][jj], vh[j2][jj + 1]);
                mma_bf16(o[j], ah, vl[j2][jj], vl[j2][jj + 1]);
            }
        }
    }

    // ---- epilogue: normalize, gate, scramble, store split bf16 ----
    const int i_o = h * 32 + (l >> 3);
    #pragma unroll
    for (int rr = 0; rr < 2; rr++) {
        float v = sm[rr];
        v += __shfl_xor_sync(0xffffffffu, v, 1);
        v += __shfl_xor_sync(0xffffffffu, v, 2);
        const float inv = 1.0f / v;
        const int s = s0 + (lane >> 2) + rr * 8;
        const int j_o = ((l & 7) << 5) + (s >> 3);
        const int k_o = (s & 7) << 5;
        const size_t gb = ((size_t)i_o * 256 + j_o) * 256 + k_o;
        const size_t ob = ((size_t)i_o * 256 + j_o) * 512 + k_o;
        #pragma unroll
        for (int j = 0; j < 4; j++) {
            const int c = j * 8 + (lane & 3) * 2;
            const float2 gg = *(const float2*)(Gg + gb + c);
            const float w0 = o[j][rr * 2] * inv
                             / (1.0f + exp2f(-gg.x * 1.44269504088896f));
            const float w1 = o[j][rr * 2 + 1] * inv
                             / (1.0f + exp2f(-gg.y * 1.44269504088896f));
            uint32_t H, L;
            split2(w0, w1, H, L);
            *(uint32_t*)(Osplit + ob + c)       = H;
            *(uint32_t*)(Osplit + ob + 256 + c) = L;
        }
    }
}

// ---------------------------------------------------------------------------
extern "C" void kernel_launch(void* const* d_in, const int* in_sizes, int n_in,
                              void* d_out, int out_size)
{
    const float* m    = (const float*)d_in[0];
    const float* ln_w = (const float*)d_in[1];
    const float* ln_b = (const float*)d_in[2];
    const float* wq   = (const float*)d_in[3];
    const float* wk   = (const float*)d_in[4];
    const float* wv   = (const float*)d_in[5];
    const float* wg   = (const float*)d_in[6];
    const float* bg   = (const float*)d_in[7];
    const float* wo   = (const float*)d_in[8];
    const float* bo   = (const float*)d_in[9];
    float* out = (float*)d_out;

    __nv_bfloat16 *mns, *ats, *Bq, *Bo, *qs, *ks, *vs;
    float *g;
    cudaGetSymbolAddress((void**)&mns, g_mn_split);
    cudaGetSymbolAddress((void**)&ats, g_att_split);
    cudaGetSymbolAddress((void**)&qs,  g_qs);
    cudaGetSymbolAddress((void**)&ks,  g_ks);
    cudaGetSymbolAddress((void**)&vs,  g_vs);
    cudaGetSymbolAddress((void**)&g,   g_g);
    cudaGetSymbolAddress((void**)&Bq,  g_Bqkvg);
    cudaGetSymbolAddress((void**)&Bo,  g_Bo);

    cudaFuncSetAttribute(gemm_mma,
                         cudaFuncAttributeMaxDynamicSharedMemorySize, GEMM_SMEM);
    cudaFuncSetAttribute(attn_mma_kernel,
                         cudaFuncAttributeMaxDynamicSharedMemorySize, ATT_SMEM);

    // 1. LayerNorm -> split bf16
    ln_kernel<<<NROWS / 8, 256>>>(m, ln_w, ln_b, mns);

    // 2. Weight prep
    wconv_kernel<<<dim3(768, 5), 256>>>(wq, wk, wv, wg, wo, Bq, Bo);

    // 3. Fused Q/K/V/G projection: [65536,768] @ [768,1024]
    gemm_mma<<<dim3(8, NROWS / 128), 256, GEMM_SMEM>>>(
        mns, Bq, 1024, 1, qs, ks, vs, g, nullptr, bg);

    // 4. Tensor-core flash attention (512 thr) + gate + scramble
    attn_mma_kernel<<<L_DIM * NH, 512, ATT_SMEM>>>(qs, ks, vs, g, ats);

    // 5. Output projection: [65536,768] @ [768,256] -> d_out (+bo)
    gemm_mma<<<dim3(2, NROWS / 128), 256, GEMM_SMEM>>>(
        ats, Bo, 256, 0, out, nullptr, nullptr, nullptr, bo, nullptr);
}

// round 9
// speedup vs baseline: 2.9073x; 1.0100x over previous
#include <cuda_runtime.h>
#include <cuda_bf16.h>
#include <cstdint>
#include <math.h>

// Problem constants: B=1, n_seq=S=256, seq_len=L=256, c_m=256, H=8, ch=32, HC=256
#define S_DIM 256
#define L_DIM 256
#define C_DIM 256
#define HC_DIM 256
#define NH 8
#define CH 32
#define NROWS (S_DIM * L_DIM)  // 65536

// ---------------------------------------------------------------------------
// Scratch (device globals per allocation rules)
// ---------------------------------------------------------------------------
__device__ __align__(16) __nv_bfloat16 g_mn_split[NROWS * 512];
__device__ __align__(16) __nv_bfloat16 g_att_split[NROWS * 512];
// Q/K/V attention-tile layout: [(l*8+h)][s][64] rows = [hi32|lo32] bf16
__device__ __align__(16) __nv_bfloat16 g_qs[NROWS * 512];
__device__ __align__(16) __nv_bfloat16 g_ks[NROWS * 512];
__device__ __align__(16) __nv_bfloat16 g_vs[NROWS * 512];
__device__ __align__(16) float g_g[NROWS * HC_DIM];
__device__ __align__(16) __nv_bfloat16 g_Bqkvg[768 * 1024];  // cols: q|k|v|g
__device__ __align__(16) __nv_bfloat16 g_Bo[768 * 256];

// ---------------------------------------------------------------------------
// Helpers
// ---------------------------------------------------------------------------
__device__ __forceinline__ uint32_t smem_u32(const void* p) {
    uint32_t a;
    asm("{ .reg .u64 t; cvta.to.shared.u64 t, %1; cvt.u32.u64 %0, t; }"
        : "=r"(a) : "l"(p));
    return a;
}

#define SWZ(o) ((o) ^ (((o) >> 3) & 0x70))

__device__ __forceinline__ void cp_async16(uint32_t saddr, const void* gptr) {
    asm volatile("cp.async.cg.shared.global [%0], [%1], 16;"
                 :: "r"(saddr), "l"(__cvta_generic_to_global(gptr)) : "memory");
}
#define CP_COMMIT() asm volatile("cp.async.commit_group;" ::: "memory")
#define CP_WAIT2()  asm volatile("cp.async.wait_group 2;" ::: "memory")
#define CP_WAIT0()  asm volatile("cp.async.wait_group 0;" ::: "memory")

__device__ __forceinline__ void ldsm4(uint32_t* r, uint32_t addr) {
    asm volatile("ldmatrix.sync.aligned.m8n8.x4.shared.b16 {%0,%1,%2,%3}, [%4];"
                 : "=r"(r[0]), "=r"(r[1]), "=r"(r[2]), "=r"(r[3]) : "r"(addr));
}
__device__ __forceinline__ void ldsm4t(uint32_t* r, uint32_t addr) {
    asm volatile("ldmatrix.sync.aligned.m8n8.x4.trans.shared.b16 {%0,%1,%2,%3}, [%4];"
                 : "=r"(r[0]), "=r"(r[1]), "=r"(r[2]), "=r"(r[3]) : "r"(addr));
}
__device__ __forceinline__ void mma_bf16(float* c, const uint32_t* a,
                                         uint32_t b0, uint32_t b1) {
    asm volatile(
        "mma.sync.aligned.m16n8k16.row.col.f32.bf16.bf16.f32 "
        "{%0,%1,%2,%3}, {%4,%5,%6,%7}, {%8,%9}, {%0,%1,%2,%3};"
        : "+f"(c[0]), "+f"(c[1]), "+f"(c[2]), "+f"(c[3])
        : "r"(a[0]), "r"(a[1]), "r"(a[2]), "r"(a[3]), "r"(b0), "r"(b1));
}

// fp32 -> bf16 hi/lo split (packed pairs), bit-trick hi reconstruction.
__device__ __forceinline__ void split2(float a, float b, uint32_t& h, uint32_t& l) {
    uint32_t hb;
    asm("cvt.rn.bf16x2.f32 %0, %1, %2;" : "=r"(hb) : "f"(b), "f"(a));
    const float fa = __uint_as_float(hb << 16);
    const float fb = __uint_as_float(hb & 0xffff0000u);
    const float la = a - fa;
    const float lb = b - fb;
    uint32_t lo;
    asm("cvt.rn.bf16x2.f32 %0, %1, %2;" : "=r"(lo) : "f"(lb), "f"(la));
    h = hb;
    l = lo;
}

// ---------------------------------------------------------------------------
// LayerNorm -> split bf16 [row][512]. One warp per row.
// ---------------------------------------------------------------------------
__global__ __launch_bounds__(256) void ln_kernel(
    const float* __restrict__ m, const float* __restrict__ w,
    const float* __restrict__ b, __nv_bfloat16* __restrict__ osplit)
{
    const int warp = threadIdx.x >> 5;
    const int lane = threadIdx.x & 31;
    const int row  = blockIdx.x * 8 + warp;

    const float4* x4 = (const float4*)(m + (size_t)row * C_DIM);
    float4 v0 = x4[lane * 2 + 0];
    float4 v1 = x4[lane * 2 + 1];

    float s1 = (v0.x + v0.y) + (v0.z + v0.w) + (v1.x + v1.y) + (v1.z + v1.w);
    float s2 = v0.x * v0.x + v0.y * v0.y + v0.z * v0.z + v0.w * v0.w
             + v1.x * v1.x + v1.y * v1.y + v1.z * v1.z + v1.w * v1.w;
    #pragma unroll
    for (int o = 16; o > 0; o >>= 1) {
        s1 += __shfl_xor_sync(0xffffffffu, s1, o);
        s2 += __shfl_xor_sync(0xffffffffu, s2, o);
    }
    const float mu  = s1 * (1.0f / 256.0f);
    const float var = s2 * (1.0f / 256.0f) - mu * mu;
    const float rs  = rsqrtf(var + 1e-5f);

    const float4* w4 = (const float4*)w;
    const float4* b4 = (const float4*)b;
    float4 w0 = w4[lane * 2 + 0], w1 = w4[lane * 2 + 1];
    float4 b0 = b4[lane * 2 + 0], b1 = b4[lane * 2 + 1];

    float r[8];
    r[0] = (v0.x - mu) * rs * w0.x + b0.x;
    r[1] = (v0.y - mu) * rs * w0.y + b0.y;
    r[2] = (v0.z - mu) * rs * w0.z + b0.z;
    r[3] = (v0.w - mu) * rs * w0.w + b0.w;
    r[4] = (v1.x - mu) * rs * w1.x + b1.x;
    r[5] = (v1.y - mu) * rs * w1.y + b1.y;
    r[6] = (v1.z - mu) * rs * w1.z + b1.z;
    r[7] = (v1.w - mu) * rs * w1.w + b1.w;

    uint4 H, L;
    split2(r[0], r[1], H.x, L.x);
    split2(r[2], r[3], H.y, L.y);
    split2(r[4], r[5], H.z, L.z);
    split2(r[6], r[7], H.w, L.w);
    const size_t ofs = (size_t)row * 512 + lane * 8;
    *(uint4*)(osplit + ofs)       = H;
    *(uint4*)(osplit + ofs + 256) = L;
}

// ---------------------------------------------------------------------------
// Weight prep: B_ext[k_ext][n] with k_ext rows [hi, hi, lo] from w[k][n].
// ---------------------------------------------------------------------------
__global__ __launch_bounds__(256) void wconv_kernel(
    const float* __restrict__ w0, const float* __restrict__ w1,
    const float* __restrict__ w2, const float* __restrict__ w3,
    const float* __restrict__ w4,
    __nv_bfloat16* __restrict__ Bqkvg, __nv_bfloat16* __restrict__ Bo)
{
    const float* ws[5] = {w0, w1, w2, w3, w4};
    const int k   = blockIdx.x;        // 0..767
    const int wi  = blockIdx.y;        // 0..4
    const int n   = threadIdx.x;       // 0..255
    const int ks  = k & 255;
    const int seg = k >> 8;            // 0,1 -> hi ; 2 -> lo
    float x = ws[wi][ks * 256 + n];
    __nv_bfloat16 h = __float2bfloat16_rn(x);
    __nv_bfloat16 v = (seg < 2) ? h : __float2bfloat16_rn(x - __bfloat162float(h));
    if (wi < 4) Bqkvg[(size_t)k * 1024 + wi * 256 + n] = v;
    else        Bo[(size_t)k * 256 + n] = v;
}

// ---------------------------------------------------------------------------
// bf16 GEMM via mma.sync: C[M=65536, Nb] = A_ext[M,768] @ B_ext[768,Nb]
// Hoisted swizzle addressing (unchanged from R8 — it delivered).
// ---------------------------------------------------------------------------
#define STAGE_BYTES 32768
#define NSTAGE 3
#define GEMM_SMEM (NSTAGE * STAGE_BYTES)

__device__ __forceinline__ void ld_chunk(
    uint32_t sbase, const __nv_bfloat16* __restrict__ A,
    const __nv_bfloat16* __restrict__ B, int Nb,
    size_t row0, int n0, int kb, int tid)
{
    const int a_off = (kb < 8 ? kb : kb - 8) * 64;
    #pragma unroll
    for (int t = 0; t < 4; t++) {
        const int i = tid + t * 256;
        const int r = i >> 3, c8 = i & 7;
        cp_async16(sbase + SWZ((uint32_t)(r * 128 + c8 * 16)),
                   A + (row0 + r) * 512 + a_off + c8 * 8);
    }
    const uint32_t bbase = sbase + 16384;
    #pragma unroll
    for (int t = 0; t < 4; t++) {
        const int i = tid + t * 256;
        const int k = i >> 4, u = i & 15;
        const uint32_t sub = (u >= 8) ? 8192u : 0u;
        cp_async16(bbase + sub + SWZ((uint32_t)(k * 128 + (u & 7) * 16)),
                   B + (size_t)(kb * 64 + k) * Nb + n0 + u * 8);
    }
}

__global__ __launch_bounds__(256) void gemm_mma(
    const __nv_bfloat16* __restrict__ A, const __nv_bfloat16* __restrict__ B,
    int Nb, int qkv_mode,
    void* C0, void* C1, void* C2, void* C3,
    const float* bias0, const float* bias3)
{
    extern __shared__ char smem[];
    const uint32_t sb = smem_u32(smem);
    const int tid  = threadIdx.x;
    const int warp = tid >> 5, lane = tid & 31;
    const int wm = (warp >> 2) * 64;
    const int wn = (warp & 3) * 32;
    const size_t row0 = (size_t)blockIdx.y * 128;
    const int n0 = blockIdx.x * 128;

    #pragma unroll
    for (int s = 0; s < 3; s++) {
        ld_chunk(sb + s * STAGE_BYTES, A, B, Nb, row0, n0, s, tid);
        CP_COMMIT();
    }

    float acc[4][4][4];
    #pragma unroll
    for (int i = 0; i < 4; i++)
        #pragma unroll
        for (int j = 0; j < 4; j++)
            #pragma unroll
            for (int x = 0; x < 4; x++) acc[i][j][x] = 0.0f;

    const int lr  = lane & 15;
    const int lh  = lane >> 4;
    const uint32_t bsub = (wn >= 64) ? 8192u : 0u;
    const int wn2 = wn & 63;

    const uint32_t mix = (uint32_t)((lr & 7) << 4);
    uint32_t abase[4];
    #pragma unroll
    for (int i = 0; i < 4; i++)
        abase[i] = (uint32_t)((wm + i * 16 + lr) * 128)
                   + ((uint32_t)(lh * 16) ^ mix);
    uint32_t bbase[2];
    #pragma unroll
    for (int j2 = 0; j2 < 2; j2++)
        bbase[j2] = 16384u + bsub + (uint32_t)(lr * 128)
                    + ((uint32_t)(wn2 * 2 + j2 * 32 + lh * 16) ^ mix);

    #pragma unroll 1
    for (int kb = 0; kb < 12; kb++) {
        CP_WAIT2();
        __syncthreads();
        const int stg = kb % 3;
        const uint32_t sgb = sb + stg * STAGE_BYTES;

        #pragma unroll
        for (int kk = 0; kk < 4; kk++) {
            uint32_t a[4][4];
            #pragma unroll
            for (int i = 0; i < 4; i++)
                ldsm4(a[i], sgb + (abase[i] ^ (uint32_t)(kk * 32)));
            uint32_t bfr[2][4];
            #pragma unroll
            for (int j2 = 0; j2 < 2; j2++)
                ldsm4t(bfr[j2], sgb + bbase[j2] + (uint32_t)(kk * 2048));
            #pragma unroll
            for (int i = 0; i < 4; i++)
                #pragma unroll
                for (int j = 0; j < 4; j++)
                    mma_bf16(acc[i][j], a[i],
                             bfr[j >> 1][(j & 1) * 2], bfr[j >> 1][(j & 1) * 2 + 1]);
        }
        __syncthreads();
        if (kb + 3 < 12) ld_chunk(sb + stg * STAGE_BYTES, A, B, Nb, row0, n0, kb + 3, tid);
        CP_COMMIT();
    }

    const int buf = (n0 >> 8) & 3;
    const int colbase = (n0 & 255) + wn + (lane & 3) * 2;

    if (qkv_mode && buf < 3) {
        __nv_bfloat16* Cq = (__nv_bfloat16*)((buf == 0) ? C0 : (buf == 1) ? C1 : C2);
        const float qsc = (buf == 0) ? 0.17677669529663689f * 1.44269504088896f
                                     : 1.0f;
        #pragma unroll
        for (int i = 0; i < 4; i++) {
            const int r0 = (int)row0 + wm + i * 16 + (lane >> 2);
            #pragma unroll
            for (int j = 0; j < 4; j++) {
                const int col = colbase + j * 8;
                const int hh = col >> 5, cc = col & 31;
                #pragma unroll
                for (int rr = 0; rr < 2; rr++) {
                    const int r = r0 + rr * 8;
                    const int s = r >> 8, ll = r & 255;
                    const size_t dst = ((size_t)(ll * 8 + hh) * 256 + s) * 64 + cc;
                    uint32_t H, L;
                    split2(acc[i][j][rr * 2] * qsc, acc[i][j][rr * 2 + 1] * qsc,
                           H, L);
                    *(uint32_t*)(Cq + dst)      = H;
                    *(uint32_t*)(Cq + dst + 32) = L;
                }
            }
        }
    } else {
        float* C = (float*)((qkv_mode) ? C3 : C0);
        const float* bias = (qkv_mode) ? bias3 : bias0;
        #pragma unroll
        for (int i = 0; i < 4; i++) {
            const size_t r0 = row0 + wm + i * 16 + (lane >> 2);
            #pragma unroll
            for (int j = 0; j < 4; j++) {
                const int col = colbase + j * 8;
                float bx = 0.f, by = 0.f;
                if (bias) { bx = bias[col]; by = bias[col + 1]; }
                float2 v0 = make_float2(acc[i][j][0] + bx, acc[i][j][1] + by);
                float2 v1 = make_float2(acc[i][j][2] + bx, acc[i][j][3] + by);
                *(float2*)(C + r0 * 256 + col)       = v0;
                *(float2*)(C + (r0 + 8) * 256 + col) = v1;
            }
        }
    }
}

// ---------------------------------------------------------------------------
// Tensor-core flash attention per (l,h) tile, 512 threads / 16 warps.
// Software-pipelined at 16-t-block granularity: S(gt+1) overlaps
// exp/split/PV(gt) — two independent MMA streams in flight per warp.
//   s' = h*32 + l/8 ; l' = (l%8)*32 + s/8 ; c' = (s%8)*32 + c
// ---------------------------------------------------------------------------
#define ATT_SMEM (3 * 32768)

__global__ __launch_bounds__(512) void attn_mma_kernel(
    const __nv_bfloat16* __restrict__ Qg, const __nv_bfloat16* __restrict__ Kg,
    const __nv_bfloat16* __restrict__ Vg, const float* __restrict__ Gg,
    __nv_bfloat16* __restrict__ Osplit)
{
    extern __shared__ char smem[];
    const uint32_t sb = smem_u32(smem);
    const uint32_t QS = sb, KS = sb + 32768, VS = sb + 65536;

    const int tile = blockIdx.x;
    const int l = tile >> 3, h = tile & 7;
    const int tid = threadIdx.x;
    const size_t gbase0 = (size_t)tile * 256 * 64;

    // Load Q, K, V tiles (32KB each) via cp.async
    #pragma unroll
    for (int t = 0; t < 4; t++) {
        const int idx = t * 512 + tid;
        const int r = idx >> 3, j = idx & 7;
        const uint32_t so = SWZ((uint32_t)(r * 128 + j * 16));
        const size_t go = gbase0 + (size_t)r * 64 + j * 8;
        cp_async16(QS + so, Qg + go);
        cp_async16(KS + so, Kg + go);
        cp_async16(VS + so, Vg + go);
    }
    CP_COMMIT();
    CP_WAIT0();
    __syncthreads();

    const int warp = tid >> 5, lane = tid & 31;
    const int s0 = warp * 16;
    const int lr = lane & 15, lh = lane >> 4;

    // Q fragments (16 rows per warp, hi+lo; Q pre-scaled by scale*log2e)
    uint32_t qh[2][4], ql[2][4];
    #pragma unroll
    for (int kk = 0; kk < 2; kk++) {
        const uint32_t rowb = (uint32_t)(s0 + lr) * 128;
        ldsm4(qh[kk], QS + SWZ(rowb + (kk * 16 + lh * 8) * 2));
        ldsm4(ql[kk], QS + SWZ(rowb + (32 + kk * 16 + lh * 8) * 2));
    }

    // Hoisted swizzled K/V base addresses (t-block stride 2048B is above
    // the swizzle bits). Fragment order c: hi0, hi1, lo0, lo1.
    const int klr = (lane & 7) + ((lane >> 4) << 3);
    const uint32_t mix = (uint32_t)((lane & 7) << 4);
    const uint32_t kcolb = (uint32_t)(((lane >> 3) & 1) * 16);
    uint32_t kaddr[4], vaddr[4];
    #pragma unroll
    for (int c = 0; c < 4; c++) {
        kaddr[c] = KS + (uint32_t)(klr * 128) + ((kcolb + c * 32) ^ mix);
        vaddr[c] = VS + (uint32_t)(lr * 128)
                   + (((uint32_t)(lh * 16) + c * 32) ^ mix);
    }

    float o[4][4];
    #pragma unroll
    for (int j = 0; j < 4; j++)
        #pragma unroll
        for (int x = 0; x < 4; x++) o[j][x] = 0.0f;
    float sm[2] = {0.f, 0.f};

    // S-block compute: 16 t-cols -> s[2][4] (two n8 targets)
    auto S_compute = [&](int gt, float s[2][4]) {
        const uint32_t gg = (uint32_t)(gt * 2048);
        uint32_t kh[2][4], kl[2][4];
        ldsm4(kh[0], kaddr[0] + gg);
        ldsm4(kh[1], kaddr[1] + gg);
        ldsm4(kl[0], kaddr[2] + gg);
        ldsm4(kl[1], kaddr[3] + gg);
        #pragma unroll
        for (int x = 0; x < 4; x++) { s[0][x] = 0.f; s[1][x] = 0.f; }
        #pragma unroll
        for (int ch = 0; ch < 2; ch++) {
            mma_bf16(s[0], qh[ch], kh[ch][0], kh[ch][1]);
            mma_bf16(s[1], qh[ch], kh[ch][2], kh[ch][3]);
            mma_bf16(s[0], ql[ch], kh[ch][0], kh[ch][1]);
            mma_bf16(s[1], ql[ch], kh[ch][2], kh[ch][3]);
            mma_bf16(s[0], qh[ch], kl[ch][0], kl[ch][1]);
            mma_bf16(s[1], qh[ch], kl[ch][2], kl[ch][3]);
        }
    };

    // exp + sum + split + P·V accumulate for one t-block
    auto PV_compute = [&](int gt, float s[2][4]) {
        #pragma unroll
        for (int tgt = 0; tgt < 2; tgt++) {
            #pragma unroll
            for (int x = 0; x < 4; x++) s[tgt][x] = exp2f(s[tgt][x]);
        }
        sm[0] += (s[0][0] + s[0][1]) + (s[1][0] + s[1][1]);
        sm[1] += (s[0][2] + s[0][3]) + (s[1][2] + s[1][3]);

        uint32_t ah[4], al[4];
        split2(s[0][0], s[0][1], ah[0], al[0]);
        split2(s[0][2], s[0][3], ah[1], al[1]);
        split2(s[1][0], s[1][1], ah[2], al[2]);
        split2(s[1][2], s[1][3], ah[3], al[3]);

        const uint32_t gg = (uint32_t)(gt * 2048);
        uint32_t vh[2][4], vl[2][4];
        ldsm4t(vh[0], vaddr[0] + gg);
        ldsm4t(vh[1], vaddr[1] + gg);
        ldsm4t(vl[0], vaddr[2] + gg);
        ldsm4t(vl[1], vaddr[3] + gg);
        #pragma unroll
        for (int j = 0; j < 4; j++) {
            const int j2 = j >> 1, jj = (j & 1) * 2;
            mma_bf16(o[j], ah, vh[j2][jj], vh[j2][jj + 1]);
            mma_bf16(o[j], al, vh[j2][jj], vh[j2][jj + 1]);
            mma_bf16(o[j], ah, vl[j2][jj], vl[j2][jj + 1]);
        }
    };

    // Ping-pong software pipeline over 16 t-blocks
    float s_a[2][4], s_b[2][4];
    S_compute(0, s_a);
    #pragma unroll
    for (int gt = 0; gt < 16; gt += 2) {
        if (gt + 1 < 16) S_compute(gt + 1, s_b);
        PV_compute(gt, s_a);
        if (gt + 2 < 16) S_compute(gt + 2, s_a);
        if (gt + 1 < 16) PV_compute(gt + 1, s_b);
    }

    // ---- epilogue: normalize, gate, scramble, store split bf16 ----
    const int i_o = h * 32 + (l >> 3);
    #pragma unroll
    for (int rr = 0; rr < 2; rr++) {
        float v = sm[rr];
        v += __shfl_xor_sync(0xffffffffu, v, 1);
        v += __shfl_xor_sync(0xffffffffu, v, 2);
        const float inv = 1.0f / v;
        const int s = s0 + (lane >> 2) + rr * 8;
        const int j_o = ((l & 7) << 5) + (s >> 3);
        const int k_o = (s & 7) << 5;
        const size_t gb = ((size_t)i_o * 256 + j_o) * 256 + k_o;
        const size_t ob = ((size_t)i_o * 256 + j_o) * 512 + k_o;
        #pragma unroll
        for (int j = 0; j < 4; j++) {
            const int c = j * 8 + (lane & 3) * 2;
            const float2 gg = *(const float2*)(Gg + gb + c);
            const float w0 = o[j][rr * 2] * inv
                             / (1.0f + exp2f(-gg.x * 1.44269504088896f));
            const float w1 = o[j][rr * 2 + 1] * inv
                             / (1.0f + exp2f(-gg.y * 1.44269504088896f));
            uint32_t H, L;
            split2(w0, w1, H, L);
            *(uint32_t*)(Osplit + ob + c)       = H;
            *(uint32_t*)(Osplit + ob + 256 + c) = L;
        }
    }
}

// ---------------------------------------------------------------------------
extern "C" void kernel_launch(void* const* d_in, const int* in_sizes, int n_in,
                              void* d_out, int out_size)
{
    const float* m    = (const float*)d_in[0];
    const float* ln_w = (const float*)d_in[1];
    const float* ln_b = (const float*)d_in[2];
    const float* wq   = (const float*)d_in[3];
    const float* wk   = (const float*)d_in[4];
    const float* wv   = (const float*)d_in[5];
    const float* wg   = (const float*)d_in[6];
    const float* bg   = (const float*)d_in[7];
    const float* wo   = (const float*)d_in[8];
    const float* bo   = (const float*)d_in[9];
    float* out = (float*)d_out;

    __nv_bfloat16 *mns, *ats, *Bq, *Bo, *qs, *ks, *vs;
    float *g;
    cudaGetSymbolAddress((void**)&mns, g_mn_split);
    cudaGetSymbolAddress((void**)&ats, g_att_split);
    cudaGetSymbolAddress((void**)&qs,  g_qs);
    cudaGetSymbolAddress((void**)&ks,  g_ks);
    cudaGetSymbolAddress((void**)&vs,  g_vs);
    cudaGetSymbolAddress((void**)&g,   g_g);
    cudaGetSymbolAddress((void**)&Bq,  g_Bqkvg);
    cudaGetSymbolAddress((void**)&Bo,  g_Bo);

    cudaFuncSetAttribute(gemm_mma,
                         cudaFuncAttributeMaxDynamicSharedMemorySize, GEMM_SMEM);
    cudaFuncSetAttribute(attn_mma_kernel,
                         cudaFuncAttributeMaxDynamicSharedMemorySize, ATT_SMEM);

    // 1. LayerNorm -> split bf16
    ln_kernel<<<NROWS / 8, 256>>>(m, ln_w, ln_b, mns);

    // 2. Weight prep
    wconv_kernel<<<dim3(768, 5), 256>>>(wq, wk, wv, wg, wo, Bq, Bo);

    // 3. Fused Q/K/V/G projection: [65536,768] @ [768,1024]
    gemm_mma<<<dim3(8, NROWS / 128), 256, GEMM_SMEM>>>(
        mns, Bq, 1024, 1, qs, ks, vs, g, nullptr, bg);

    // 4. Tensor-core flash attention (pipelined) + gate + scramble
    attn_mma_kernel<<<L_DIM * NH, 512, ATT_SMEM>>>(qs, ks, vs, g, ats);

    // 5. Output projection: [65536,768] @ [768,256] -> d_out (+bo)
    gemm_mma<<<dim3(2, NROWS / 128), 256, GEMM_SMEM>>>(
        ats, Bo, 256, 0, out, nullptr, nullptr, nullptr, bo, nullptr);
}

// round 10
// speedup vs baseline: 3.2075x; 1.1033x over previous
#include <cuda_runtime.h>
#include <cuda_bf16.h>
#include <cstdint>
#include <math.h>

// Problem constants: B=1, n_seq=S=256, seq_len=L=256, c_m=256, H=8, ch=32, HC=256
#define S_DIM 256
#define L_DIM 256
#define C_DIM 256
#define HC_DIM 256
#define NH 8
#define CH 32
#define NROWS (S_DIM * L_DIM)  // 65536

// ---------------------------------------------------------------------------
// Scratch (device globals per allocation rules)
// ---------------------------------------------------------------------------
__device__ __align__(16) __nv_bfloat16 g_mn_split[NROWS * 512];
__device__ __align__(16) __nv_bfloat16 g_att_split[NROWS * 512];
// Q/K/V attention-tile layout: [(l*8+h)][s][64] rows = [hi32|lo32] bf16
__device__ __align__(16) __nv_bfloat16 g_qs[NROWS * 512];
__device__ __align__(16) __nv_bfloat16 g_ks[NROWS * 512];
__device__ __align__(16) __nv_bfloat16 g_vs[NROWS * 512];
__device__ __align__(16) float g_g[NROWS * HC_DIM];
__device__ __align__(16) __nv_bfloat16 g_Bqkvg[768 * 1024];  // cols: q|k|v|g
__device__ __align__(16) __nv_bfloat16 g_Bo[768 * 256];

// ---------------------------------------------------------------------------
// Helpers
// ---------------------------------------------------------------------------
__device__ __forceinline__ uint32_t smem_u32(const void* p) {
    uint32_t a;
    asm("{ .reg .u64 t; cvta.to.shared.u64 t, %1; cvt.u32.u64 %0, t; }"
        : "=r"(a) : "l"(p));
    return a;
}

#define SWZ(o) ((o) ^ (((o) >> 3) & 0x70))

__device__ __forceinline__ void cp_async16(uint32_t saddr, const void* gptr) {
    asm volatile("cp.async.cg.shared.global [%0], [%1], 16;"
                 :: "r"(saddr), "l"(__cvta_generic_to_global(gptr)) : "memory");
}
#define CP_COMMIT() asm volatile("cp.async.commit_group;" ::: "memory")
#define CP_WAIT2()  asm volatile("cp.async.wait_group 2;" ::: "memory")
#define CP_WAIT0()  asm volatile("cp.async.wait_group 0;" ::: "memory")

__device__ __forceinline__ void ldsm4(uint32_t* r, uint32_t addr) {
    asm volatile("ldmatrix.sync.aligned.m8n8.x4.shared.b16 {%0,%1,%2,%3}, [%4];"
                 : "=r"(r[0]), "=r"(r[1]), "=r"(r[2]), "=r"(r[3]) : "r"(addr));
}
__device__ __forceinline__ void ldsm4t(uint32_t* r, uint32_t addr) {
    asm volatile("ldmatrix.sync.aligned.m8n8.x4.trans.shared.b16 {%0,%1,%2,%3}, [%4];"
                 : "=r"(r[0]), "=r"(r[1]), "=r"(r[2]), "=r"(r[3]) : "r"(addr));
}
__device__ __forceinline__ void mma_bf16(float* c, const uint32_t* a,
                                         uint32_t b0, uint32_t b1) {
    asm volatile(
        "mma.sync.aligned.m16n8k16.row.col.f32.bf16.bf16.f32 "
        "{%0,%1,%2,%3}, {%4,%5,%6,%7}, {%8,%9}, {%0,%1,%2,%3};"
        : "+f"(c[0]), "+f"(c[1]), "+f"(c[2]), "+f"(c[3])
        : "r"(a[0]), "r"(a[1]), "r"(a[2]), "r"(a[3]), "r"(b0), "r"(b1));
}

// fp32 -> bf16 hi/lo split (packed pairs), bit-trick hi reconstruction.
__device__ __forceinline__ void split2(float a, float b, uint32_t& h, uint32_t& l) {
    uint32_t hb;
    asm("cvt.rn.bf16x2.f32 %0, %1, %2;" : "=r"(hb) : "f"(b), "f"(a));
    const float fa = __uint_as_float(hb << 16);
    const float fb = __uint_as_float(hb & 0xffff0000u);
    const float la = a - fa;
    const float lb = b - fb;
    uint32_t lo;
    asm("cvt.rn.bf16x2.f32 %0, %1, %2;" : "=r"(lo) : "f"(lb), "f"(la));
    h = hb;
    l = lo;
}

// ---------------------------------------------------------------------------
// LayerNorm -> split bf16 [row][512]. One warp per row.
// ---------------------------------------------------------------------------
__global__ __launch_bounds__(256) void ln_kernel(
    const float* __restrict__ m, const float* __restrict__ w,
    const float* __restrict__ b, __nv_bfloat16* __restrict__ osplit)
{
    const int warp = threadIdx.x >> 5;
    const int lane = threadIdx.x & 31;
    const int row  = blockIdx.x * 8 + warp;

    const float4* x4 = (const float4*)(m + (size_t)row * C_DIM);
    float4 v0 = x4[lane * 2 + 0];
    float4 v1 = x4[lane * 2 + 1];

    float s1 = (v0.x + v0.y) + (v0.z + v0.w) + (v1.x + v1.y) + (v1.z + v1.w);
    float s2 = v0.x * v0.x + v0.y * v0.y + v0.z * v0.z + v0.w * v0.w
             + v1.x * v1.x + v1.y * v1.y + v1.z * v1.z + v1.w * v1.w;
    #pragma unroll
    for (int o = 16; o > 0; o >>= 1) {
        s1 += __shfl_xor_sync(0xffffffffu, s1, o);
        s2 += __shfl_xor_sync(0xffffffffu, s2, o);
    }
    const float mu  = s1 * (1.0f / 256.0f);
    const float var = s2 * (1.0f / 256.0f) - mu * mu;
    const float rs  = rsqrtf(var + 1e-5f);

    const float4* w4 = (const float4*)w;
    const float4* b4 = (const float4*)b;
    float4 w0 = w4[lane * 2 + 0], w1 = w4[lane * 2 + 1];
    float4 b0 = b4[lane * 2 + 0], b1 = b4[lane * 2 + 1];

    float r[8];
    r[0] = (v0.x - mu) * rs * w0.x + b0.x;
    r[1] = (v0.y - mu) * rs * w0.y + b0.y;
    r[2] = (v0.z - mu) * rs * w0.z + b0.z;
    r[3] = (v0.w - mu) * rs * w0.w + b0.w;
    r[4] = (v1.x - mu) * rs * w1.x + b1.x;
    r[5] = (v1.y - mu) * rs * w1.y + b1.y;
    r[6] = (v1.z - mu) * rs * w1.z + b1.z;
    r[7] = (v1.w - mu) * rs * w1.w + b1.w;

    uint4 H, L;
    split2(r[0], r[1], H.x, L.x);
    split2(r[2], r[3], H.y, L.y);
    split2(r[4], r[5], H.z, L.z);
    split2(r[6], r[7], H.w, L.w);
    const size_t ofs = (size_t)row * 512 + lane * 8;
    *(uint4*)(osplit + ofs)       = H;
    *(uint4*)(osplit + ofs + 256) = L;
}

// ---------------------------------------------------------------------------
// Weight prep: B_ext[k_ext][n] with k_ext rows [hi, hi, lo] from w[k][n].
// ---------------------------------------------------------------------------
__global__ __launch_bounds__(256) void wconv_kernel(
    const float* __restrict__ w0, const float* __restrict__ w1,
    const float* __restrict__ w2, const float* __restrict__ w3,
    const float* __restrict__ w4,
    __nv_bfloat16* __restrict__ Bqkvg, __nv_bfloat16* __restrict__ Bo)
{
    const float* ws[5] = {w0, w1, w2, w3, w4};
    const int k   = blockIdx.x;        // 0..767
    const int wi  = blockIdx.y;        // 0..4
    const int n   = threadIdx.x;       // 0..255
    const int ks  = k & 255;
    const int seg = k >> 8;            // 0,1 -> hi ; 2 -> lo
    float x = ws[wi][ks * 256 + n];
    __nv_bfloat16 h = __float2bfloat16_rn(x);
    __nv_bfloat16 v = (seg < 2) ? h : __float2bfloat16_rn(x - __bfloat162float(h));
    if (wi < 4) Bqkvg[(size_t)k * 1024 + wi * 256 + n] = v;
    else        Bo[(size_t)k * 256 + n] = v;
}

// ---------------------------------------------------------------------------
// bf16 GEMM via mma.sync: C[M=65536, Nb] = A_ext[M,768] @ B_ext[768,Nb]
// ---------------------------------------------------------------------------
#define STAGE_BYTES 32768
#define NSTAGE 3
#define GEMM_SMEM (NSTAGE * STAGE_BYTES)

__device__ __forceinline__ void ld_chunk(
    uint32_t sbase, const __nv_bfloat16* __restrict__ A,
    const __nv_bfloat16* __restrict__ B, int Nb,
    size_t row0, int n0, int kb, int tid)
{
    const int a_off = (kb < 8 ? kb : kb - 8) * 64;
    #pragma unroll
    for (int t = 0; t < 4; t++) {
        const int i = tid + t * 256;
        const int r = i >> 3, c8 = i & 7;
        cp_async16(sbase + SWZ((uint32_t)(r * 128 + c8 * 16)),
                   A + (row0 + r) * 512 + a_off + c8 * 8);
    }
    const uint32_t bbase = sbase + 16384;
    #pragma unroll
    for (int t = 0; t < 4; t++) {
        const int i = tid + t * 256;
        const int k = i >> 4, u = i & 15;
        const uint32_t sub = (u >= 8) ? 8192u : 0u;
        cp_async16(bbase + sub + SWZ((uint32_t)(k * 128 + (u & 7) * 16)),
                   B + (size_t)(kb * 64 + k) * Nb + n0 + u * 8);
    }
}

__global__ __launch_bounds__(256) void gemm_mma(
    const __nv_bfloat16* __restrict__ A, const __nv_bfloat16* __restrict__ B,
    int Nb, int qkv_mode,
    void* C0, void* C1, void* C2, void* C3,
    const float* bias0, const float* bias3)
{
    extern __shared__ char smem[];
    const uint32_t sb = smem_u32(smem);
    const int tid  = threadIdx.x;
    const int warp = tid >> 5, lane = tid & 31;
    const int wm = (warp >> 2) * 64;
    const int wn = (warp & 3) * 32;
    const size_t row0 = (size_t)blockIdx.y * 128;
    const int n0 = blockIdx.x * 128;

    #pragma unroll
    for (int s = 0; s < 3; s++) {
        ld_chunk(sb + s * STAGE_BYTES, A, B, Nb, row0, n0, s, tid);
        CP_COMMIT();
    }

    float acc[4][4][4];
    #pragma unroll
    for (int i = 0; i < 4; i++)
        #pragma unroll
        for (int j = 0; j < 4; j++)
            #pragma unroll
            for (int x = 0; x < 4; x++) acc[i][j][x] = 0.0f;

    const int lr  = lane & 15;
    const int lh  = lane >> 4;
    const uint32_t bsub = (wn >= 64) ? 8192u : 0u;
    const int wn2 = wn & 63;

    const uint32_t mix = (uint32_t)((lr & 7) << 4);
    uint32_t abase[4];
    #pragma unroll
    for (int i = 0; i < 4; i++)
        abase[i] = (uint32_t)((wm + i * 16 + lr) * 128)
                   + ((uint32_t)(lh * 16) ^ mix);
    uint32_t bbase[2];
    #pragma unroll
    for (int j2 = 0; j2 < 2; j2++)
        bbase[j2] = 16384u + bsub + (uint32_t)(lr * 128)
                    + ((uint32_t)(wn2 * 2 + j2 * 32 + lh * 16) ^ mix);

    #pragma unroll 1
    for (int kb = 0; kb < 12; kb++) {
        CP_WAIT2();
        __syncthreads();
        const int stg = kb % 3;
        const uint32_t sgb = sb + stg * STAGE_BYTES;

        #pragma unroll
        for (int kk = 0; kk < 4; kk++) {
            uint32_t a[4][4];
            #pragma unroll
            for (int i = 0; i < 4; i++)
                ldsm4(a[i], sgb + (abase[i] ^ (uint32_t)(kk * 32)));
            uint32_t bfr[2][4];
            #pragma unroll
            for (int j2 = 0; j2 < 2; j2++)
                ldsm4t(bfr[j2], sgb + bbase[j2] + (uint32_t)(kk * 2048));
            #pragma unroll
            for (int i = 0; i < 4; i++)
                #pragma unroll
                for (int j = 0; j < 4; j++)
                    mma_bf16(acc[i][j], a[i],
                             bfr[j >> 1][(j & 1) * 2], bfr[j >> 1][(j & 1) * 2 + 1]);
        }
        __syncthreads();
        if (kb + 3 < 12) ld_chunk(sb + stg * STAGE_BYTES, A, B, Nb, row0, n0, kb + 3, tid);
        CP_COMMIT();
    }

    const int buf = (n0 >> 8) & 3;
    const int colbase = (n0 & 255) + wn + (lane & 3) * 2;

    if (qkv_mode && buf < 3) {
        __nv_bfloat16* Cq = (__nv_bfloat16*)((buf == 0) ? C0 : (buf == 1) ? C1 : C2);
        const float qsc = (buf == 0) ? 0.17677669529663689f * 1.44269504088896f
                                     : 1.0f;
        #pragma unroll
        for (int i = 0; i < 4; i++) {
            const int r0 = (int)row0 + wm + i * 16 + (lane >> 2);
            #pragma unroll
            for (int j = 0; j < 4; j++) {
                const int col = colbase + j * 8;
                const int hh = col >> 5, cc = col & 31;
                #pragma unroll
                for (int rr = 0; rr < 2; rr++) {
                    const int r = r0 + rr * 8;
                    const int s = r >> 8, ll = r & 255;
                    const size_t dst = ((size_t)(ll * 8 + hh) * 256 + s) * 64 + cc;
                    uint32_t H, L;
                    split2(acc[i][j][rr * 2] * qsc, acc[i][j][rr * 2 + 1] * qsc,
                           H, L);
                    *(uint32_t*)(Cq + dst)      = H;
                    *(uint32_t*)(Cq + dst + 32) = L;
                }
            }
        }
    } else {
        float* C = (float*)((qkv_mode) ? C3 : C0);
        const float* bias = (qkv_mode) ? bias3 : bias0;
        #pragma unroll
        for (int i = 0; i < 4; i++) {
            const size_t r0 = row0 + wm + i * 16 + (lane >> 2);
            #pragma unroll
            for (int j = 0; j < 4; j++) {
                const int col = colbase + j * 8;
                float bx = 0.f, by = 0.f;
                if (bias) { bx = bias[col]; by = bias[col + 1]; }
                float2 v0 = make_float2(acc[i][j][0] + bx, acc[i][j][1] + by);
                float2 v1 = make_float2(acc[i][j][2] + bx, acc[i][j][3] + by);
                *(float2*)(C + r0 * 256 + col)       = v0;
                *(float2*)(C + (r0 + 8) * 256 + col) = v1;
            }
        }
    }
}

// ---------------------------------------------------------------------------
// Tensor-core flash attention per (l,h) tile, 512 threads / 16 warps,
// 2 CTAs/SM (launch_bounds minBlocks=2 -> ptxas targets <=64 regs).
// kaddr/vaddr arrays halved via (x+64)^mix == (x^mix)^64 identity.
//   s' = h*32 + l/8 ; l' = (l%8)*32 + s/8 ; c' = (s%8)*32 + c
// ---------------------------------------------------------------------------
#define ATT_SMEM (3 * 32768)

__global__ __launch_bounds__(512, 2) void attn_mma_kernel(
    const __nv_bfloat16* __restrict__ Qg, const __nv_bfloat16* __restrict__ Kg,
    const __nv_bfloat16* __restrict__ Vg, const float* __restrict__ Gg,
    __nv_bfloat16* __restrict__ Osplit)
{
    extern __shared__ char smem[];
    const uint32_t sb = smem_u32(smem);
    const uint32_t QS = sb, KS = sb + 32768, VS = sb + 65536;

    const int tile = blockIdx.x;
    const int l = tile >> 3, h = tile & 7;
    const int tid = threadIdx.x;
    const size_t gbase0 = (size_t)tile * 256 * 64;

    // Load Q, K, V tiles (32KB each) via cp.async
    #pragma unroll
    for (int t = 0; t < 4; t++) {
        const int idx = t * 512 + tid;
        const int r = idx >> 3, j = idx & 7;
        const uint32_t so = SWZ((uint32_t)(r * 128 + j * 16));
        const size_t go = gbase0 + (size_t)r * 64 + j * 8;
        cp_async16(QS + so, Qg + go);
        cp_async16(KS + so, Kg + go);
        cp_async16(VS + so, Vg + go);
    }
    CP_COMMIT();
    CP_WAIT0();
    __syncthreads();

    const int warp = tid >> 5, lane = tid & 31;
    const int s0 = warp * 16;
    const int lr = lane & 15, lh = lane >> 4;

    // Q fragments (16 rows per warp, hi+lo; Q pre-scaled by scale*log2e)
    uint32_t qh[2][4], ql[2][4];
    #pragma unroll
    for (int kk = 0; kk < 2; kk++) {
        const uint32_t rowb = (uint32_t)(s0 + lr) * 128;
        ldsm4(qh[kk], QS + SWZ(rowb + (kk * 16 + lh * 8) * 2));
        ldsm4(ql[kk], QS + SWZ(rowb + (32 + kk * 16 + lh * 8) * 2));
    }

    // Hoisted swizzled K/V bases; cols 64.. obtained by ^64 at use site
    // ((x+64)^mix == (x^mix)^64 since x<64 has bit6 clear).
    const int klr = (lane & 7) + ((lane >> 4) << 3);
    const uint32_t mix = (uint32_t)((lane & 7) << 4);
    const uint32_t kcolb = (uint32_t)(((lane >> 3) & 1) * 16);
    uint32_t kaddr[2], vaddr[2];
    #pragma unroll
    for (int c = 0; c < 2; c++) {
        kaddr[c] = KS + (uint32_t)(klr * 128) + ((kcolb + c * 32) ^ mix);
        vaddr[c] = VS + (uint32_t)(lr * 128)
                   + (((uint32_t)(lh * 16) + c * 32) ^ mix);
    }

    float o[4][4];
    #pragma unroll
    for (int j = 0; j < 4; j++)
        #pragma unroll
        for (int x = 0; x < 4; x++) o[j][x] = 0.0f;
    float sm[2] = {0.f, 0.f};

    // S-block compute: 16 t-cols -> s[2][4] (two n8 targets)
    auto S_compute = [&](int gt, float s[2][4]) {
        const uint32_t gg = (uint32_t)(gt * 2048);
        uint32_t kh[2][4], kl[2][4];
        ldsm4(kh[0], kaddr[0] + gg);
        ldsm4(kh[1], kaddr[1] + gg);
        ldsm4(kl[0], (kaddr[0] + gg) ^ 64u);
        ldsm4(kl[1], (kaddr[1] + gg) ^ 64u);
        #pragma unroll
        for (int x = 0; x < 4; x++) { s[0][x] = 0.f; s[1][x] = 0.f; }
        #pragma unroll
        for (int ch = 0; ch < 2; ch++) {
            mma_bf16(s[0], qh[ch], kh[ch][0], kh[ch][1]);
            mma_bf16(s[1], qh[ch], kh[ch][2], kh[ch][3]);
            mma_bf16(s[0], ql[ch], kh[ch][0], kh[ch][1]);
            mma_bf16(s[1], ql[ch], kh[ch][2], kh[ch][3]);
            mma_bf16(s[0], qh[ch], kl[ch][0], kl[ch][1]);
            mma_bf16(s[1], qh[ch], kl[ch][2], kl[ch][3]);
        }
    };

    // exp + sum + split + P·V accumulate for one t-block
    auto PV_compute = [&](int gt, float s[2][4]) {
        #pragma unroll
        for (int tgt = 0; tgt < 2; tgt++) {
            #pragma unroll
            for (int x = 0; x < 4; x++) s[tgt][x] = exp2f(s[tgt][x]);
        }
        sm[0] += (s[0][0] + s[0][1]) + (s[1][0] + s[1][1]);
        sm[1] += (s[0][2] + s[0][3]) + (s[1][2] + s[1][3]);

        uint32_t ah[4], al[4];
        split2(s[0][0], s[0][1], ah[0], al[0]);
        split2(s[0][2], s[0][3], ah[1], al[1]);
        split2(s[1][0], s[1][1], ah[2], al[2]);
        split2(s[1][2], s[1][3], ah[3], al[3]);

        const uint32_t gg = (uint32_t)(gt * 2048);
        uint32_t vh[2][4], vl[2][4];
        ldsm4t(vh[0], vaddr[0] + gg);
        ldsm4t(vh[1], vaddr[1] + gg);
        ldsm4t(vl[0], (vaddr[0] + gg) ^ 64u);
        ldsm4t(vl[1], (vaddr[1] + gg) ^ 64u);
        #pragma unroll
        for (int j = 0; j < 4; j++) {
            const int j2 = j >> 1, jj = (j & 1) * 2;
            mma_bf16(o[j], ah, vh[j2][jj], vh[j2][jj + 1]);
            mma_bf16(o[j], al, vh[j2][jj], vh[j2][jj + 1]);
            mma_bf16(o[j], ah, vl[j2][jj], vl[j2][jj + 1]);
        }
    };

    // Ping-pong software pipeline over 16 t-blocks
    float s_a[2][4], s_b[2][4];
    S_compute(0, s_a);
    #pragma unroll
    for (int gt = 0; gt < 16; gt += 2) {
        if (gt + 1 < 16) S_compute(gt + 1, s_b);
        PV_compute(gt, s_a);
        if (gt + 2 < 16) S_compute(gt + 2, s_a);
        if (gt + 1 < 16) PV_compute(gt + 1, s_b);
    }

    // ---- epilogue: normalize, gate, scramble, store split bf16 ----
    const int i_o = h * 32 + (l >> 3);
    #pragma unroll
    for (int rr = 0; rr < 2; rr++) {
        float v = sm[rr];
        v += __shfl_xor_sync(0xffffffffu, v, 1);
        v += __shfl_xor_sync(0xffffffffu, v, 2);
        const float inv = 1.0f / v;
        const int s = s0 + (lane >> 2) + rr * 8;
        const int j_o = ((l & 7) << 5) + (s >> 3);
        const int k_o = (s & 7) << 5;
        const size_t gb = ((size_t)i_o * 256 + j_o) * 256 + k_o;
        const size_t ob = ((size_t)i_o * 256 + j_o) * 512 + k_o;
        #pragma unroll
        for (int j = 0; j < 4; j++) {
            const int c = j * 8 + (lane & 3) * 2;
            const float2 gg = *(const float2*)(Gg + gb + c);
            const float w0 = o[j][rr * 2] * inv
                             / (1.0f + exp2f(-gg.x * 1.44269504088896f));
            const float w1 = o[j][rr * 2 + 1] * inv
                             / (1.0f + exp2f(-gg.y * 1.44269504088896f));
            uint32_t H, L;
            split2(w0, w1, H, L);
            *(uint32_t*)(Osplit + ob + c)       = H;
            *(uint32_t*)(Osplit + ob + 256 + c) = L;
        }
    }
}

// ---------------------------------------------------------------------------
extern "C" void kernel_launch(void* const* d_in, const int* in_sizes, int n_in,
                              void* d_out, int out_size)
{
    const float* m    = (const float*)d_in[0];
    const float* ln_w = (const float*)d_in[1];
    const float* ln_b = (const float*)d_in[2];
    const float* wq   = (const float*)d_in[3];
    const float* wk   = (const float*)d_in[4];
    const float* wv   = (const float*)d_in[5];
    const float* wg   = (const float*)d_in[6];
    const float* bg   = (const float*)d_in[7];
    const float* wo   = (const float*)d_in[8];
    const float* bo   = (const float*)d_in[9];
    float* out = (float*)d_out;

    __nv_bfloat16 *mns, *ats, *Bq, *Bo, *qs, *ks, *vs;
    float *g;
    cudaGetSymbolAddress((void**)&mns, g_mn_split);
    cudaGetSymbolAddress((void**)&ats, g_att_split);
    cudaGetSymbolAddress((void**)&qs,  g_qs);
    cudaGetSymbolAddress((void**)&ks,  g_ks);
    cudaGetSymbolAddress((void**)&vs,  g_vs);
    cudaGetSymbolAddress((void**)&g,   g_g);
    cudaGetSymbolAddress((void**)&Bq,  g_Bqkvg);
    cudaGetSymbolAddress((void**)&Bo,  g_Bo);

    cudaFuncSetAttribute(gemm_mma,
                         cudaFuncAttributeMaxDynamicSharedMemorySize, GEMM_SMEM);
    cudaFuncSetAttribute(attn_mma_kernel,
                         cudaFuncAttributeMaxDynamicSharedMemorySize, ATT_SMEM);

    // 1. LayerNorm -> split bf16
    ln_kernel<<<NROWS / 8, 256>>>(m, ln_w, ln_b, mns);

    // 2. Weight prep
    wconv_kernel<<<dim3(768, 5), 256>>>(wq, wk, wv, wg, wo, Bq, Bo);

    // 3. Fused Q/K/V/G projection: [65536,768] @ [768,1024]
    gemm_mma<<<dim3(8, NROWS / 128), 256, GEMM_SMEM>>>(
        mns, Bq, 1024, 1, qs, ks, vs, g, nullptr, bg);

    // 4. Tensor-core flash attention (2 CTA/SM) + gate + scramble
    attn_mma_kernel<<<L_DIM * NH, 512, ATT_SMEM>>>(qs, ks, vs, g, ats);

    // 5. Output projection: [65536,768] @ [768,256] -> d_out (+bo)
    gemm_mma<<<dim3(2, NROWS / 128), 256, GEMM_SMEM>>>(
        ats, Bo, 256, 0, out, nullptr, nullptr, nullptr, bo, nullptr);
}

// round 11
// speedup vs baseline: 3.2127x; 1.0016x over previous
#include <cuda_runtime.h>
#include <cuda_bf16.h>
#include <cstdint>
#include <math.h>

// Problem constants: B=1, n_seq=S=256, seq_len=L=256, c_m=256, H=8, ch=32, HC=256
#define S_DIM 256
#define L_DIM 256
#define C_DIM 256
#define HC_DIM 256
#define NH 8
#define CH 32
#define NROWS (S_DIM * L_DIM)  // 65536

// ---------------------------------------------------------------------------
// Scratch (device globals per allocation rules)
// ---------------------------------------------------------------------------
__device__ __align__(16) __nv_bfloat16 g_mn_split[NROWS * 512];
__device__ __align__(16) __nv_bfloat16 g_att_split[NROWS * 512];
// Q/K/V attention-tile layout: [(l*8+h)][s][64] rows = [hi32|lo32] bf16
__device__ __align__(16) __nv_bfloat16 g_qs[NROWS * 512];
__device__ __align__(16) __nv_bfloat16 g_ks[NROWS * 512];
__device__ __align__(16) __nv_bfloat16 g_vs[NROWS * 512];
__device__ __align__(16) float g_g[NROWS * HC_DIM];
__device__ __align__(16) __nv_bfloat16 g_Bqkvg[768 * 1024];  // cols: q|k|v|g
__device__ __align__(16) __nv_bfloat16 g_Bo[768 * 256];

// ---------------------------------------------------------------------------
// Helpers
// ---------------------------------------------------------------------------
__device__ __forceinline__ uint32_t smem_u32(const void* p) {
    uint32_t a;
    asm("{ .reg .u64 t; cvta.to.shared.u64 t, %1; cvt.u32.u64 %0, t; }"
        : "=r"(a) : "l"(p));
    return a;
}

#define SWZ(o) ((o) ^ (((o) >> 3) & 0x70))

__device__ __forceinline__ void cp_async16(uint32_t saddr, const void* gptr) {
    asm volatile("cp.async.cg.shared.global [%0], [%1], 16;"
                 :: "r"(saddr), "l"(__cvta_generic_to_global(gptr)) : "memory");
}
#define CP_COMMIT() asm volatile("cp.async.commit_group;" ::: "memory")
#define CP_WAIT2()  asm volatile("cp.async.wait_group 2;" ::: "memory")
#define CP_WAIT0()  asm volatile("cp.async.wait_group 0;" ::: "memory")

__device__ __forceinline__ void ldsm4(uint32_t* r, uint32_t addr) {
    asm volatile("ldmatrix.sync.aligned.m8n8.x4.shared.b16 {%0,%1,%2,%3}, [%4];"
                 : "=r"(r[0]), "=r"(r[1]), "=r"(r[2]), "=r"(r[3]) : "r"(addr));
}
__device__ __forceinline__ void ldsm4t(uint32_t* r, uint32_t addr) {
    asm volatile("ldmatrix.sync.aligned.m8n8.x4.trans.shared.b16 {%0,%1,%2,%3}, [%4];"
                 : "=r"(r[0]), "=r"(r[1]), "=r"(r[2]), "=r"(r[3]) : "r"(addr));
}
__device__ __forceinline__ void mma_bf16(float* c, const uint32_t* a,
                                         uint32_t b0, uint32_t b1) {
    asm volatile(
        "mma.sync.aligned.m16n8k16.row.col.f32.bf16.bf16.f32 "
        "{%0,%1,%2,%3}, {%4,%5,%6,%7}, {%8,%9}, {%0,%1,%2,%3};"
        : "+f"(c[0]), "+f"(c[1]), "+f"(c[2]), "+f"(c[3])
        : "r"(a[0]), "r"(a[1]), "r"(a[2]), "r"(a[3]), "r"(b0), "r"(b1));
}

// fp32 -> bf16 hi/lo split (packed pairs), bit-trick hi reconstruction.
__device__ __forceinline__ void split2(float a, float b, uint32_t& h, uint32_t& l) {
    uint32_t hb;
    asm("cvt.rn.bf16x2.f32 %0, %1, %2;" : "=r"(hb) : "f"(b), "f"(a));
    const float fa = __uint_as_float(hb << 16);
    const float fb = __uint_as_float(hb & 0xffff0000u);
    const float la = a - fa;
    const float lb = b - fb;
    uint32_t lo;
    asm("cvt.rn.bf16x2.f32 %0, %1, %2;" : "=r"(lo) : "f"(lb), "f"(la));
    h = hb;
    l = lo;
}

// ---------------------------------------------------------------------------
// LayerNorm -> split bf16 [row][512]. One warp per row.
// ---------------------------------------------------------------------------
__global__ __launch_bounds__(256) void ln_kernel(
    const float* __restrict__ m, const float* __restrict__ w,
    const float* __restrict__ b, __nv_bfloat16* __restrict__ osplit)
{
    const int warp = threadIdx.x >> 5;
    const int lane = threadIdx.x & 31;
    const int row  = blockIdx.x * 8 + warp;

    const float4* x4 = (const float4*)(m + (size_t)row * C_DIM);
    float4 v0 = x4[lane * 2 + 0];
    float4 v1 = x4[lane * 2 + 1];

    float s1 = (v0.x + v0.y) + (v0.z + v0.w) + (v1.x + v1.y) + (v1.z + v1.w);
    float s2 = v0.x * v0.x + v0.y * v0.y + v0.z * v0.z + v0.w * v0.w
             + v1.x * v1.x + v1.y * v1.y + v1.z * v1.z + v1.w * v1.w;
    #pragma unroll
    for (int o = 16; o > 0; o >>= 1) {
        s1 += __shfl_xor_sync(0xffffffffu, s1, o);
        s2 += __shfl_xor_sync(0xffffffffu, s2, o);
    }
    const float mu  = s1 * (1.0f / 256.0f);
    const float var = s2 * (1.0f / 256.0f) - mu * mu;
    const float rs  = rsqrtf(var + 1e-5f);

    const float4* w4 = (const float4*)w;
    const float4* b4 = (const float4*)b;
    float4 w0 = w4[lane * 2 + 0], w1 = w4[lane * 2 + 1];
    float4 b0 = b4[lane * 2 + 0], b1 = b4[lane * 2 + 1];

    float r[8];
    r[0] = (v0.x - mu) * rs * w0.x + b0.x;
    r[1] = (v0.y - mu) * rs * w0.y + b0.y;
    r[2] = (v0.z - mu) * rs * w0.z + b0.z;
    r[3] = (v0.w - mu) * rs * w0.w + b0.w;
    r[4] = (v1.x - mu) * rs * w1.x + b1.x;
    r[5] = (v1.y - mu) * rs * w1.y + b1.y;
    r[6] = (v1.z - mu) * rs * w1.z + b1.z;
    r[7] = (v1.w - mu) * rs * w1.w + b1.w;

    uint4 H, L;
    split2(r[0], r[1], H.x, L.x);
    split2(r[2], r[3], H.y, L.y);
    split2(r[4], r[5], H.z, L.z);
    split2(r[6], r[7], H.w, L.w);
    const size_t ofs = (size_t)row * 512 + lane * 8;
    *(uint4*)(osplit + ofs)       = H;
    *(uint4*)(osplit + ofs + 256) = L;
}

// ---------------------------------------------------------------------------
// Weight prep: B_ext[k_ext][n] with k_ext rows [hi, hi, lo] from w[k][n].
// ---------------------------------------------------------------------------
__global__ __launch_bounds__(256) void wconv_kernel(
    const float* __restrict__ w0, const float* __restrict__ w1,
    const float* __restrict__ w2, const float* __restrict__ w3,
    const float* __restrict__ w4,
    __nv_bfloat16* __restrict__ Bqkvg, __nv_bfloat16* __restrict__ Bo)
{
    const float* ws[5] = {w0, w1, w2, w3, w4};
    const int k   = blockIdx.x;        // 0..767
    const int wi  = blockIdx.y;        // 0..4
    const int n   = threadIdx.x;       // 0..255
    const int ks  = k & 255;
    const int seg = k >> 8;            // 0,1 -> hi ; 2 -> lo
    float x = ws[wi][ks * 256 + n];
    __nv_bfloat16 h = __float2bfloat16_rn(x);
    __nv_bfloat16 v = (seg < 2) ? h : __float2bfloat16_rn(x - __bfloat162float(h));
    if (wi < 4) Bqkvg[(size_t)k * 1024 + wi * 256 + n] = v;
    else        Bo[(size_t)k * 256 + n] = v;
}

// ---------------------------------------------------------------------------
// bf16 GEMM via mma.sync: C[M=65536, Nb] = A_ext[M,768] @ B_ext[768,Nb]
// 2 CTAs/SM (launch_bounds minBlocks=2 -> regs capped at 128; smem 2x96KB).
// ---------------------------------------------------------------------------
#define STAGE_BYTES 32768
#define NSTAGE 3
#define GEMM_SMEM (NSTAGE * STAGE_BYTES)

__device__ __forceinline__ void ld_chunk(
    uint32_t sbase, const __nv_bfloat16* __restrict__ A,
    const __nv_bfloat16* __restrict__ B, int Nb,
    size_t row0, int n0, int kb, int tid)
{
    const int a_off = (kb < 8 ? kb : kb - 8) * 64;
    #pragma unroll
    for (int t = 0; t < 4; t++) {
        const int i = tid + t * 256;
        const int r = i >> 3, c8 = i & 7;
        cp_async16(sbase + SWZ((uint32_t)(r * 128 + c8 * 16)),
                   A + (row0 + r) * 512 + a_off + c8 * 8);
    }
    const uint32_t bbase = sbase + 16384;
    #pragma unroll
    for (int t = 0; t < 4; t++) {
        const int i = tid + t * 256;
        const int k = i >> 4, u = i & 15;
        const uint32_t sub = (u >= 8) ? 8192u : 0u;
        cp_async16(bbase + sub + SWZ((uint32_t)(k * 128 + (u & 7) * 16)),
                   B + (size_t)(kb * 64 + k) * Nb + n0 + u * 8);
    }
}

__global__ __launch_bounds__(256, 2) void gemm_mma(
    const __nv_bfloat16* __restrict__ A, const __nv_bfloat16* __restrict__ B,
    int Nb, int qkv_mode,
    void* C0, void* C1, void* C2, void* C3,
    const float* bias0, const float* bias3)
{
    extern __shared__ char smem[];
    const uint32_t sb = smem_u32(smem);
    const int tid  = threadIdx.x;
    const int warp = tid >> 5, lane = tid & 31;
    const int wm = (warp >> 2) * 64;
    const int wn = (warp & 3) * 32;
    const size_t row0 = (size_t)blockIdx.y * 128;
    const int n0 = blockIdx.x * 128;

    #pragma unroll
    for (int s = 0; s < 3; s++) {
        ld_chunk(sb + s * STAGE_BYTES, A, B, Nb, row0, n0, s, tid);
        CP_COMMIT();
    }

    float acc[4][4][4];
    #pragma unroll
    for (int i = 0; i < 4; i++)
        #pragma unroll
        for (int j = 0; j < 4; j++)
            #pragma unroll
            for (int x = 0; x < 4; x++) acc[i][j][x] = 0.0f;

    const int lr  = lane & 15;
    const int lh  = lane >> 4;
    const uint32_t bsub = (wn >= 64) ? 8192u : 0u;
    const int wn2 = wn & 63;

    const uint32_t mix = (uint32_t)((lr & 7) << 4);
    uint32_t abase[4];
    #pragma unroll
    for (int i = 0; i < 4; i++)
        abase[i] = (uint32_t)((wm + i * 16 + lr) * 128)
                   + ((uint32_t)(lh * 16) ^ mix);
    uint32_t bbase[2];
    #pragma unroll
    for (int j2 = 0; j2 < 2; j2++)
        bbase[j2] = 16384u + bsub + (uint32_t)(lr * 128)
                    + ((uint32_t)(wn2 * 2 + j2 * 32 + lh * 16) ^ mix);

    #pragma unroll 1
    for (int kb = 0; kb < 12; kb++) {
        CP_WAIT2();
        __syncthreads();
        const int stg = kb % 3;
        const uint32_t sgb = sb + stg * STAGE_BYTES;

        #pragma unroll
        for (int kk = 0; kk < 4; kk++) {
            uint32_t a[4][4];
            #pragma unroll
            for (int i = 0; i < 4; i++)
                ldsm4(a[i], sgb + (abase[i] ^ (uint32_t)(kk * 32)));
            uint32_t bfr[2][4];
            #pragma unroll
            for (int j2 = 0; j2 < 2; j2++)
                ldsm4t(bfr[j2], sgb + bbase[j2] + (uint32_t)(kk * 2048));
            #pragma unroll
            for (int i = 0; i < 4; i++)
                #pragma unroll
                for (int j = 0; j < 4; j++)
                    mma_bf16(acc[i][j], a[i],
                             bfr[j >> 1][(j & 1) * 2], bfr[j >> 1][(j & 1) * 2 + 1]);
        }
        __syncthreads();
        if (kb + 3 < 12) ld_chunk(sb + stg * STAGE_BYTES, A, B, Nb, row0, n0, kb + 3, tid);
        CP_COMMIT();
    }

    const int buf = (n0 >> 8) & 3;
    const int colbase = (n0 & 255) + wn + (lane & 3) * 2;

    if (qkv_mode && buf < 3) {
        __nv_bfloat16* Cq = (__nv_bfloat16*)((buf == 0) ? C0 : (buf == 1) ? C1 : C2);
        const float qsc = (buf == 0) ? 0.17677669529663689f * 1.44269504088896f
                                     : 1.0f;
        #pragma unroll
        for (int i = 0; i < 4; i++) {
            const int r0 = (int)row0 + wm + i * 16 + (lane >> 2);
            #pragma unroll
            for (int j = 0; j < 4; j++) {
                const int col = colbase + j * 8;
                const int hh = col >> 5, cc = col & 31;
                #pragma unroll
                for (int rr = 0; rr < 2; rr++) {
                    const int r = r0 + rr * 8;
                    const int s = r >> 8, ll = r & 255;
                    const size_t dst = ((size_t)(ll * 8 + hh) * 256 + s) * 64 + cc;
                    uint32_t H, L;
                    split2(acc[i][j][rr * 2] * qsc, acc[i][j][rr * 2 + 1] * qsc,
                           H, L);
                    *(uint32_t*)(Cq + dst)      = H;
                    *(uint32_t*)(Cq + dst + 32) = L;
                }
            }
        }
    } else {
        float* C = (float*)((qkv_mode) ? C3 : C0);
        const float* bias = (qkv_mode) ? bias3 : bias0;
        #pragma unroll
        for (int i = 0; i < 4; i++) {
            const size_t r0 = row0 + wm + i * 16 + (lane >> 2);
            #pragma unroll
            for (int j = 0; j < 4; j++) {
                const int col = colbase + j * 8;
                float bx = 0.f, by = 0.f;
                if (bias) { bx = bias[col]; by = bias[col + 1]; }
                float2 v0 = make_float2(acc[i][j][0] + bx, acc[i][j][1] + by);
                float2 v1 = make_float2(acc[i][j][2] + bx, acc[i][j][3] + by);
                *(float2*)(C + r0 * 256 + col)       = v0;
                *(float2*)(C + (r0 + 8) * 256 + col) = v1;
            }
        }
    }
}

// ---------------------------------------------------------------------------
// Tensor-core flash attention per (l,h) tile, 512 threads / 16 warps,
// 2 CTAs/SM. (Unchanged from R10 — it delivered exactly as predicted.)
//   s' = h*32 + l/8 ; l' = (l%8)*32 + s/8 ; c' = (s%8)*32 + c
// ---------------------------------------------------------------------------
#define ATT_SMEM (3 * 32768)

__global__ __launch_bounds__(512, 2) void attn_mma_kernel(
    const __nv_bfloat16* __restrict__ Qg, const __nv_bfloat16* __restrict__ Kg,
    const __nv_bfloat16* __restrict__ Vg, const float* __restrict__ Gg,
    __nv_bfloat16* __restrict__ Osplit)
{
    extern __shared__ char smem[];
    const uint32_t sb = smem_u32(smem);
    const uint32_t QS = sb, KS = sb + 32768, VS = sb + 65536;

    const int tile = blockIdx.x;
    const int l = tile >> 3, h = tile & 7;
    const int tid = threadIdx.x;
    const size_t gbase0 = (size_t)tile * 256 * 64;

    // Load Q, K, V tiles (32KB each) via cp.async
    #pragma unroll
    for (int t = 0; t < 4; t++) {
        const int idx = t * 512 + tid;
        const int r = idx >> 3, j = idx & 7;
        const uint32_t so = SWZ((uint32_t)(r * 128 + j * 16));
        const size_t go = gbase0 + (size_t)r * 64 + j * 8;
        cp_async16(QS + so, Qg + go);
        cp_async16(KS + so, Kg + go);
        cp_async16(VS + so, Vg + go);
    }
    CP_COMMIT();
    CP_WAIT0();
    __syncthreads();

    const int warp = tid >> 5, lane = tid & 31;
    const int s0 = warp * 16;
    const int lr = lane & 15, lh = lane >> 4;

    // Q fragments (16 rows per warp, hi+lo; Q pre-scaled by scale*log2e)
    uint32_t qh[2][4], ql[2][4];
    #pragma unroll
    for (int kk = 0; kk < 2; kk++) {
        const uint32_t rowb = (uint32_t)(s0 + lr) * 128;
        ldsm4(qh[kk], QS + SWZ(rowb + (kk * 16 + lh * 8) * 2));
        ldsm4(ql[kk], QS + SWZ(rowb + (32 + kk * 16 + lh * 8) * 2));
    }

    // Hoisted swizzled K/V bases; cols 64.. obtained by ^64 at use site.
    const int klr = (lane & 7) + ((lane >> 4) << 3);
    const uint32_t mix = (uint32_t)((lane & 7) << 4);
    const uint32_t kcolb = (uint32_t)(((lane >> 3) & 1) * 16);
    uint32_t kaddr[2], vaddr[2];
    #pragma unroll
    for (int c = 0; c < 2; c++) {
        kaddr[c] = KS + (uint32_t)(klr * 128) + ((kcolb + c * 32) ^ mix);
        vaddr[c] = VS + (uint32_t)(lr * 128)
                   + (((uint32_t)(lh * 16) + c * 32) ^ mix);
    }

    float o[4][4];
    #pragma unroll
    for (int j = 0; j < 4; j++)
        #pragma unroll
        for (int x = 0; x < 4; x++) o[j][x] = 0.0f;
    float sm[2] = {0.f, 0.f};

    auto S_compute = [&](int gt, float s[2][4]) {
        const uint32_t gg = (uint32_t)(gt * 2048);
        uint32_t kh[2][4], kl[2][4];
        ldsm4(kh[0], kaddr[0] + gg);
        ldsm4(kh[1], kaddr[1] + gg);
        ldsm4(kl[0], (kaddr[0] + gg) ^ 64u);
        ldsm4(kl[1], (kaddr[1] + gg) ^ 64u);
        #pragma unroll
        for (int x = 0; x < 4; x++) { s[0][x] = 0.f; s[1][x] = 0.f; }
        #pragma unroll
        for (int ch = 0; ch < 2; ch++) {
            mma_bf16(s[0], qh[ch], kh[ch][0], kh[ch][1]);
            mma_bf16(s[1], qh[ch], kh[ch][2], kh[ch][3]);
            mma_bf16(s[0], ql[ch], kh[ch][0], kh[ch][1]);
            mma_bf16(s[1], ql[ch], kh[ch][2], kh[ch][3]);
            mma_bf16(s[0], qh[ch], kl[ch][0], kl[ch][1]);
            mma_bf16(s[1], qh[ch], kl[ch][2], kl[ch][3]);
        }
    };

    auto PV_compute = [&](int gt, float s[2][4]) {
        #pragma unroll
        for (int tgt = 0; tgt < 2; tgt++) {
            #pragma unroll
            for (int x = 0; x < 4; x++) s[tgt][x] = exp2f(s[tgt][x]);
        }
        sm[0] += (s[0][0] + s[0][1]) + (s[1][0] + s[1][1]);
        sm[1] += (s[0][2] + s[0][3]) + (s[1][2] + s[1][3]);

        uint32_t ah[4], al[4];
        split2(s[0][0], s[0][1], ah[0], al[0]);
        split2(s[0][2], s[0][3], ah[1], al[1]);
        split2(s[1][0], s[1][1], ah[2], al[2]);
        split2(s[1][2], s[1][3], ah[3], al[3]);

        const uint32_t gg = (uint32_t)(gt * 2048);
        uint32_t vh[2][4], vl[2][4];
        ldsm4t(vh[0], vaddr[0] + gg);
        ldsm4t(vh[1], vaddr[1] + gg);
        ldsm4t(vl[0], (vaddr[0] + gg) ^ 64u);
        ldsm4t(vl[1], (vaddr[1] + gg) ^ 64u);
        #pragma unroll
        for (int j = 0; j < 4; j++) {
            const int j2 = j >> 1, jj = (j & 1) * 2;
            mma_bf16(o[j], ah, vh[j2][jj], vh[j2][jj + 1]);
            mma_bf16(o[j], al, vh[j2][jj], vh[j2][jj + 1]);
            mma_bf16(o[j], ah, vl[j2][jj], vl[j2][jj + 1]);
        }
    };

    // Ping-pong software pipeline over 16 t-blocks
    float s_a[2][4], s_b[2][4];
    S_compute(0, s_a);
    #pragma unroll
    for (int gt = 0; gt < 16; gt += 2) {
        if (gt + 1 < 16) S_compute(gt + 1, s_b);
        PV_compute(gt, s_a);
        if (gt + 2 < 16) S_compute(gt + 2, s_a);
        if (gt + 1 < 16) PV_compute(gt + 1, s_b);
    }

    // ---- epilogue: normalize, gate, scramble, store split bf16 ----
    const int i_o = h * 32 + (l >> 3);
    #pragma unroll
    for (int rr = 0; rr < 2; rr++) {
        float v = sm[rr];
        v += __shfl_xor_sync(0xffffffffu, v, 1);
        v += __shfl_xor_sync(0xffffffffu, v, 2);
        const float inv = 1.0f / v;
        const int s = s0 + (lane >> 2) + rr * 8;
        const int j_o = ((l & 7) << 5) + (s >> 3);
        const int k_o = (s & 7) << 5;
        const size_t gb = ((size_t)i_o * 256 + j_o) * 256 + k_o;
        const size_t ob = ((size_t)i_o * 256 + j_o) * 512 + k_o;
        #pragma unroll
        for (int j = 0; j < 4; j++) {
            const int c = j * 8 + (lane & 3) * 2;
            const float2 gg = *(const float2*)(Gg + gb + c);
            const float w0 = o[j][rr * 2] * inv
                             / (1.0f + exp2f(-gg.x * 1.44269504088896f));
            const float w1 = o[j][rr * 2 + 1] * inv
                             / (1.0f + exp2f(-gg.y * 1.44269504088896f));
            uint32_t H, L;
            split2(w0, w1, H, L);
            *(uint32_t*)(Osplit + ob + c)       = H;
            *(uint32_t*)(Osplit + ob + 256 + c) = L;
        }
    }
}

// ---------------------------------------------------------------------------
extern "C" void kernel_launch(void* const* d_in, const int* in_sizes, int n_in,
                              void* d_out, int out_size)
{
    const float* m    = (const float*)d_in[0];
    const float* ln_w = (const float*)d_in[1];
    const float* ln_b = (const float*)d_in[2];
    const float* wq   = (const float*)d_in[3];
    const float* wk   = (const float*)d_in[4];
    const float* wv   = (const float*)d_in[5];
    const float* wg   = (const float*)d_in[6];
    const float* bg   = (const float*)d_in[7];
    const float* wo   = (const float*)d_in[8];
    const float* bo   = (const float*)d_in[9];
    float* out = (float*)d_out;

    __nv_bfloat16 *mns, *ats, *Bq, *Bo, *qs, *ks, *vs;
    float *g;
    cudaGetSymbolAddress((void**)&mns, g_mn_split);
    cudaGetSymbolAddress((void**)&ats, g_att_split);
    cudaGetSymbolAddress((void**)&qs,  g_qs);
    cudaGetSymbolAddress((void**)&ks,  g_ks);
    cudaGetSymbolAddress((void**)&vs,  g_vs);
    cudaGetSymbolAddress((void**)&g,   g_g);
    cudaGetSymbolAddress((void**)&Bq,  g_Bqkvg);
    cudaGetSymbolAddress((void**)&Bo,  g_Bo);

    cudaFuncSetAttribute(gemm_mma,
                         cudaFuncAttributeMaxDynamicSharedMemorySize, GEMM_SMEM);
    cudaFuncSetAttribute(attn_mma_kernel,
                         cudaFuncAttributeMaxDynamicSharedMemorySize, ATT_SMEM);

    // 1. LayerNorm -> split bf16
    ln_kernel<<<NROWS / 8, 256>>>(m, ln_w, ln_b, mns);

    // 2. Weight prep
    wconv_kernel<<<dim3(768, 5), 256>>>(wq, wk, wv, wg, wo, Bq, Bo);

    // 3. Fused Q/K/V/G projection: [65536,768] @ [768,1024]
    gemm_mma<<<dim3(8, NROWS / 128), 256, GEMM_SMEM>>>(
        mns, Bq, 1024, 1, qs, ks, vs, g, nullptr, bg);

    // 4. Tensor-core flash attention (2 CTA/SM) + gate + scramble
    attn_mma_kernel<<<L_DIM * NH, 512, ATT_SMEM>>>(qs, ks, vs, g, ats);

    // 5. Output projection: [65536,768] @ [768,256] -> d_out (+bo)
    gemm_mma<<<dim3(2, NROWS / 128), 256, GEMM_SMEM>>>(
        ats, Bo, 256, 0, out, nullptr, nullptr, nullptr, bo, nullptr);
}